// round 7
// baseline (speedup 1.0000x reference)
#include <cuda_runtime.h>
#include <cuda_bf16.h>
#include <cstdint>

#define N_NODES 50000
#define IN_F    64
#define HIDDEN  512
#define N_EDGES 160000
#define N_TRAIN 80000
#define N_CLASS 7
#define BN_EPS  1e-5f

// ---------------- static device scratch (no allocation) ----------------
__device__ __align__(16) float g_bufA[(size_t)N_NODES * HIDDEN];
__device__ __align__(16) float g_bufB[(size_t)N_NODES * HIDDEN];
__device__ __align__(16) float g_agg0[(size_t)N_NODES * IN_F];
__device__ __align__(16) __nv_bfloat16 g_hA[(size_t)N_NODES * HIDDEN];
__device__ __align__(16) __nv_bfloat16 g_lA[(size_t)N_NODES * HIDDEN];
__device__ __align__(16) __nv_bfloat16 g_hB[(size_t)N_NODES * HIDDEN];
__device__ __align__(16) __nv_bfloat16 g_lB[(size_t)N_NODES * HIDDEN];
#define WSLOT (HIDDEN * HIDDEN)
__device__ __align__(16) __nv_bfloat16 g_wh[6 * WSLOT];
__device__ __align__(16) __nv_bfloat16 g_wl[6 * WSLOT];

// ---------------- PTX helpers (base-target only: sm_80-class) ----------------
__device__ __forceinline__ uint32_t cvta_shared(const void* p) {
    uint32_t a;
    asm("{ .reg .u64 t; cvta.to.shared.u64 t, %1; cvt.u32.u64 %0, t; }" : "=r"(a) : "l"(p));
    return a;
}
#define CP16(dst, src) \
    asm volatile("cp.async.cg.shared.global [%0], [%1], 16;" :: "r"(dst), "l"(src))
#define CP_COMMIT() asm volatile("cp.async.commit_group;" ::: "memory")
#define CP_WAIT2()  asm volatile("cp.async.wait_group 2;" ::: "memory")

__device__ __forceinline__ void ldm4(uint32_t* r, uint32_t addr) {
    asm volatile("ldmatrix.sync.aligned.m8n8.x4.shared.b16 {%0,%1,%2,%3}, [%4];"
        : "=r"(r[0]), "=r"(r[1]), "=r"(r[2]), "=r"(r[3]) : "r"(addr));
}
__device__ __forceinline__ void mma16816(float* d, const uint32_t* a, const uint32_t* b) {
    asm volatile(
        "mma.sync.aligned.m16n8k16.row.col.f32.bf16.bf16.f32 "
        "{%0,%1,%2,%3},{%4,%5,%6,%7},{%8,%9},{%0,%1,%2,%3};"
        : "+f"(d[0]), "+f"(d[1]), "+f"(d[2]), "+f"(d[3])
        : "r"(a[0]), "r"(a[1]), "r"(a[2]), "r"(a[3]), "r"(b[0]), "r"(b[1]));
}

// ---------------- HMMA split-bf16 GEMM ----------------
// C[M,512] = A[M,K] @ B[512,K]^T with A=(Ah+Al), B=(Bh+Bl) bf16.
// CTA 128x256 (512 thr, 4x4 warps of 32x64), BK=32, 3-stage cp.async.
#define GBM   128
#define GBN   256
#define GBK   32
#define ROWB  80                     // 64B data + 16B pad (conflict-free ldmatrix)
#define AMATB (128 * ROWB)           // 10240
#define BMATB (256 * ROWB)           // 20480
#define STB   (2 * AMATB + 2 * BMATB)  // 61440 (Ah,Al,Bh,Bl)
#define NSTAGE 3
#define SMEMSZ (NSTAGE * STB)        // 184320

template <bool RELU, bool BN_EN, bool OUTF32>
__global__ void __launch_bounds__(512, 1)
hmma_gemm_kernel(const __nv_bfloat16* __restrict__ Ah, const __nv_bfloat16* __restrict__ Al,
                 const __nv_bfloat16* __restrict__ Bh, const __nv_bfloat16* __restrict__ Bl,
                 const float* __restrict__ bias,
                 const float* __restrict__ bng, const float* __restrict__ bnb,
                 const float* __restrict__ bnm, const float* __restrict__ bnv,
                 float* __restrict__ Cf, float* __restrict__ Cf2,
                 const float* __restrict__ epsp,
                 __nv_bfloat16* __restrict__ Ch, __nv_bfloat16* __restrict__ Cl,
                 int M, int K) {
    extern __shared__ char smem[];
    const uint32_t sb = cvta_shared(smem);
    const int tid = threadIdx.x, lane = tid & 31, wid = tid >> 5;
    const int wm = wid >> 2, wn = wid & 3;           // 4x4 warp grid
    const int rowBase = blockIdx.y * GBM;
    const int colBase = blockIdx.x * GBN;
    const int NC = K / GBK;

    float acc[2][8][4];
#pragma unroll
    for (int a = 0; a < 2; a++)
#pragma unroll
        for (int b = 0; b < 8; b++)
#pragma unroll
            for (int c = 0; c < 4; c++) acc[a][b][c] = 0.0f;

    auto load_stage = [&](int c) {
        const int st = c % NSTAGE;
        const uint32_t base = sb + st * STB;
        const int kOff = c * GBK;
        // A: 128 rows x 4 chunks = 512 CP16 per matrix (1 per thread)
        {
            int row = tid >> 2, ch = tid & 3;
            int gr = rowBase + row;
            if (gr > M - 1) gr = M - 1;              // clamp (finite junk, rows not stored)
            size_t ga = (size_t)gr * K + kOff + ch * 8;
            uint32_t so = (uint32_t)row * ROWB + ch * 16;
            CP16(base + so, Ah + ga);
            CP16(base + AMATB + so, Al + ga);
        }
        // B: 256 rows x 4 chunks = 1024 CP16 per matrix (2 per thread)
#pragma unroll
        for (int u = 0; u < 2; u++) {
            int idx = tid + u * 512;
            int row = idx >> 2, ch = idx & 3;
            size_t gb = (size_t)(colBase + row) * K + kOff + ch * 8;
            uint32_t so = (uint32_t)row * ROWB + ch * 16;
            CP16(base + 2 * AMATB + so, Bh + gb);
            CP16(base + 2 * AMATB + BMATB + so, Bl + gb);
        }
        CP_COMMIT();
    };

    // ldmatrix per-lane address offsets
    const int mrow = (lane & 7) + ((lane >> 3) & 1) * 8;
    const uint32_t aoff = (uint32_t)(wm * 32 + mrow) * ROWB + (lane >> 4) * 16;
    const int nrow = (lane & 7) + ((lane >> 4) << 3);
    const uint32_t boff = (uint32_t)(wn * 64 + nrow) * ROWB + ((lane >> 3) & 1) * 16;

    load_stage(0);
    if (NC > 1) load_stage(1); else CP_COMMIT();

    for (int c = 0; c < NC; c++) {
        if (c + 2 < NC) load_stage(c + 2);
        else            CP_COMMIT();          // keep group count uniform
        CP_WAIT2();                           // stage c complete
        __syncthreads();

        const int st = c % NSTAGE;
        const uint32_t aB = sb + st * STB;
        const uint32_t bB = aB + 2 * AMATB;
#pragma unroll
        for (int ks = 0; ks < 2; ks++) {      // two k16 steps per BK=32
            uint32_t ahf[2][4], alf[2][4];
#pragma unroll
            for (int mt = 0; mt < 2; mt++) {
                uint32_t ad = aB + aoff + mt * (16 * ROWB) + ks * 32;
                ldm4(ahf[mt], ad);
                ldm4(alf[mt], ad + AMATB);
            }
#pragma unroll
            for (int jp = 0; jp < 4; jp++) {  // B fragments loaded per-jp (low reg pressure)
                uint32_t bhf[4], blf[4];
                uint32_t bd = bB + boff + jp * (16 * ROWB) + ks * 32;
                ldm4(bhf, bd);
                ldm4(blf, bd + BMATB);
#pragma unroll
                for (int h = 0; h < 2; h++) {
                    int j = jp * 2 + h;
#pragma unroll
                    for (int mt = 0; mt < 2; mt++) {
                        mma16816(acc[mt][j], ahf[mt], &bhf[h * 2]);
                        mma16816(acc[mt][j], ahf[mt], &blf[h * 2]);
                        mma16816(acc[mt][j], alf[mt], &bhf[h * 2]);
                    }
                }
            }
        }
        __syncthreads();                      // stage c free before it is overwritten
    }

    // ---------------- epilogue (direct from registers) ----------------
    const int g = lane >> 2, t = lane & 3;
    const float es = (OUTF32 && Cf2) ? (1.0f + *epsp) : 0.0f;
#pragma unroll
    for (int mt = 0; mt < 2; mt++) {
        int rbase = rowBase + wm * 32 + mt * 16 + g;
#pragma unroll
        for (int half = 0; half < 2; half++) {
            int r = rbase + half * 8;
            if (r >= M) continue;
#pragma unroll
            for (int j = 0; j < 8; j++) {
                int cidx = colBase + wn * 64 + j * 8 + 2 * t;
                float v0 = acc[mt][j][half * 2 + 0] + bias[cidx];
                float v1 = acc[mt][j][half * 2 + 1] + bias[cidx + 1];
                if (RELU) { v0 = fmaxf(v0, 0.0f); v1 = fmaxf(v1, 0.0f); }
                if (BN_EN) {
                    v0 = (v0 - bnm[cidx]) * rsqrtf(bnv[cidx] + BN_EPS) * bng[cidx] + bnb[cidx];
                    v1 = (v1 - bnm[cidx + 1]) * rsqrtf(bnv[cidx + 1] + BN_EPS) * bng[cidx + 1] + bnb[cidx + 1];
                }
                if (OUTF32) {
                    *(float2*)(Cf + (size_t)r * HIDDEN + cidx) = make_float2(v0, v1);
                    if (Cf2)
                        *(float2*)(Cf2 + (size_t)r * HIDDEN + cidx) =
                            make_float2(v0 * es, v1 * es);
                } else {
                    __nv_bfloat16 h0 = __float2bfloat16(v0);
                    __nv_bfloat16 h1 = __float2bfloat16(v1);
                    __nv_bfloat16 l0 = __float2bfloat16(v0 - __bfloat162float(h0));
                    __nv_bfloat16 l1 = __float2bfloat16(v1 - __bfloat162float(h1));
                    *(uint32_t*)(Ch + (size_t)r * HIDDEN + cidx) =
                        (uint32_t)__bfloat16_as_ushort(h0) | ((uint32_t)__bfloat16_as_ushort(h1) << 16);
                    *(uint32_t*)(Cl + (size_t)r * HIDDEN + cidx) =
                        (uint32_t)__bfloat16_as_ushort(l0) | ((uint32_t)__bfloat16_as_ushort(l1) << 16);
                }
            }
        }
    }
}

// ---------------- auxiliary kernels ----------------
__global__ void scale_copy_kernel(const float4* __restrict__ in, float4* __restrict__ out,
                                  const float* __restrict__ eps, int n4) {
    float s = 1.0f + *eps;
    int i = blockIdx.x * blockDim.x + threadIdx.x;
    if (i < n4) {
        float4 v = in[i];
        v.x *= s; v.y *= s; v.z *= s; v.w *= s;
        out[i] = v;
    }
}

__global__ void scatter_add_kernel(const float* __restrict__ h, float* __restrict__ out,
                                   const int* __restrict__ src, const int* __restrict__ dst,
                                   int nEdges, int F) {
    int warp = (blockIdx.x * blockDim.x + threadIdx.x) >> 5;
    int lane = threadIdx.x & 31;
    if (warp >= nEdges) return;
    int s = src[warp], d = dst[warp];
    const float4* hs = (const float4*)(h + (size_t)s * F);
    float* od = out + (size_t)d * F;
    int f4 = F >> 2;
    for (int i = lane; i < f4; i += 32) {
        float4 v = hs[i];
        atomicAdd(od + 4 * i + 0, v.x);
        atomicAdd(od + 4 * i + 1, v.y);
        atomicAdd(od + 4 * i + 2, v.z);
        atomicAdd(od + 4 * i + 3, v.w);
    }
}

__global__ void split_kernel(const float4* __restrict__ in, uint32_t* __restrict__ hi,
                             uint32_t* __restrict__ lo, int n4) {
    int i = blockIdx.x * blockDim.x + threadIdx.x;
    if (i >= n4) return;
    float4 v = in[i];
    __nv_bfloat16 h0 = __float2bfloat16(v.x), h1 = __float2bfloat16(v.y);
    __nv_bfloat16 h2 = __float2bfloat16(v.z), h3 = __float2bfloat16(v.w);
    __nv_bfloat16 l0 = __float2bfloat16(v.x - __bfloat162float(h0));
    __nv_bfloat16 l1 = __float2bfloat16(v.y - __bfloat162float(h1));
    __nv_bfloat16 l2 = __float2bfloat16(v.z - __bfloat162float(h2));
    __nv_bfloat16 l3 = __float2bfloat16(v.w - __bfloat162float(h3));
    hi[2 * i]     = (uint32_t)__bfloat16_as_ushort(h0) | ((uint32_t)__bfloat16_as_ushort(h1) << 16);
    hi[2 * i + 1] = (uint32_t)__bfloat16_as_ushort(h2) | ((uint32_t)__bfloat16_as_ushort(h3) << 16);
    lo[2 * i]     = (uint32_t)__bfloat16_as_ushort(l0) | ((uint32_t)__bfloat16_as_ushort(l1) << 16);
    lo[2 * i + 1] = (uint32_t)__bfloat16_as_ushort(l2) | ((uint32_t)__bfloat16_as_ushort(l3) << 16);
}

// W[K,N] f32 -> Wh[N,K], Wl[N,K] bf16 (transpose + split)
__global__ void wsplit_kernel(const float* __restrict__ W, __nv_bfloat16* __restrict__ Wh,
                              __nv_bfloat16* __restrict__ Wl, int K, int N) {
    __shared__ float t[32][33];
    int n0 = blockIdx.x * 32, k0 = blockIdx.y * 32;
    int tx = threadIdx.x, ty = threadIdx.y;
#pragma unroll
    for (int i = 0; i < 4; i++)
        t[ty + i * 8][tx] = W[(size_t)(k0 + ty + i * 8) * N + n0 + tx];
    __syncthreads();
#pragma unroll
    for (int i = 0; i < 4; i++) {
        float v = t[tx][ty + i * 8];
        __nv_bfloat16 h = __float2bfloat16(v);
        __nv_bfloat16 l = __float2bfloat16(v - __bfloat162float(h));
        size_t o = (size_t)(n0 + ty + i * 8) * K + k0 + tx;
        Wh[o] = h;
        Wl[o] = l;
    }
}

__global__ void __launch_bounds__(256)
edge_pred_kernel(const float* __restrict__ h, const int* __restrict__ ei,
                 const int* __restrict__ train_id, const float* __restrict__ W,
                 const float* __restrict__ b, float* __restrict__ out) {
    __shared__ float sW[HIDDEN * N_CLASS];
    __shared__ float sb[N_CLASS];
    for (int i = threadIdx.x; i < HIDDEN * N_CLASS; i += blockDim.x) sW[i] = W[i];
    if (threadIdx.x < N_CLASS) sb[threadIdx.x] = b[threadIdx.x];
    __syncthreads();
    int warp = (blockIdx.x * blockDim.x + threadIdx.x) >> 5;
    int lane = threadIdx.x & 31;
    if (warp >= N_TRAIN) return;
    int te = train_id[warp];
    int n0 = ei[te], n1 = ei[N_EDGES + te];
    const float4* h0 = (const float4*)(h + (size_t)n0 * HIDDEN);
    const float4* h1 = (const float4*)(h + (size_t)n1 * HIDDEN);
    float acc[N_CLASS];
#pragma unroll
    for (int j = 0; j < N_CLASS; j++) acc[j] = 0.0f;
    for (int k4 = lane; k4 < HIDDEN / 4; k4 += 32) {
        float4 a = h0[k4], c = h1[k4];
        float p0 = a.x * c.x, p1 = a.y * c.y, p2 = a.z * c.z, p3 = a.w * c.w;
        int k = k4 * 4;
#pragma unroll
        for (int j = 0; j < N_CLASS; j++)
            acc[j] += p0 * sW[(k + 0) * N_CLASS + j] + p1 * sW[(k + 1) * N_CLASS + j] +
                      p2 * sW[(k + 2) * N_CLASS + j] + p3 * sW[(k + 3) * N_CLASS + j];
    }
#pragma unroll
    for (int j = 0; j < N_CLASS; j++)
#pragma unroll
        for (int off = 16; off > 0; off >>= 1)
            acc[j] += __shfl_xor_sync(0xffffffffu, acc[j], off);
    if (lane == 0) {
#pragma unroll
        for (int j = 0; j < N_CLASS; j++)
            out[(size_t)warp * N_CLASS + j] = acc[j] + sb[j];
    }
}

// ---------------- launcher ----------------
extern "C" void kernel_launch(void* const* d_in, const int* in_sizes, int n_in,
                              void* d_out, int out_size) {
    const float* x     = (const float*)d_in[0];
    const int*   ei    = (const int*)d_in[1];
    const int*   trid  = (const int*)d_in[2];
    const float* W1    = (const float*)d_in[3];
    const float* b1    = (const float*)d_in[4];
    const float* W2    = (const float*)d_in[5];
    const float* b2    = (const float*)d_in[6];
    const float* W3    = (const float*)d_in[7];
    const float* b3    = (const float*)d_in[8];
    const float* bn1g  = (const float*)d_in[9];
    const float* bn1b  = (const float*)d_in[10];
    const float* bn1m  = (const float*)d_in[11];
    const float* bn1v  = (const float*)d_in[12];
    const float* eps1  = (const float*)d_in[13];
    const float* W4    = (const float*)d_in[14];
    const float* b4    = (const float*)d_in[15];
    const float* bn2g  = (const float*)d_in[16];
    const float* bn2b  = (const float*)d_in[17];
    const float* bn2m  = (const float*)d_in[18];
    const float* bn2v  = (const float*)d_in[19];
    const float* eps2  = (const float*)d_in[20];
    const float* lin1W = (const float*)d_in[21];
    const float* lin1b = (const float*)d_in[22];
    const float* lin2W = (const float*)d_in[23];
    const float* lin2b = (const float*)d_in[24];
    const float* fc2W  = (const float*)d_in[25];
    const float* fc2b  = (const float*)d_in[26];
    float* out = (float*)d_out;

    float *bufA, *bufB, *agg0;
    __nv_bfloat16 *hA, *lA, *hB, *lB, *wh, *wl;
    cudaGetSymbolAddress((void**)&bufA, g_bufA);
    cudaGetSymbolAddress((void**)&bufB, g_bufB);
    cudaGetSymbolAddress((void**)&agg0, g_agg0);
    cudaGetSymbolAddress((void**)&hA, g_hA);
    cudaGetSymbolAddress((void**)&lA, g_lA);
    cudaGetSymbolAddress((void**)&hB, g_hB);
    cudaGetSymbolAddress((void**)&lB, g_lB);
    cudaGetSymbolAddress((void**)&wh, g_wh);
    cudaGetSymbolAddress((void**)&wl, g_wl);

    cudaFuncSetAttribute(hmma_gemm_kernel<true, false, false>,
                         cudaFuncAttributeMaxDynamicSharedMemorySize, SMEMSZ);
    cudaFuncSetAttribute(hmma_gemm_kernel<true, true, true>,
                         cudaFuncAttributeMaxDynamicSharedMemorySize, SMEMSZ);
    cudaFuncSetAttribute(hmma_gemm_kernel<true, true, false>,
                         cudaFuncAttributeMaxDynamicSharedMemorySize, SMEMSZ);
    cudaFuncSetAttribute(hmma_gemm_kernel<false, false, true>,
                         cudaFuncAttributeMaxDynamicSharedMemorySize, SMEMSZ);

    const int* src = ei;
    const int* dst = ei + N_EDGES;

    // weight transpose + split
    dim3 wb(32, 8);
    wsplit_kernel<<<dim3(16, 2), wb>>>(W1, wh + 0 * WSLOT, wl + 0 * WSLOT, IN_F, HIDDEN);
    wsplit_kernel<<<dim3(16, 16), wb>>>(W2, wh + 1 * WSLOT, wl + 1 * WSLOT, HIDDEN, HIDDEN);
    wsplit_kernel<<<dim3(16, 16), wb>>>(W3, wh + 2 * WSLOT, wl + 2 * WSLOT, HIDDEN, HIDDEN);
    wsplit_kernel<<<dim3(16, 16), wb>>>(W4, wh + 3 * WSLOT, wl + 3 * WSLOT, HIDDEN, HIDDEN);
    wsplit_kernel<<<dim3(16, 16), wb>>>(lin1W, wh + 4 * WSLOT, wl + 4 * WSLOT, HIDDEN, HIDDEN);
    wsplit_kernel<<<dim3(16, 16), wb>>>(lin2W, wh + 5 * WSLOT, wl + 5 * WSLOT, HIDDEN, HIDDEN);

    // agg1 on x (fp32) then split
    {
        int n4 = N_NODES * IN_F / 4;
        scale_copy_kernel<<<(n4 + 255) / 256, 256>>>((const float4*)x, (float4*)agg0, eps1, n4);
        scatter_add_kernel<<<(N_EDGES * 32 + 255) / 256, 256>>>(x, agg0, src, dst, N_EDGES, IN_F);
        split_kernel<<<(n4 + 255) / 256, 256>>>((const float4*)agg0, (uint32_t*)hA, (uint32_t*)lA, n4);
    }

    dim3 gg(HIDDEN / GBN, (N_NODES + GBM - 1) / GBM);  // (2, 391)

    // L1: relu(agg @ W1 + b1) -> split pair
    hmma_gemm_kernel<true, false, false><<<gg, 512, SMEMSZ>>>(
        hA, lA, wh + 0 * WSLOT, wl + 0 * WSLOT, b1, nullptr, nullptr, nullptr, nullptr,
        nullptr, nullptr, nullptr, hB, lB, N_NODES, IN_F);
    // L2: relu(h @ W2 + b2) -> split pair
    hmma_gemm_kernel<true, false, false><<<gg, 512, SMEMSZ>>>(
        hB, lB, wh + 1 * WSLOT, wl + 1 * WSLOT, b2, nullptr, nullptr, nullptr, nullptr,
        nullptr, nullptr, nullptr, hA, lA, N_NODES, HIDDEN);
    // L3: bn1(relu(h @ W3 + b3)) -> fp32 bufA + (1+eps2)-scaled bufB (fused)
    hmma_gemm_kernel<true, true, true><<<gg, 512, SMEMSZ>>>(
        hA, lA, wh + 2 * WSLOT, wl + 2 * WSLOT, b3, bn1g, bn1b, bn1m, bn1v,
        bufA, bufB, eps2, nullptr, nullptr, N_NODES, HIDDEN);
    // agg2: bufB += bufA[src] scattered, then split
    {
        int n4 = N_NODES * HIDDEN / 4;
        scatter_add_kernel<<<(N_EDGES * 32 + 255) / 256, 256>>>(bufA, bufB, src, dst, N_EDGES, HIDDEN);
        split_kernel<<<(n4 + 255) / 256, 256>>>((const float4*)bufB, (uint32_t*)hA, (uint32_t*)lA, n4);
    }
    // L4: bn2(relu(h @ W4 + b4)) -> split pair
    hmma_gemm_kernel<true, true, false><<<gg, 512, SMEMSZ>>>(
        hA, lA, wh + 3 * WSLOT, wl + 3 * WSLOT, b4, bn2g, bn2b, bn2m, bn2v,
        nullptr, nullptr, nullptr, hB, lB, N_NODES, HIDDEN);
    // L5: relu(h @ lin1W + lin1b) -> split pair
    hmma_gemm_kernel<true, false, false><<<gg, 512, SMEMSZ>>>(
        hB, lB, wh + 4 * WSLOT, wl + 4 * WSLOT, lin1b, nullptr, nullptr, nullptr, nullptr,
        nullptr, nullptr, nullptr, hA, lA, N_NODES, HIDDEN);
    // L6: h @ lin2W + lin2b -> fp32
    hmma_gemm_kernel<false, false, true><<<gg, 512, SMEMSZ>>>(
        hA, lA, wh + 5 * WSLOT, wl + 5 * WSLOT, lin2b, nullptr, nullptr, nullptr, nullptr,
        bufA, nullptr, nullptr, nullptr, nullptr, N_NODES, HIDDEN);
    // edge classifier
    edge_pred_kernel<<<(N_TRAIN * 32 + 255) / 256, 256>>>(bufA, ei, trid, fc2W, fc2b, out);
}

// round 8
// speedup vs baseline: 1.8595x; 1.8595x over previous
#include <cuda_runtime.h>
#include <cuda_bf16.h>
#include <cstdint>

#define N_NODES 50000
#define IN_F    64
#define HIDDEN  512
#define N_EDGES 160000
#define N_TRAIN 80000
#define N_CLASS 7
#define BN_EPS  1e-5f

// ---------------- static device scratch (no allocation) ----------------
__device__ __align__(16) float g_bufA[(size_t)N_NODES * HIDDEN];
__device__ __align__(16) float g_bufB[(size_t)N_NODES * HIDDEN];
__device__ __align__(16) float g_agg0[(size_t)N_NODES * IN_F];
__device__ __align__(16) __nv_bfloat16 g_hA[(size_t)N_NODES * HIDDEN];
__device__ __align__(16) __nv_bfloat16 g_lA[(size_t)N_NODES * HIDDEN];
__device__ __align__(16) __nv_bfloat16 g_hB[(size_t)N_NODES * HIDDEN];
__device__ __align__(16) __nv_bfloat16 g_lB[(size_t)N_NODES * HIDDEN];
#define WSLOT (HIDDEN * HIDDEN)
__device__ __align__(16) __nv_bfloat16 g_wh[6 * WSLOT];
__device__ __align__(16) __nv_bfloat16 g_wl[6 * WSLOT];

// ---------------- PTX helpers (base-target only: sm_80-class) ----------------
__device__ __forceinline__ uint32_t cvta_shared(const void* p) {
    uint32_t a;
    asm("{ .reg .u64 t; cvta.to.shared.u64 t, %1; cvt.u32.u64 %0, t; }" : "=r"(a) : "l"(p));
    return a;
}
#define CP16(dst, src) \
    asm volatile("cp.async.cg.shared.global [%0], [%1], 16;" :: "r"(dst), "l"(src))
#define CP_COMMIT() asm volatile("cp.async.commit_group;" ::: "memory")
#define CP_WAIT1()  asm volatile("cp.async.wait_group 1;" ::: "memory")

__device__ __forceinline__ void ldm4(uint32_t* r, uint32_t addr) {
    asm volatile("ldmatrix.sync.aligned.m8n8.x4.shared.b16 {%0,%1,%2,%3}, [%4];"
        : "=r"(r[0]), "=r"(r[1]), "=r"(r[2]), "=r"(r[3]) : "r"(addr));
}
__device__ __forceinline__ void mma16816(float* d, const uint32_t* a, const uint32_t* b) {
    asm volatile(
        "mma.sync.aligned.m16n8k16.row.col.f32.bf16.bf16.f32 "
        "{%0,%1,%2,%3},{%4,%5,%6,%7},{%8,%9},{%0,%1,%2,%3};"
        : "+f"(d[0]), "+f"(d[1]), "+f"(d[2]), "+f"(d[3])
        : "r"(a[0]), "r"(a[1]), "r"(a[2]), "r"(a[3]), "r"(b[0]), "r"(b[1]));
}

// swizzle: logical (row, 16B-chunk c in 0..3) -> phys byte offset within a
// 64B-row matrix tile. chunk' = c ^ ((row>>1)&3): any 8 consecutive rows at a
// fixed logical chunk hit 8 distinct 16B bank groups -> ldmatrix conflict-free.
__device__ __forceinline__ uint32_t swz(uint32_t row, uint32_t c) {
    return row * 64u + ((c ^ ((row >> 1) & 3u)) << 4);
}

// ---------------- HMMA split-bf16 GEMM ----------------
// C[M,512] = A[M,K] @ B[512,K]^T with A=(Ah+Al), B=(Bh+Bl) bf16.
// CTA 128x128, BK=32, 3-stage cp.async, swizzled 64B rows, 2 CTAs/SM.
#define GBM   128
#define GBN   128
#define GBK   32
#define MATB  (128 * 64)             // 8192 per matrix per stage
#define STB   (4 * MATB)             // 32768 per stage (Ah,Al,Bh,Bl)
#define NSTAGE 3
#define SMEMSZ (NSTAGE * STB)        // 98304 -> 2 CTAs/SM

template <bool RELU, bool BN_EN, bool OUTF32>
__global__ void __launch_bounds__(256, 2)
hmma_gemm_kernel(const __nv_bfloat16* __restrict__ Ah, const __nv_bfloat16* __restrict__ Al,
                 const __nv_bfloat16* __restrict__ Bh, const __nv_bfloat16* __restrict__ Bl,
                 const float* __restrict__ bias,
                 const float* __restrict__ bng, const float* __restrict__ bnb,
                 const float* __restrict__ bnm, const float* __restrict__ bnv,
                 float* __restrict__ Cf, float* __restrict__ Cf2,
                 const float* __restrict__ epsp,
                 __nv_bfloat16* __restrict__ Ch, __nv_bfloat16* __restrict__ Cl,
                 int M, int K) {
    extern __shared__ char smem[];
    const uint32_t sb = cvta_shared(smem);
    const int tid = threadIdx.x, lane = tid & 31, wid = tid >> 5;
    const int wm = wid >> 1, wn = wid & 1;           // 4x2 warp grid
    const int rowBase = blockIdx.y * GBM;
    const int colBase = blockIdx.x * GBN;
    const int NC = K / GBK;

    float acc[2][8][4];
#pragma unroll
    for (int a = 0; a < 2; a++)
#pragma unroll
        for (int b = 0; b < 8; b++)
#pragma unroll
            for (int c = 0; c < 4; c++) acc[a][b][c] = 0.0f;

    auto load_stage = [&](int c) {
        const int st = c % NSTAGE;
        const uint32_t base = sb + st * STB;
        const int kOff = c * GBK;
#pragma unroll
        for (int u = 0; u < 2; u++) {
            int idx = tid + u * 256;
            uint32_t row = (uint32_t)idx >> 2, ch = (uint32_t)idx & 3;
            int gr = rowBase + (int)row;
            if (gr > M - 1) gr = M - 1;              // clamp (finite junk, rows not stored)
            size_t ga = (size_t)gr * K + kOff + ch * 8;
            uint32_t so = swz(row, ch);
            CP16(base + so, Ah + ga);
            CP16(base + MATB + so, Al + ga);
            size_t gb = (size_t)(colBase + (int)row) * K + kOff + ch * 8;
            CP16(base + 2 * MATB + so, Bh + gb);
            CP16(base + 3 * MATB + so, Bl + gb);
        }
        CP_COMMIT();
    };

    // ldmatrix per-lane row indices (chunk varies with ks -> swizzled per use)
    const uint32_t mrow = (uint32_t)((lane & 7) + ((lane >> 3) & 1) * 8);
    const uint32_t aChunkBit = (uint32_t)(lane >> 4);          // 0/1
    const uint32_t nrow = (uint32_t)((lane & 7) + ((lane >> 4) << 3));
    const uint32_t bChunkBit = (uint32_t)((lane >> 3) & 1);    // 0/1

    load_stage(0);
    if (NC > 1) load_stage(1); else CP_COMMIT();

    for (int c = 0; c < NC; c++) {
        CP_WAIT1();                           // stage c complete
        __syncthreads();                      // all threads done with stage c-? (see note)
        if (c + 2 < NC) load_stage(c + 2);
        else            CP_COMMIT();          // keep group count uniform

        const int st = c % NSTAGE;
        const uint32_t aB = sb + st * STB;
        const uint32_t bB = aB + 2 * MATB;
#pragma unroll
        for (int ks = 0; ks < 2; ks++) {      // two k16 steps per BK=32
            const uint32_t cA = (uint32_t)ks * 2 + aChunkBit;
            const uint32_t cB = (uint32_t)ks * 2 + bChunkBit;
            uint32_t ahf[2][4], alf[2][4], bhf[4][4], blf[4][4];
#pragma unroll
            for (int mt = 0; mt < 2; mt++) {
                uint32_t ad = aB + swz((uint32_t)(wm * 32 + mt * 16) + mrow, cA);
                ldm4(ahf[mt], ad);
                ldm4(alf[mt], ad + MATB);
            }
#pragma unroll
            for (int jp = 0; jp < 4; jp++) {
                uint32_t bd = bB + swz((uint32_t)(wn * 64 + jp * 16) + nrow, cB);
                ldm4(bhf[jp], bd);
                ldm4(blf[jp], bd + MATB);
            }
#pragma unroll
            for (int mt = 0; mt < 2; mt++)
#pragma unroll
                for (int j = 0; j < 8; j++)
                    mma16816(acc[mt][j], ahf[mt], &bhf[j >> 1][(j & 1) * 2]);
#pragma unroll
            for (int mt = 0; mt < 2; mt++)
#pragma unroll
                for (int j = 0; j < 8; j++)
                    mma16816(acc[mt][j], ahf[mt], &blf[j >> 1][(j & 1) * 2]);
#pragma unroll
            for (int mt = 0; mt < 2; mt++)
#pragma unroll
                for (int j = 0; j < 8; j++)
                    mma16816(acc[mt][j], alf[mt], &bhf[j >> 1][(j & 1) * 2]);
        }
        // no trailing sync needed: 3 distinct stage buffers; the next
        // iteration's top sync orders all compute before buffer reuse.
    }

    // ---------------- epilogue (direct from registers) ----------------
    const int g = lane >> 2, t = lane & 3;
    const float es = (OUTF32 && Cf2) ? (1.0f + *epsp) : 0.0f;
#pragma unroll
    for (int mt = 0; mt < 2; mt++) {
        int rbase = rowBase + wm * 32 + mt * 16 + g;
#pragma unroll
        for (int half = 0; half < 2; half++) {
            int r = rbase + half * 8;
            if (r >= M) continue;
#pragma unroll
            for (int j = 0; j < 8; j++) {
                int cidx = colBase + wn * 64 + j * 8 + 2 * t;
                float v0 = acc[mt][j][half * 2 + 0] + bias[cidx];
                float v1 = acc[mt][j][half * 2 + 1] + bias[cidx + 1];
                if (RELU) { v0 = fmaxf(v0, 0.0f); v1 = fmaxf(v1, 0.0f); }
                if (BN_EN) {
                    v0 = (v0 - bnm[cidx]) * rsqrtf(bnv[cidx] + BN_EPS) * bng[cidx] + bnb[cidx];
                    v1 = (v1 - bnm[cidx + 1]) * rsqrtf(bnv[cidx + 1] + BN_EPS) * bng[cidx + 1] + bnb[cidx + 1];
                }
                if (OUTF32) {
                    *(float2*)(Cf + (size_t)r * HIDDEN + cidx) = make_float2(v0, v1);
                    if (Cf2)
                        *(float2*)(Cf2 + (size_t)r * HIDDEN + cidx) =
                            make_float2(v0 * es, v1 * es);
                } else {
                    __nv_bfloat16 h0 = __float2bfloat16(v0);
                    __nv_bfloat16 h1 = __float2bfloat16(v1);
                    __nv_bfloat16 l0 = __float2bfloat16(v0 - __bfloat162float(h0));
                    __nv_bfloat16 l1 = __float2bfloat16(v1 - __bfloat162float(h1));
                    *(uint32_t*)(Ch + (size_t)r * HIDDEN + cidx) =
                        (uint32_t)__bfloat16_as_ushort(h0) | ((uint32_t)__bfloat16_as_ushort(h1) << 16);
                    *(uint32_t*)(Cl + (size_t)r * HIDDEN + cidx) =
                        (uint32_t)__bfloat16_as_ushort(l0) | ((uint32_t)__bfloat16_as_ushort(l1) << 16);
                }
            }
        }
    }
}

// ---------------- auxiliary kernels ----------------
__global__ void scale_copy_kernel(const float4* __restrict__ in, float4* __restrict__ out,
                                  const float* __restrict__ eps, int n4) {
    float s = 1.0f + *eps;
    int i = blockIdx.x * blockDim.x + threadIdx.x;
    if (i < n4) {
        float4 v = in[i];
        v.x *= s; v.y *= s; v.z *= s; v.w *= s;
        out[i] = v;
    }
}

__global__ void scatter_add_kernel(const float* __restrict__ h, float* __restrict__ out,
                                   const int* __restrict__ src, const int* __restrict__ dst,
                                   int nEdges, int F) {
    int warp = (blockIdx.x * blockDim.x + threadIdx.x) >> 5;
    int lane = threadIdx.x & 31;
    if (warp >= nEdges) return;
    int s = src[warp], d = dst[warp];
    const float4* hs = (const float4*)(h + (size_t)s * F);
    float* od = out + (size_t)d * F;
    int f4 = F >> 2;
    for (int i = lane; i < f4; i += 32) {
        float4 v = hs[i];
        atomicAdd(od + 4 * i + 0, v.x);
        atomicAdd(od + 4 * i + 1, v.y);
        atomicAdd(od + 4 * i + 2, v.z);
        atomicAdd(od + 4 * i + 3, v.w);
    }
}

__global__ void split_kernel(const float4* __restrict__ in, uint32_t* __restrict__ hi,
                             uint32_t* __restrict__ lo, int n4) {
    int i = blockIdx.x * blockDim.x + threadIdx.x;
    if (i >= n4) return;
    float4 v = in[i];
    __nv_bfloat16 h0 = __float2bfloat16(v.x), h1 = __float2bfloat16(v.y);
    __nv_bfloat16 h2 = __float2bfloat16(v.z), h3 = __float2bfloat16(v.w);
    __nv_bfloat16 l0 = __float2bfloat16(v.x - __bfloat162float(h0));
    __nv_bfloat16 l1 = __float2bfloat16(v.y - __bfloat162float(h1));
    __nv_bfloat16 l2 = __float2bfloat16(v.z - __bfloat162float(h2));
    __nv_bfloat16 l3 = __float2bfloat16(v.w - __bfloat162float(h3));
    hi[2 * i]     = (uint32_t)__bfloat16_as_ushort(h0) | ((uint32_t)__bfloat16_as_ushort(h1) << 16);
    hi[2 * i + 1] = (uint32_t)__bfloat16_as_ushort(h2) | ((uint32_t)__bfloat16_as_ushort(h3) << 16);
    lo[2 * i]     = (uint32_t)__bfloat16_as_ushort(l0) | ((uint32_t)__bfloat16_as_ushort(l1) << 16);
    lo[2 * i + 1] = (uint32_t)__bfloat16_as_ushort(l2) | ((uint32_t)__bfloat16_as_ushort(l3) << 16);
}

// W[K,N] f32 -> Wh[N,K], Wl[N,K] bf16 (transpose + split)
__global__ void wsplit_kernel(const float* __restrict__ W, __nv_bfloat16* __restrict__ Wh,
                              __nv_bfloat16* __restrict__ Wl, int K, int N) {
    __shared__ float t[32][33];
    int n0 = blockIdx.x * 32, k0 = blockIdx.y * 32;
    int tx = threadIdx.x, ty = threadIdx.y;
#pragma unroll
    for (int i = 0; i < 4; i++)
        t[ty + i * 8][tx] = W[(size_t)(k0 + ty + i * 8) * N + n0 + tx];
    __syncthreads();
#pragma unroll
    for (int i = 0; i < 4; i++) {
        float v = t[tx][ty + i * 8];
        __nv_bfloat16 h = __float2bfloat16(v);
        __nv_bfloat16 l = __float2bfloat16(v - __bfloat162float(h));
        size_t o = (size_t)(n0 + ty + i * 8) * K + k0 + tx;
        Wh[o] = h;
        Wl[o] = l;
    }
}

__global__ void __launch_bounds__(256)
edge_pred_kernel(const float* __restrict__ h, const int* __restrict__ ei,
                 const int* __restrict__ train_id, const float* __restrict__ W,
                 const float* __restrict__ b, float* __restrict__ out) {
    __shared__ float sW[HIDDEN * N_CLASS];
    __shared__ float sb[N_CLASS];
    for (int i = threadIdx.x; i < HIDDEN * N_CLASS; i += blockDim.x) sW[i] = W[i];
    if (threadIdx.x < N_CLASS) sb[threadIdx.x] = b[threadIdx.x];
    __syncthreads();
    int warp = (blockIdx.x * blockDim.x + threadIdx.x) >> 5;
    int lane = threadIdx.x & 31;
    if (warp >= N_TRAIN) return;
    int te = train_id[warp];
    int n0 = ei[te], n1 = ei[N_EDGES + te];
    const float4* h0 = (const float4*)(h + (size_t)n0 * HIDDEN);
    const float4* h1 = (const float4*)(h + (size_t)n1 * HIDDEN);
    float acc[N_CLASS];
#pragma unroll
    for (int j = 0; j < N_CLASS; j++) acc[j] = 0.0f;
    for (int k4 = lane; k4 < HIDDEN / 4; k4 += 32) {
        float4 a = h0[k4], c = h1[k4];
        float p0 = a.x * c.x, p1 = a.y * c.y, p2 = a.z * c.z, p3 = a.w * c.w;
        int k = k4 * 4;
#pragma unroll
        for (int j = 0; j < N_CLASS; j++)
            acc[j] += p0 * sW[(k + 0) * N_CLASS + j] + p1 * sW[(k + 1) * N_CLASS + j] +
                      p2 * sW[(k + 2) * N_CLASS + j] + p3 * sW[(k + 3) * N_CLASS + j];
    }
#pragma unroll
    for (int j = 0; j < N_CLASS; j++)
#pragma unroll
        for (int off = 16; off > 0; off >>= 1)
            acc[j] += __shfl_xor_sync(0xffffffffu, acc[j], off);
    if (lane == 0) {
#pragma unroll
        for (int j = 0; j < N_CLASS; j++)
            out[(size_t)warp * N_CLASS + j] = acc[j] + sb[j];
    }
}

// ---------------- launcher ----------------
extern "C" void kernel_launch(void* const* d_in, const int* in_sizes, int n_in,
                              void* d_out, int out_size) {
    const float* x     = (const float*)d_in[0];
    const int*   ei    = (const int*)d_in[1];
    const int*   trid  = (const int*)d_in[2];
    const float* W1    = (const float*)d_in[3];
    const float* b1    = (const float*)d_in[4];
    const float* W2    = (const float*)d_in[5];
    const float* b2    = (const float*)d_in[6];
    const float* W3    = (const float*)d_in[7];
    const float* b3    = (const float*)d_in[8];
    const float* bn1g  = (const float*)d_in[9];
    const float* bn1b  = (const float*)d_in[10];
    const float* bn1m  = (const float*)d_in[11];
    const float* bn1v  = (const float*)d_in[12];
    const float* eps1  = (const float*)d_in[13];
    const float* W4    = (const float*)d_in[14];
    const float* b4    = (const float*)d_in[15];
    const float* bn2g  = (const float*)d_in[16];
    const float* bn2b  = (const float*)d_in[17];
    const float* bn2m  = (const float*)d_in[18];
    const float* bn2v  = (const float*)d_in[19];
    const float* eps2  = (const float*)d_in[20];
    const float* lin1W = (const float*)d_in[21];
    const float* lin1b = (const float*)d_in[22];
    const float* lin2W = (const float*)d_in[23];
    const float* lin2b = (const float*)d_in[24];
    const float* fc2W  = (const float*)d_in[25];
    const float* fc2b  = (const float*)d_in[26];
    float* out = (float*)d_out;

    float *bufA, *bufB, *agg0;
    __nv_bfloat16 *hA, *lA, *hB, *lB, *wh, *wl;
    cudaGetSymbolAddress((void**)&bufA, g_bufA);
    cudaGetSymbolAddress((void**)&bufB, g_bufB);
    cudaGetSymbolAddress((void**)&agg0, g_agg0);
    cudaGetSymbolAddress((void**)&hA, g_hA);
    cudaGetSymbolAddress((void**)&lA, g_lA);
    cudaGetSymbolAddress((void**)&hB, g_hB);
    cudaGetSymbolAddress((void**)&lB, g_lB);
    cudaGetSymbolAddress((void**)&wh, g_wh);
    cudaGetSymbolAddress((void**)&wl, g_wl);

    cudaFuncSetAttribute(hmma_gemm_kernel<true, false, false>,
                         cudaFuncAttributeMaxDynamicSharedMemorySize, SMEMSZ);
    cudaFuncSetAttribute(hmma_gemm_kernel<true, true, true>,
                         cudaFuncAttributeMaxDynamicSharedMemorySize, SMEMSZ);
    cudaFuncSetAttribute(hmma_gemm_kernel<true, true, false>,
                         cudaFuncAttributeMaxDynamicSharedMemorySize, SMEMSZ);
    cudaFuncSetAttribute(hmma_gemm_kernel<false, false, true>,
                         cudaFuncAttributeMaxDynamicSharedMemorySize, SMEMSZ);

    const int* src = ei;
    const int* dst = ei + N_EDGES;

    // weight transpose + split
    dim3 wb(32, 8);
    wsplit_kernel<<<dim3(16, 2), wb>>>(W1, wh + 0 * WSLOT, wl + 0 * WSLOT, IN_F, HIDDEN);
    wsplit_kernel<<<dim3(16, 16), wb>>>(W2, wh + 1 * WSLOT, wl + 1 * WSLOT, HIDDEN, HIDDEN);
    wsplit_kernel<<<dim3(16, 16), wb>>>(W3, wh + 2 * WSLOT, wl + 2 * WSLOT, HIDDEN, HIDDEN);
    wsplit_kernel<<<dim3(16, 16), wb>>>(W4, wh + 3 * WSLOT, wl + 3 * WSLOT, HIDDEN, HIDDEN);
    wsplit_kernel<<<dim3(16, 16), wb>>>(lin1W, wh + 4 * WSLOT, wl + 4 * WSLOT, HIDDEN, HIDDEN);
    wsplit_kernel<<<dim3(16, 16), wb>>>(lin2W, wh + 5 * WSLOT, wl + 5 * WSLOT, HIDDEN, HIDDEN);

    // agg1 on x (fp32) then split
    {
        int n4 = N_NODES * IN_F / 4;
        scale_copy_kernel<<<(n4 + 255) / 256, 256>>>((const float4*)x, (float4*)agg0, eps1, n4);
        scatter_add_kernel<<<(N_EDGES * 32 + 255) / 256, 256>>>(x, agg0, src, dst, N_EDGES, IN_F);
        split_kernel<<<(n4 + 255) / 256, 256>>>((const float4*)agg0, (uint32_t*)hA, (uint32_t*)lA, n4);
    }

    dim3 gg(HIDDEN / GBN, (N_NODES + GBM - 1) / GBM);  // (4, 391)

    // L1: relu(agg @ W1 + b1) -> split pair
    hmma_gemm_kernel<true, false, false><<<gg, 256, SMEMSZ>>>(
        hA, lA, wh + 0 * WSLOT, wl + 0 * WSLOT, b1, nullptr, nullptr, nullptr, nullptr,
        nullptr, nullptr, nullptr, hB, lB, N_NODES, IN_F);
    // L2: relu(h @ W2 + b2) -> split pair
    hmma_gemm_kernel<true, false, false><<<gg, 256, SMEMSZ>>>(
        hB, lB, wh + 1 * WSLOT, wl + 1 * WSLOT, b2, nullptr, nullptr, nullptr, nullptr,
        nullptr, nullptr, nullptr, hA, lA, N_NODES, HIDDEN);
    // L3: bn1(relu(h @ W3 + b3)) -> fp32 bufA + (1+eps2)-scaled bufB (fused)
    hmma_gemm_kernel<true, true, true><<<gg, 256, SMEMSZ>>>(
        hA, lA, wh + 2 * WSLOT, wl + 2 * WSLOT, b3, bn1g, bn1b, bn1m, bn1v,
        bufA, bufB, eps2, nullptr, nullptr, N_NODES, HIDDEN);
    // agg2: bufB += bufA[src] scattered, then split
    {
        int n4 = N_NODES * HIDDEN / 4;
        scatter_add_kernel<<<(N_EDGES * 32 + 255) / 256, 256>>>(bufA, bufB, src, dst, N_EDGES, HIDDEN);
        split_kernel<<<(n4 + 255) / 256, 256>>>((const float4*)bufB, (uint32_t*)hA, (uint32_t*)lA, n4);
    }
    // L4: bn2(relu(h @ W4 + b4)) -> split pair
    hmma_gemm_kernel<true, true, false><<<gg, 256, SMEMSZ>>>(
        hA, lA, wh + 3 * WSLOT, wl + 3 * WSLOT, b4, bn2g, bn2b, bn2m, bn2v,
        nullptr, nullptr, nullptr, hB, lB, N_NODES, HIDDEN);
    // L5: relu(h @ lin1W + lin1b) -> split pair
    hmma_gemm_kernel<true, false, false><<<gg, 256, SMEMSZ>>>(
        hB, lB, wh + 4 * WSLOT, wl + 4 * WSLOT, lin1b, nullptr, nullptr, nullptr, nullptr,
        nullptr, nullptr, nullptr, hA, lA, N_NODES, HIDDEN);
    // L6: h @ lin2W + lin2b -> fp32
    hmma_gemm_kernel<false, false, true><<<gg, 256, SMEMSZ>>>(
        hA, lA, wh + 5 * WSLOT, wl + 5 * WSLOT, lin2b, nullptr, nullptr, nullptr, nullptr,
        bufA, nullptr, nullptr, nullptr, nullptr, N_NODES, HIDDEN);
    // edge classifier
    edge_pred_kernel<<<(N_TRAIN * 32 + 255) / 256, 256>>>(bufA, ei, trid, fc2W, fc2b, out);
}

// round 9
// speedup vs baseline: 2.0192x; 1.0859x over previous
#include <cuda_runtime.h>
#include <cuda_bf16.h>
#include <cstdint>

#define N_NODES 50000
#define IN_F    64
#define HIDDEN  512
#define N_EDGES 160000
#define N_TRAIN 80000
#define N_CLASS 7
#define BN_EPS  1e-5f

// ---------------- static device scratch (no allocation) ----------------
__device__ __align__(16) float g_bufA[(size_t)N_NODES * HIDDEN];
__device__ __align__(16) float g_bufB[(size_t)N_NODES * HIDDEN];
__device__ __align__(16) float g_agg0[(size_t)N_NODES * IN_F];
__device__ __align__(16) __nv_bfloat16 g_hA[(size_t)N_NODES * HIDDEN];
__device__ __align__(16) __nv_bfloat16 g_lA[(size_t)N_NODES * HIDDEN];
__device__ __align__(16) __nv_bfloat16 g_hB[(size_t)N_NODES * HIDDEN];
__device__ __align__(16) __nv_bfloat16 g_lB[(size_t)N_NODES * HIDDEN];
#define WSLOT (HIDDEN * HIDDEN)
__device__ __align__(16) __nv_bfloat16 g_wh[6 * WSLOT];
__device__ __align__(16) __nv_bfloat16 g_wl[6 * WSLOT];

// ---------------- PTX helpers (base-target only: sm_80/90-class) ----------------
__device__ __forceinline__ uint32_t cvta_shared(const void* p) {
    uint32_t a;
    asm("{ .reg .u64 t; cvta.to.shared.u64 t, %1; cvt.u32.u64 %0, t; }" : "=r"(a) : "l"(p));
    return a;
}
#define CP16(dst, src) \
    asm volatile("cp.async.cg.shared.global [%0], [%1], 16;" :: "r"(dst), "l"(src))
#define CP_COMMIT() asm volatile("cp.async.commit_group;" ::: "memory")
#define CP_WAIT1()  asm volatile("cp.async.wait_group 1;" ::: "memory")

__device__ __forceinline__ void ldm4(uint32_t* r, uint32_t addr) {
    asm volatile("ldmatrix.sync.aligned.m8n8.x4.shared.b16 {%0,%1,%2,%3}, [%4];"
        : "=r"(r[0]), "=r"(r[1]), "=r"(r[2]), "=r"(r[3]) : "r"(addr));
}
__device__ __forceinline__ void mma16816(float* d, const uint32_t* a, const uint32_t* b) {
    asm volatile(
        "mma.sync.aligned.m16n8k16.row.col.f32.bf16.bf16.f32 "
        "{%0,%1,%2,%3},{%4,%5,%6,%7},{%8,%9},{%0,%1,%2,%3};"
        : "+f"(d[0]), "+f"(d[1]), "+f"(d[2]), "+f"(d[3])
        : "r"(a[0]), "r"(a[1]), "r"(a[2]), "r"(a[3]), "r"(b[0]), "r"(b[1]));
}
// vectorized global reduction (PTX ISA 8.1, sm_90 base target)
__device__ __forceinline__ void red_add_v4(float* addr, float4 v) {
    asm volatile("red.global.add.v4.f32 [%0], {%1, %2, %3, %4};"
        :: "l"(addr), "f"(v.x), "f"(v.y), "f"(v.z), "f"(v.w) : "memory");
}

// swizzle: logical (row, 16B-chunk c in 0..3) -> phys byte offset within a
// 64B-row matrix tile. chunk' = c ^ ((row>>1)&3): any 8 consecutive rows at a
// fixed logical chunk hit 8 distinct 16B bank groups -> ldmatrix conflict-free.
__device__ __forceinline__ uint32_t swz(uint32_t row, uint32_t c) {
    return row * 64u + ((c ^ ((row >> 1) & 3u)) << 4);
}

// ---------------- HMMA split-bf16 GEMM ----------------
// C[M,512] = A[M,K] @ B[512,K]^T with A=(Ah+Al), B=(Bh+Bl) bf16.
// CTA 128x128, BK=32, 3-stage cp.async, swizzled 64B rows, 2 CTAs/SM.
#define GBM   128
#define GBN   128
#define GBK   32
#define MATB  (128 * 64)             // 8192 per matrix per stage
#define STB   (4 * MATB)             // 32768 per stage (Ah,Al,Bh,Bl)
#define NSTAGE 3
#define SMEMSZ (NSTAGE * STB)        // 98304 -> 2 CTAs/SM

template <bool RELU, bool BN_EN, bool OUTF32>
__global__ void __launch_bounds__(256, 2)
hmma_gemm_kernel(const __nv_bfloat16* __restrict__ Ah, const __nv_bfloat16* __restrict__ Al,
                 const __nv_bfloat16* __restrict__ Bh, const __nv_bfloat16* __restrict__ Bl,
                 const float* __restrict__ bias,
                 const float* __restrict__ bng, const float* __restrict__ bnb,
                 const float* __restrict__ bnm, const float* __restrict__ bnv,
                 float* __restrict__ Cf, float* __restrict__ Cf2,
                 const float* __restrict__ epsp,
                 __nv_bfloat16* __restrict__ Ch, __nv_bfloat16* __restrict__ Cl,
                 int M, int K) {
    extern __shared__ char smem[];
    const uint32_t sb = cvta_shared(smem);
    const int tid = threadIdx.x, lane = tid & 31, wid = tid >> 5;
    const int wm = wid >> 1, wn = wid & 1;           // 4x2 warp grid
    const int rowBase = blockIdx.y * GBM;
    const int colBase = blockIdx.x * GBN;
    const int NC = K / GBK;

    float acc[2][8][4];
#pragma unroll
    for (int a = 0; a < 2; a++)
#pragma unroll
        for (int b = 0; b < 8; b++)
#pragma unroll
            for (int c = 0; c < 4; c++) acc[a][b][c] = 0.0f;

    auto load_stage = [&](int c) {
        const int st = c % NSTAGE;
        const uint32_t base = sb + st * STB;
        const int kOff = c * GBK;
#pragma unroll
        for (int u = 0; u < 2; u++) {
            int idx = tid + u * 256;
            uint32_t row = (uint32_t)idx >> 2, ch = (uint32_t)idx & 3;
            int gr = rowBase + (int)row;
            if (gr > M - 1) gr = M - 1;              // clamp (finite junk, rows not stored)
            size_t ga = (size_t)gr * K + kOff + ch * 8;
            uint32_t so = swz(row, ch);
            CP16(base + so, Ah + ga);
            CP16(base + MATB + so, Al + ga);
            size_t gb = (size_t)(colBase + (int)row) * K + kOff + ch * 8;
            CP16(base + 2 * MATB + so, Bh + gb);
            CP16(base + 3 * MATB + so, Bl + gb);
        }
        CP_COMMIT();
    };

    // ldmatrix per-lane row indices (chunk varies with ks -> swizzled per use)
    const uint32_t mrow = (uint32_t)((lane & 7) + ((lane >> 3) & 1) * 8);
    const uint32_t aChunkBit = (uint32_t)(lane >> 4);          // 0/1
    const uint32_t nrow = (uint32_t)((lane & 7) + ((lane >> 4) << 3));
    const uint32_t bChunkBit = (uint32_t)((lane >> 3) & 1);    // 0/1

    load_stage(0);
    if (NC > 1) load_stage(1); else CP_COMMIT();

    for (int c = 0; c < NC; c++) {
        CP_WAIT1();                           // stage c complete
        __syncthreads();
        if (c + 2 < NC) load_stage(c + 2);
        else            CP_COMMIT();          // keep group count uniform

        const int st = c % NSTAGE;
        const uint32_t aB = sb + st * STB;
        const uint32_t bB = aB + 2 * MATB;
#pragma unroll
        for (int ks = 0; ks < 2; ks++) {      // two k16 steps per BK=32
            const uint32_t cA = (uint32_t)ks * 2 + aChunkBit;
            const uint32_t cB = (uint32_t)ks * 2 + bChunkBit;
            uint32_t ahf[2][4], alf[2][4], bhf[4][4], blf[4][4];
#pragma unroll
            for (int mt = 0; mt < 2; mt++) {
                uint32_t ad = aB + swz((uint32_t)(wm * 32 + mt * 16) + mrow, cA);
                ldm4(ahf[mt], ad);
                ldm4(alf[mt], ad + MATB);
            }
#pragma unroll
            for (int jp = 0; jp < 4; jp++) {
                uint32_t bd = bB + swz((uint32_t)(wn * 64 + jp * 16) + nrow, cB);
                ldm4(bhf[jp], bd);
                ldm4(blf[jp], bd + MATB);
            }
#pragma unroll
            for (int mt = 0; mt < 2; mt++)
#pragma unroll
                for (int j = 0; j < 8; j++)
                    mma16816(acc[mt][j], ahf[mt], &bhf[j >> 1][(j & 1) * 2]);
#pragma unroll
            for (int mt = 0; mt < 2; mt++)
#pragma unroll
                for (int j = 0; j < 8; j++)
                    mma16816(acc[mt][j], ahf[mt], &blf[j >> 1][(j & 1) * 2]);
#pragma unroll
            for (int mt = 0; mt < 2; mt++)
#pragma unroll
                for (int j = 0; j < 8; j++)
                    mma16816(acc[mt][j], alf[mt], &bhf[j >> 1][(j & 1) * 2]);
        }
        // no trailing sync needed: 3 distinct stage buffers; the next
        // iteration's top sync orders all compute before buffer reuse.
    }

    // ---------------- epilogue (direct from registers) ----------------
    const int g = lane >> 2, t = lane & 3;
    const float es = (OUTF32 && Cf2) ? (1.0f + *epsp) : 0.0f;
#pragma unroll
    for (int mt = 0; mt < 2; mt++) {
        int rbase = rowBase + wm * 32 + mt * 16 + g;
#pragma unroll
        for (int half = 0; half < 2; half++) {
            int r = rbase + half * 8;
            if (r >= M) continue;
#pragma unroll
            for (int j = 0; j < 8; j++) {
                int cidx = colBase + wn * 64 + j * 8 + 2 * t;
                float v0 = acc[mt][j][half * 2 + 0] + bias[cidx];
                float v1 = acc[mt][j][half * 2 + 1] + bias[cidx + 1];
                if (RELU) { v0 = fmaxf(v0, 0.0f); v1 = fmaxf(v1, 0.0f); }
                if (BN_EN) {
                    v0 = (v0 - bnm[cidx]) * rsqrtf(bnv[cidx] + BN_EPS) * bng[cidx] + bnb[cidx];
                    v1 = (v1 - bnm[cidx + 1]) * rsqrtf(bnv[cidx + 1] + BN_EPS) * bng[cidx + 1] + bnb[cidx + 1];
                }
                if (OUTF32) {
                    *(float2*)(Cf + (size_t)r * HIDDEN + cidx) = make_float2(v0, v1);
                    if (Cf2)
                        *(float2*)(Cf2 + (size_t)r * HIDDEN + cidx) =
                            make_float2(v0 * es, v1 * es);
                } else {
                    __nv_bfloat16 h0 = __float2bfloat16(v0);
                    __nv_bfloat16 h1 = __float2bfloat16(v1);
                    __nv_bfloat16 l0 = __float2bfloat16(v0 - __bfloat162float(h0));
                    __nv_bfloat16 l1 = __float2bfloat16(v1 - __bfloat162float(h1));
                    *(uint32_t*)(Ch + (size_t)r * HIDDEN + cidx) =
                        (uint32_t)__bfloat16_as_ushort(h0) | ((uint32_t)__bfloat16_as_ushort(h1) << 16);
                    *(uint32_t*)(Cl + (size_t)r * HIDDEN + cidx) =
                        (uint32_t)__bfloat16_as_ushort(l0) | ((uint32_t)__bfloat16_as_ushort(l1) << 16);
                }
            }
        }
    }
}

// ---------------- auxiliary kernels ----------------
__global__ void scale_copy_kernel(const float4* __restrict__ in, float4* __restrict__ out,
                                  const float* __restrict__ eps, int n4) {
    float s = 1.0f + *eps;
    int i = blockIdx.x * blockDim.x + threadIdx.x;
    if (i < n4) {
        float4 v = in[i];
        v.x *= s; v.y *= s; v.z *= s; v.w *= s;
        out[i] = v;
    }
}

// out[dst[e]] += h[src[e]]  -- one warp/edge, float4 loads, v4 vector reductions
__global__ void scatter_add_kernel(const float* __restrict__ h, float* __restrict__ out,
                                   const int* __restrict__ src, const int* __restrict__ dst,
                                   int nEdges, int F) {
    int warp = (blockIdx.x * blockDim.x + threadIdx.x) >> 5;
    int lane = threadIdx.x & 31;
    if (warp >= nEdges) return;
    int s = src[warp], d = dst[warp];
    const float4* hs = (const float4*)(h + (size_t)s * F);
    float* od = out + (size_t)d * F;
    int f4 = F >> 2;
    for (int i = lane; i < f4; i += 32) {
        float4 v = hs[i];
        red_add_v4(od + 4 * i, v);
    }
}

__global__ void split_kernel(const float4* __restrict__ in, uint32_t* __restrict__ hi,
                             uint32_t* __restrict__ lo, int n4) {
    int i = blockIdx.x * blockDim.x + threadIdx.x;
    if (i >= n4) return;
    float4 v = in[i];
    __nv_bfloat16 h0 = __float2bfloat16(v.x), h1 = __float2bfloat16(v.y);
    __nv_bfloat16 h2 = __float2bfloat16(v.z), h3 = __float2bfloat16(v.w);
    __nv_bfloat16 l0 = __float2bfloat16(v.x - __bfloat162float(h0));
    __nv_bfloat16 l1 = __float2bfloat16(v.y - __bfloat162float(h1));
    __nv_bfloat16 l2 = __float2bfloat16(v.z - __bfloat162float(h2));
    __nv_bfloat16 l3 = __float2bfloat16(v.w - __bfloat162float(h3));
    hi[2 * i]     = (uint32_t)__bfloat16_as_ushort(h0) | ((uint32_t)__bfloat16_as_ushort(h1) << 16);
    hi[2 * i + 1] = (uint32_t)__bfloat16_as_ushort(h2) | ((uint32_t)__bfloat16_as_ushort(h3) << 16);
    lo[2 * i]     = (uint32_t)__bfloat16_as_ushort(l0) | ((uint32_t)__bfloat16_as_ushort(l1) << 16);
    lo[2 * i + 1] = (uint32_t)__bfloat16_as_ushort(l2) | ((uint32_t)__bfloat16_as_ushort(l3) << 16);
}

// W[K,N] f32 -> Wh[N,K], Wl[N,K] bf16 (transpose + split)
__global__ void wsplit_kernel(const float* __restrict__ W, __nv_bfloat16* __restrict__ Wh,
                              __nv_bfloat16* __restrict__ Wl, int K, int N) {
    __shared__ float t[32][33];
    int n0 = blockIdx.x * 32, k0 = blockIdx.y * 32;
    int tx = threadIdx.x, ty = threadIdx.y;
#pragma unroll
    for (int i = 0; i < 4; i++)
        t[ty + i * 8][tx] = W[(size_t)(k0 + ty + i * 8) * N + n0 + tx];
    __syncthreads();
#pragma unroll
    for (int i = 0; i < 4; i++) {
        float v = t[tx][ty + i * 8];
        __nv_bfloat16 h = __float2bfloat16(v);
        __nv_bfloat16 l = __float2bfloat16(v - __bfloat162float(h));
        size_t o = (size_t)(n0 + ty + i * 8) * K + k0 + tx;
        Wh[o] = h;
        Wl[o] = l;
    }
}

__global__ void __launch_bounds__(256)
edge_pred_kernel(const float* __restrict__ h, const int* __restrict__ ei,
                 const int* __restrict__ train_id, const float* __restrict__ W,
                 const float* __restrict__ b, float* __restrict__ out) {
    __shared__ float sW[HIDDEN * N_CLASS];
    __shared__ float sb[N_CLASS];
    for (int i = threadIdx.x; i < HIDDEN * N_CLASS; i += blockDim.x) sW[i] = W[i];
    if (threadIdx.x < N_CLASS) sb[threadIdx.x] = b[threadIdx.x];
    __syncthreads();
    int warp = (blockIdx.x * blockDim.x + threadIdx.x) >> 5;
    int lane = threadIdx.x & 31;
    if (warp >= N_TRAIN) return;
    int te = train_id[warp];
    int n0 = ei[te], n1 = ei[N_EDGES + te];
    const float4* h0 = (const float4*)(h + (size_t)n0 * HIDDEN);
    const float4* h1 = (const float4*)(h + (size_t)n1 * HIDDEN);
    float acc[N_CLASS];
#pragma unroll
    for (int j = 0; j < N_CLASS; j++) acc[j] = 0.0f;
    for (int k4 = lane; k4 < HIDDEN / 4; k4 += 32) {
        float4 a = h0[k4], c = h1[k4];
        float p0 = a.x * c.x, p1 = a.y * c.y, p2 = a.z * c.z, p3 = a.w * c.w;
        int k = k4 * 4;
#pragma unroll
        for (int j = 0; j < N_CLASS; j++)
            acc[j] += p0 * sW[(k + 0) * N_CLASS + j] + p1 * sW[(k + 1) * N_CLASS + j] +
                      p2 * sW[(k + 2) * N_CLASS + j] + p3 * sW[(k + 3) * N_CLASS + j];
    }
#pragma unroll
    for (int j = 0; j < N_CLASS; j++)
#pragma unroll
        for (int off = 16; off > 0; off >>= 1)
            acc[j] += __shfl_xor_sync(0xffffffffu, acc[j], off);
    if (lane == 0) {
#pragma unroll
        for (int j = 0; j < N_CLASS; j++)
            out[(size_t)warp * N_CLASS + j] = acc[j] + sb[j];
    }
}

// ---------------- launcher ----------------
extern "C" void kernel_launch(void* const* d_in, const int* in_sizes, int n_in,
                              void* d_out, int out_size) {
    const float* x     = (const float*)d_in[0];
    const int*   ei    = (const int*)d_in[1];
    const int*   trid  = (const int*)d_in[2];
    const float* W1    = (const float*)d_in[3];
    const float* b1    = (const float*)d_in[4];
    const float* W2    = (const float*)d_in[5];
    const float* b2    = (const float*)d_in[6];
    const float* W3    = (const float*)d_in[7];
    const float* b3    = (const float*)d_in[8];
    const float* bn1g  = (const float*)d_in[9];
    const float* bn1b  = (const float*)d_in[10];
    const float* bn1m  = (const float*)d_in[11];
    const float* bn1v  = (const float*)d_in[12];
    const float* eps1  = (const float*)d_in[13];
    const float* W4    = (const float*)d_in[14];
    const float* b4    = (const float*)d_in[15];
    const float* bn2g  = (const float*)d_in[16];
    const float* bn2b  = (const float*)d_in[17];
    const float* bn2m  = (const float*)d_in[18];
    const float* bn2v  = (const float*)d_in[19];
    const float* eps2  = (const float*)d_in[20];
    const float* lin1W = (const float*)d_in[21];
    const float* lin1b = (const float*)d_in[22];
    const float* lin2W = (const float*)d_in[23];
    const float* lin2b = (const float*)d_in[24];
    const float* fc2W  = (const float*)d_in[25];
    const float* fc2b  = (const float*)d_in[26];
    float* out = (float*)d_out;

    float *bufA, *bufB, *agg0;
    __nv_bfloat16 *hA, *lA, *hB, *lB, *wh, *wl;
    cudaGetSymbolAddress((void**)&bufA, g_bufA);
    cudaGetSymbolAddress((void**)&bufB, g_bufB);
    cudaGetSymbolAddress((void**)&agg0, g_agg0);
    cudaGetSymbolAddress((void**)&hA, g_hA);
    cudaGetSymbolAddress((void**)&lA, g_lA);
    cudaGetSymbolAddress((void**)&hB, g_hB);
    cudaGetSymbolAddress((void**)&lB, g_lB);
    cudaGetSymbolAddress((void**)&wh, g_wh);
    cudaGetSymbolAddress((void**)&wl, g_wl);

    cudaFuncSetAttribute(hmma_gemm_kernel<true, false, false>,
                         cudaFuncAttributeMaxDynamicSharedMemorySize, SMEMSZ);
    cudaFuncSetAttribute(hmma_gemm_kernel<true, true, true>,
                         cudaFuncAttributeMaxDynamicSharedMemorySize, SMEMSZ);
    cudaFuncSetAttribute(hmma_gemm_kernel<true, true, false>,
                         cudaFuncAttributeMaxDynamicSharedMemorySize, SMEMSZ);
    cudaFuncSetAttribute(hmma_gemm_kernel<false, false, true>,
                         cudaFuncAttributeMaxDynamicSharedMemorySize, SMEMSZ);

    const int* src = ei;
    const int* dst = ei + N_EDGES;

    // weight transpose + split
    dim3 wb(32, 8);
    wsplit_kernel<<<dim3(16, 2), wb>>>(W1, wh + 0 * WSLOT, wl + 0 * WSLOT, IN_F, HIDDEN);
    wsplit_kernel<<<dim3(16, 16), wb>>>(W2, wh + 1 * WSLOT, wl + 1 * WSLOT, HIDDEN, HIDDEN);
    wsplit_kernel<<<dim3(16, 16), wb>>>(W3, wh + 2 * WSLOT, wl + 2 * WSLOT, HIDDEN, HIDDEN);
    wsplit_kernel<<<dim3(16, 16), wb>>>(W4, wh + 3 * WSLOT, wl + 3 * WSLOT, HIDDEN, HIDDEN);
    wsplit_kernel<<<dim3(16, 16), wb>>>(lin1W, wh + 4 * WSLOT, wl + 4 * WSLOT, HIDDEN, HIDDEN);
    wsplit_kernel<<<dim3(16, 16), wb>>>(lin2W, wh + 5 * WSLOT, wl + 5 * WSLOT, HIDDEN, HIDDEN);

    // agg1 on x (fp32) then split
    {
        int n4 = N_NODES * IN_F / 4;
        scale_copy_kernel<<<(n4 + 255) / 256, 256>>>((const float4*)x, (float4*)agg0, eps1, n4);
        scatter_add_kernel<<<(N_EDGES * 32 + 255) / 256, 256>>>(x, agg0, src, dst, N_EDGES, IN_F);
        split_kernel<<<(n4 + 255) / 256, 256>>>((const float4*)agg0, (uint32_t*)hA, (uint32_t*)lA, n4);
    }

    dim3 gg(HIDDEN / GBN, (N_NODES + GBM - 1) / GBM);  // (4, 391)

    // L1: relu(agg @ W1 + b1) -> split pair
    hmma_gemm_kernel<true, false, false><<<gg, 256, SMEMSZ>>>(
        hA, lA, wh + 0 * WSLOT, wl + 0 * WSLOT, b1, nullptr, nullptr, nullptr, nullptr,
        nullptr, nullptr, nullptr, hB, lB, N_NODES, IN_F);
    // L2: relu(h @ W2 + b2) -> split pair
    hmma_gemm_kernel<true, false, false><<<gg, 256, SMEMSZ>>>(
        hB, lB, wh + 1 * WSLOT, wl + 1 * WSLOT, b2, nullptr, nullptr, nullptr, nullptr,
        nullptr, nullptr, nullptr, hA, lA, N_NODES, HIDDEN);
    // L3: bn1(relu(h @ W3 + b3)) -> fp32 bufA + (1+eps2)-scaled bufB (fused)
    hmma_gemm_kernel<true, true, true><<<gg, 256, SMEMSZ>>>(
        hA, lA, wh + 2 * WSLOT, wl + 2 * WSLOT, b3, bn1g, bn1b, bn1m, bn1v,
        bufA, bufB, eps2, nullptr, nullptr, N_NODES, HIDDEN);
    // agg2: bufB += bufA[src] scattered, then split
    {
        int n4 = N_NODES * HIDDEN / 4;
        scatter_add_kernel<<<(N_EDGES * 32 + 255) / 256, 256>>>(bufA, bufB, src, dst, N_EDGES, HIDDEN);
        split_kernel<<<(n4 + 255) / 256, 256>>>((const float4*)bufB, (uint32_t*)hA, (uint32_t*)lA, n4);
    }
    // L4: bn2(relu(h @ W4 + b4)) -> split pair
    hmma_gemm_kernel<true, true, false><<<gg, 256, SMEMSZ>>>(
        hA, lA, wh + 3 * WSLOT, wl + 3 * WSLOT, b4, bn2g, bn2b, bn2m, bn2v,
        nullptr, nullptr, nullptr, hB, lB, N_NODES, HIDDEN);
    // L5: relu(h @ lin1W + lin1b) -> split pair
    hmma_gemm_kernel<true, false, false><<<gg, 256, SMEMSZ>>>(
        hB, lB, wh + 4 * WSLOT, wl + 4 * WSLOT, lin1b, nullptr, nullptr, nullptr, nullptr,
        nullptr, nullptr, nullptr, hA, lA, N_NODES, HIDDEN);
    // L6: h @ lin2W + lin2b -> fp32
    hmma_gemm_kernel<false, false, true><<<gg, 256, SMEMSZ>>>(
        hA, lA, wh + 5 * WSLOT, wl + 5 * WSLOT, lin2b, nullptr, nullptr, nullptr, nullptr,
        bufA, nullptr, nullptr, nullptr, nullptr, N_NODES, HIDDEN);
    // edge classifier
    edge_pred_kernel<<<(N_TRAIN * 32 + 255) / 256, 256>>>(bufA, ei, trid, fc2W, fc2b, out);
}

// round 10
// speedup vs baseline: 2.7756x; 1.3746x over previous
#include <cuda_runtime.h>
#include <cuda_fp16.h>
#include <cstdint>

#define N_NODES 50000
#define IN_F    64
#define HIDDEN  512
#define N_EDGES 160000
#define N_TRAIN 80000
#define N_CLASS 7
#define BN_EPS  1e-5f

// ---------------- static device scratch (no allocation) ----------------
__device__ __align__(16) float g_bufA[(size_t)N_NODES * HIDDEN];
__device__ __align__(16) float g_bufB[(size_t)N_NODES * HIDDEN];
__device__ __align__(16) float g_agg0[(size_t)N_NODES * IN_F];
__device__ __align__(16) __half g_hA[(size_t)N_NODES * HIDDEN];
__device__ __align__(16) __half g_hB[(size_t)N_NODES * HIDDEN];
#define WSLOT (HIDDEN * HIDDEN)
__device__ __align__(16) __half g_wh[6 * WSLOT];
__device__ __align__(16) __half g_wl[6 * WSLOT];

// ---------------- PTX helpers (base-target only: sm_80/90-class) ----------------
__device__ __forceinline__ uint32_t cvta_shared(const void* p) {
    uint32_t a;
    asm("{ .reg .u64 t; cvta.to.shared.u64 t, %1; cvt.u32.u64 %0, t; }" : "=r"(a) : "l"(p));
    return a;
}
#define CP16(dst, src) \
    asm volatile("cp.async.cg.shared.global [%0], [%1], 16;" :: "r"(dst), "l"(src))
#define CP_COMMIT() asm volatile("cp.async.commit_group;" ::: "memory")
#define CP_WAIT1()  asm volatile("cp.async.wait_group 1;" ::: "memory")

__device__ __forceinline__ void ldm4(uint32_t* r, uint32_t addr) {
    asm volatile("ldmatrix.sync.aligned.m8n8.x4.shared.b16 {%0,%1,%2,%3}, [%4];"
        : "=r"(r[0]), "=r"(r[1]), "=r"(r[2]), "=r"(r[3]) : "r"(addr));
}
__device__ __forceinline__ void mma16816(float* d, const uint32_t* a, const uint32_t* b) {
    asm volatile(
        "mma.sync.aligned.m16n8k16.row.col.f32.f16.f16.f32 "
        "{%0,%1,%2,%3},{%4,%5,%6,%7},{%8,%9},{%0,%1,%2,%3};"
        : "+f"(d[0]), "+f"(d[1]), "+f"(d[2]), "+f"(d[3])
        : "r"(a[0]), "r"(a[1]), "r"(a[2]), "r"(a[3]), "r"(b[0]), "r"(b[1]));
}
// vectorized global reduction (PTX ISA 8.1, sm_90 base target)
__device__ __forceinline__ void red_add_v4(float* addr, float4 v) {
    asm volatile("red.global.add.v4.f32 [%0], {%1, %2, %3, %4};"
        :: "l"(addr), "f"(v.x), "f"(v.y), "f"(v.z), "f"(v.w) : "memory");
}
__device__ __forceinline__ uint32_t pack_h2(float a, float b) {
    __half2 h = __floats2half2_rn(a, b);
    return *(uint32_t*)&h;
}

// swizzle: logical (row, 16B-chunk c in 0..3) -> phys byte offset within a
// 64B-row matrix tile. chunk' = c ^ ((row>>1)&3): ldmatrix conflict-free.
__device__ __forceinline__ uint32_t swz(uint32_t row, uint32_t c) {
    return row * 64u + ((c ^ ((row >> 1) & 3u)) << 4);
}

// ---------------- HMMA asymmetric-split fp16 GEMM ----------------
// C[M,512] = A[M,K] @ (Wh+Wl)[512,K]^T, A single fp16, weights exact hi+lo.
// CTA 128x128, BK=32, 3-stage cp.async, swizzled 64B rows, 2 CTAs/SM.
#define GBM   128
#define GBN   128
#define GBK   32
#define MATB  (128 * 64)             // 8192 per matrix per stage
#define STB   (3 * MATB)             // 24576 per stage (A, Bh, Bl)
#define NSTAGE 3
#define SMEMSZ (NSTAGE * STB)        // 73728 -> 2 CTAs/SM

template <bool RELU, bool BN_EN, bool OUTF32>
__global__ void __launch_bounds__(256, 2)
hmma_gemm_kernel(const __half* __restrict__ A,
                 const __half* __restrict__ Bh, const __half* __restrict__ Bl,
                 const float* __restrict__ bias,
                 const float* __restrict__ bng, const float* __restrict__ bnb,
                 const float* __restrict__ bnm, const float* __restrict__ bnv,
                 float* __restrict__ Cf, float* __restrict__ Cf2,
                 const float* __restrict__ epsp,
                 __half* __restrict__ Ch,
                 int M, int K) {
    extern __shared__ char smem[];
    const uint32_t sb = cvta_shared(smem);
    const int tid = threadIdx.x, lane = tid & 31, wid = tid >> 5;
    const int wm = wid >> 1, wn = wid & 1;           // 4x2 warp grid
    const int rowBase = blockIdx.y * GBM;
    const int colBase = blockIdx.x * GBN;
    const int NC = K / GBK;

    float acc[2][8][4];
#pragma unroll
    for (int a = 0; a < 2; a++)
#pragma unroll
        for (int b = 0; b < 8; b++)
#pragma unroll
            for (int c = 0; c < 4; c++) acc[a][b][c] = 0.0f;

    auto load_stage = [&](int c) {
        const int st = c % NSTAGE;
        const uint32_t base = sb + st * STB;
        const int kOff = c * GBK;
#pragma unroll
        for (int u = 0; u < 2; u++) {
            int idx = tid + u * 256;
            uint32_t row = (uint32_t)idx >> 2, ch = (uint32_t)idx & 3;
            int gr = rowBase + (int)row;
            if (gr > M - 1) gr = M - 1;              // clamp (finite junk, rows not stored)
            uint32_t so = swz(row, ch);
            CP16(base + so, A + (size_t)gr * K + kOff + ch * 8);
            size_t gb = (size_t)(colBase + (int)row) * K + kOff + ch * 8;
            CP16(base + MATB + so, Bh + gb);
            CP16(base + 2 * MATB + so, Bl + gb);
        }
        CP_COMMIT();
    };

    // ldmatrix per-lane row indices (chunk varies with ks -> swizzled per use)
    const uint32_t mrow = (uint32_t)((lane & 7) + ((lane >> 3) & 1) * 8);
    const uint32_t aChunkBit = (uint32_t)(lane >> 4);          // 0/1
    const uint32_t nrow = (uint32_t)((lane & 7) + ((lane >> 4) << 3));
    const uint32_t bChunkBit = (uint32_t)((lane >> 3) & 1);    // 0/1

    load_stage(0);
    if (NC > 1) load_stage(1); else CP_COMMIT();

    for (int c = 0; c < NC; c++) {
        CP_WAIT1();                           // stage c complete
        __syncthreads();
        if (c + 2 < NC) load_stage(c + 2);
        else            CP_COMMIT();          // keep group count uniform

        const int st = c % NSTAGE;
        const uint32_t aB = sb + st * STB;
        const uint32_t bB = aB + MATB;
#pragma unroll
        for (int ks = 0; ks < 2; ks++) {      // two k16 steps per BK=32
            const uint32_t cA = (uint32_t)ks * 2 + aChunkBit;
            const uint32_t cB = (uint32_t)ks * 2 + bChunkBit;
            uint32_t af[2][4], bhf[4][4], blf[4][4];
#pragma unroll
            for (int mt = 0; mt < 2; mt++)
                ldm4(af[mt], aB + swz((uint32_t)(wm * 32 + mt * 16) + mrow, cA));
#pragma unroll
            for (int jp = 0; jp < 4; jp++) {
                uint32_t bd = bB + swz((uint32_t)(wn * 64 + jp * 16) + nrow, cB);
                ldm4(bhf[jp], bd);
                ldm4(blf[jp], bd + MATB);
            }
#pragma unroll
            for (int mt = 0; mt < 2; mt++)
#pragma unroll
                for (int j = 0; j < 8; j++)
                    mma16816(acc[mt][j], af[mt], &bhf[j >> 1][(j & 1) * 2]);
#pragma unroll
            for (int mt = 0; mt < 2; mt++)
#pragma unroll
                for (int j = 0; j < 8; j++)
                    mma16816(acc[mt][j], af[mt], &blf[j >> 1][(j & 1) * 2]);
        }
        // no trailing sync needed: 3 distinct stage buffers; the next
        // iteration's top sync orders all compute before buffer reuse.
    }

    // ---------------- epilogue (direct from registers) ----------------
    const int g = lane >> 2, t = lane & 3;
    const float es = (OUTF32 && Cf2) ? (1.0f + *epsp) : 0.0f;
#pragma unroll
    for (int mt = 0; mt < 2; mt++) {
        int rbase = rowBase + wm * 32 + mt * 16 + g;
#pragma unroll
        for (int half = 0; half < 2; half++) {
            int r = rbase + half * 8;
            if (r >= M) continue;
#pragma unroll
            for (int j = 0; j < 8; j++) {
                int cidx = colBase + wn * 64 + j * 8 + 2 * t;
                float v0 = acc[mt][j][half * 2 + 0] + bias[cidx];
                float v1 = acc[mt][j][half * 2 + 1] + bias[cidx + 1];
                if (RELU) { v0 = fmaxf(v0, 0.0f); v1 = fmaxf(v1, 0.0f); }
                if (BN_EN) {
                    v0 = (v0 - bnm[cidx]) * rsqrtf(bnv[cidx] + BN_EPS) * bng[cidx] + bnb[cidx];
                    v1 = (v1 - bnm[cidx + 1]) * rsqrtf(bnv[cidx + 1] + BN_EPS) * bng[cidx + 1] + bnb[cidx + 1];
                }
                if (OUTF32) {
                    *(float2*)(Cf + (size_t)r * HIDDEN + cidx) = make_float2(v0, v1);
                    if (Cf2)
                        *(float2*)(Cf2 + (size_t)r * HIDDEN + cidx) =
                            make_float2(v0 * es, v1 * es);
                } else {
                    *(uint32_t*)(Ch + (size_t)r * HIDDEN + cidx) = pack_h2(v0, v1);
                }
            }
        }
    }
}

// ---------------- auxiliary kernels ----------------
__global__ void scale_copy_kernel(const float4* __restrict__ in, float4* __restrict__ out,
                                  const float* __restrict__ eps, int n4) {
    float s = 1.0f + *eps;
    int i = blockIdx.x * blockDim.x + threadIdx.x;
    if (i < n4) {
        float4 v = in[i];
        v.x *= s; v.y *= s; v.z *= s; v.w *= s;
        out[i] = v;
    }
}

// out[dst[e]] += h[src[e]]  -- one warp/edge, float4 loads, v4 vector reductions
__global__ void scatter_add_kernel(const float* __restrict__ h, float* __restrict__ out,
                                   const int* __restrict__ src, const int* __restrict__ dst,
                                   int nEdges, int F) {
    int warp = (blockIdx.x * blockDim.x + threadIdx.x) >> 5;
    int lane = threadIdx.x & 31;
    if (warp >= nEdges) return;
    int s = src[warp], d = dst[warp];
    const float4* hs = (const float4*)(h + (size_t)s * F);
    float* od = out + (size_t)d * F;
    int f4 = F >> 2;
    for (int i = lane; i < f4; i += 32) {
        float4 v = hs[i];
        red_add_v4(od + 4 * i, v);
    }
}

// fp32 -> fp16 cast (streaming)
__global__ void quant_kernel(const float4* __restrict__ in, uint32_t* __restrict__ q, int n4) {
    int i = blockIdx.x * blockDim.x + threadIdx.x;
    if (i >= n4) return;
    float4 v = in[i];
    q[2 * i]     = pack_h2(v.x, v.y);
    q[2 * i + 1] = pack_h2(v.z, v.w);
}

// W[K,N] f32 -> Wh[N,K], Wl[N,K] fp16 (transpose + exact split)
__global__ void wsplit_kernel(const float* __restrict__ W, __half* __restrict__ Wh,
                              __half* __restrict__ Wl, int K, int N) {
    __shared__ float t[32][33];
    int n0 = blockIdx.x * 32, k0 = blockIdx.y * 32;
    int tx = threadIdx.x, ty = threadIdx.y;
#pragma unroll
    for (int i = 0; i < 4; i++)
        t[ty + i * 8][tx] = W[(size_t)(k0 + ty + i * 8) * N + n0 + tx];
    __syncthreads();
#pragma unroll
    for (int i = 0; i < 4; i++) {
        float v = t[tx][ty + i * 8];
        __half h = __float2half_rn(v);
        __half l = __float2half_rn(v - __half2float(h));
        size_t o = (size_t)(n0 + ty + i * 8) * K + k0 + tx;
        Wh[o] = h;
        Wl[o] = l;
    }
}

__global__ void __launch_bounds__(256)
edge_pred_kernel(const float* __restrict__ h, const int* __restrict__ ei,
                 const int* __restrict__ train_id, const float* __restrict__ W,
                 const float* __restrict__ b, float* __restrict__ out) {
    __shared__ float sW[HIDDEN * N_CLASS];
    __shared__ float sb[N_CLASS];
    for (int i = threadIdx.x; i < HIDDEN * N_CLASS; i += blockDim.x) sW[i] = W[i];
    if (threadIdx.x < N_CLASS) sb[threadIdx.x] = b[threadIdx.x];
    __syncthreads();
    int warp = (blockIdx.x * blockDim.x + threadIdx.x) >> 5;
    int lane = threadIdx.x & 31;
    if (warp >= N_TRAIN) return;
    int te = train_id[warp];
    int n0 = ei[te], n1 = ei[N_EDGES + te];
    const float4* h0 = (const float4*)(h + (size_t)n0 * HIDDEN);
    const float4* h1 = (const float4*)(h + (size_t)n1 * HIDDEN);
    float acc[N_CLASS];
#pragma unroll
    for (int j = 0; j < N_CLASS; j++) acc[j] = 0.0f;
    for (int k4 = lane; k4 < HIDDEN / 4; k4 += 32) {
        float4 a = h0[k4], c = h1[k4];
        float p0 = a.x * c.x, p1 = a.y * c.y, p2 = a.z * c.z, p3 = a.w * c.w;
        int k = k4 * 4;
#pragma unroll
        for (int j = 0; j < N_CLASS; j++)
            acc[j] += p0 * sW[(k + 0) * N_CLASS + j] + p1 * sW[(k + 1) * N_CLASS + j] +
                      p2 * sW[(k + 2) * N_CLASS + j] + p3 * sW[(k + 3) * N_CLASS + j];
    }
#pragma unroll
    for (int j = 0; j < N_CLASS; j++)
#pragma unroll
        for (int off = 16; off > 0; off >>= 1)
            acc[j] += __shfl_xor_sync(0xffffffffu, acc[j], off);
    if (lane == 0) {
#pragma unroll
        for (int j = 0; j < N_CLASS; j++)
            out[(size_t)warp * N_CLASS + j] = acc[j] + sb[j];
    }
}

// ---------------- launcher ----------------
extern "C" void kernel_launch(void* const* d_in, const int* in_sizes, int n_in,
                              void* d_out, int out_size) {
    const float* x     = (const float*)d_in[0];
    const int*   ei    = (const int*)d_in[1];
    const int*   trid  = (const int*)d_in[2];
    const float* W1    = (const float*)d_in[3];
    const float* b1    = (const float*)d_in[4];
    const float* W2    = (const float*)d_in[5];
    const float* b2    = (const float*)d_in[6];
    const float* W3    = (const float*)d_in[7];
    const float* b3    = (const float*)d_in[8];
    const float* bn1g  = (const float*)d_in[9];
    const float* bn1b  = (const float*)d_in[10];
    const float* bn1m  = (const float*)d_in[11];
    const float* bn1v  = (const float*)d_in[12];
    const float* eps1  = (const float*)d_in[13];
    const float* W4    = (const float*)d_in[14];
    const float* b4    = (const float*)d_in[15];
    const float* bn2g  = (const float*)d_in[16];
    const float* bn2b  = (const float*)d_in[17];
    const float* bn2m  = (const float*)d_in[18];
    const float* bn2v  = (const float*)d_in[19];
    const float* eps2  = (const float*)d_in[20];
    const float* lin1W = (const float*)d_in[21];
    const float* lin1b = (const float*)d_in[22];
    const float* lin2W = (const float*)d_in[23];
    const float* lin2b = (const float*)d_in[24];
    const float* fc2W  = (const float*)d_in[25];
    const float* fc2b  = (const float*)d_in[26];
    float* out = (float*)d_out;

    float *bufA, *bufB, *agg0;
    __half *hA, *hB, *wh, *wl;
    cudaGetSymbolAddress((void**)&bufA, g_bufA);
    cudaGetSymbolAddress((void**)&bufB, g_bufB);
    cudaGetSymbolAddress((void**)&agg0, g_agg0);
    cudaGetSymbolAddress((void**)&hA, g_hA);
    cudaGetSymbolAddress((void**)&hB, g_hB);
    cudaGetSymbolAddress((void**)&wh, g_wh);
    cudaGetSymbolAddress((void**)&wl, g_wl);

    cudaFuncSetAttribute(hmma_gemm_kernel<true, false, false>,
                         cudaFuncAttributeMaxDynamicSharedMemorySize, SMEMSZ);
    cudaFuncSetAttribute(hmma_gemm_kernel<true, true, true>,
                         cudaFuncAttributeMaxDynamicSharedMemorySize, SMEMSZ);
    cudaFuncSetAttribute(hmma_gemm_kernel<true, true, false>,
                         cudaFuncAttributeMaxDynamicSharedMemorySize, SMEMSZ);
    cudaFuncSetAttribute(hmma_gemm_kernel<false, false, true>,
                         cudaFuncAttributeMaxDynamicSharedMemorySize, SMEMSZ);

    const int* src = ei;
    const int* dst = ei + N_EDGES;

    // weight transpose + exact hi/lo fp16 split
    dim3 wb(32, 8);
    wsplit_kernel<<<dim3(16, 2), wb>>>(W1, wh + 0 * WSLOT, wl + 0 * WSLOT, IN_F, HIDDEN);
    wsplit_kernel<<<dim3(16, 16), wb>>>(W2, wh + 1 * WSLOT, wl + 1 * WSLOT, HIDDEN, HIDDEN);
    wsplit_kernel<<<dim3(16, 16), wb>>>(W3, wh + 2 * WSLOT, wl + 2 * WSLOT, HIDDEN, HIDDEN);
    wsplit_kernel<<<dim3(16, 16), wb>>>(W4, wh + 3 * WSLOT, wl + 3 * WSLOT, HIDDEN, HIDDEN);
    wsplit_kernel<<<dim3(16, 16), wb>>>(lin1W, wh + 4 * WSLOT, wl + 4 * WSLOT, HIDDEN, HIDDEN);
    wsplit_kernel<<<dim3(16, 16), wb>>>(lin2W, wh + 5 * WSLOT, wl + 5 * WSLOT, HIDDEN, HIDDEN);

    // agg1 on x (fp32) then quantize to fp16
    {
        int n4 = N_NODES * IN_F / 4;
        scale_copy_kernel<<<(n4 + 255) / 256, 256>>>((const float4*)x, (float4*)agg0, eps1, n4);
        scatter_add_kernel<<<(N_EDGES * 32 + 255) / 256, 256>>>(x, agg0, src, dst, N_EDGES, IN_F);
        quant_kernel<<<(n4 + 255) / 256, 256>>>((const float4*)agg0, (uint32_t*)hA, n4);
    }

    dim3 gg(HIDDEN / GBN, (N_NODES + GBM - 1) / GBM);  // (4, 391)

    // L1: relu(agg @ W1 + b1) -> fp16
    hmma_gemm_kernel<true, false, false><<<gg, 256, SMEMSZ>>>(
        hA, wh + 0 * WSLOT, wl + 0 * WSLOT, b1, nullptr, nullptr, nullptr, nullptr,
        nullptr, nullptr, nullptr, hB, N_NODES, IN_F);
    // L2: relu(h @ W2 + b2) -> fp16
    hmma_gemm_kernel<true, false, false><<<gg, 256, SMEMSZ>>>(
        hB, wh + 1 * WSLOT, wl + 1 * WSLOT, b2, nullptr, nullptr, nullptr, nullptr,
        nullptr, nullptr, nullptr, hA, N_NODES, HIDDEN);
    // L3: bn1(relu(h @ W3 + b3)) -> fp32 bufA + (1+eps2)-scaled bufB (fused)
    hmma_gemm_kernel<true, true, true><<<gg, 256, SMEMSZ>>>(
        hA, wh + 2 * WSLOT, wl + 2 * WSLOT, b3, bn1g, bn1b, bn1m, bn1v,
        bufA, bufB, eps2, nullptr, N_NODES, HIDDEN);
    // agg2: bufB += bufA[src] scattered, then quantize
    {
        int n4 = N_NODES * HIDDEN / 4;
        scatter_add_kernel<<<(N_EDGES * 32 + 255) / 256, 256>>>(bufA, bufB, src, dst, N_EDGES, HIDDEN);
        quant_kernel<<<(n4 + 255) / 256, 256>>>((const float4*)bufB, (uint32_t*)hA, n4);
    }
    // L4: bn2(relu(h @ W4 + b4)) -> fp16
    hmma_gemm_kernel<true, true, false><<<gg, 256, SMEMSZ>>>(
        hA, wh + 3 * WSLOT, wl + 3 * WSLOT, b4, bn2g, bn2b, bn2m, bn2v,
        nullptr, nullptr, nullptr, hB, N_NODES, HIDDEN);
    // L5: relu(h @ lin1W + lin1b) -> fp16
    hmma_gemm_kernel<true, false, false><<<gg, 256, SMEMSZ>>>(
        hB, wh + 4 * WSLOT, wl + 4 * WSLOT, lin1b, nullptr, nullptr, nullptr, nullptr,
        nullptr, nullptr, nullptr, hA, N_NODES, HIDDEN);
    // L6: h @ lin2W + lin2b -> fp32
    hmma_gemm_kernel<false, false, true><<<gg, 256, SMEMSZ>>>(
        hA, wh + 5 * WSLOT, wl + 5 * WSLOT, lin2b, nullptr, nullptr, nullptr, nullptr,
        bufA, nullptr, nullptr, nullptr, N_NODES, HIDDEN);
    // edge classifier
    edge_pred_kernel<<<(N_TRAIN * 32 + 255) / 256, 256>>>(bufA, ei, trid, fc2W, fc2b, out);
}

// round 11
// speedup vs baseline: 3.7817x; 1.3625x over previous
#include <cuda_runtime.h>
#include <cuda_fp16.h>
#include <cstdint>

#define N_NODES 50000
#define IN_F    64
#define HIDDEN  512
#define N_EDGES 160000
#define N_TRAIN 80000
#define N_CLASS 7
#define BN_EPS  1e-5f

// ---------------- static device scratch (no allocation) ----------------
__device__ __align__(16) float g_bufA[(size_t)N_NODES * HIDDEN];
__device__ __align__(16) float g_bufB[(size_t)N_NODES * HIDDEN];
__device__ __align__(16) float g_agg0[(size_t)N_NODES * IN_F];
__device__ __align__(16) __half g_hA[(size_t)N_NODES * HIDDEN];
__device__ __align__(16) __half g_hB[(size_t)N_NODES * HIDDEN];
#define WSLOT (HIDDEN * HIDDEN)
__device__ __align__(16) __half g_wh[6 * WSLOT];

// ---------------- PTX helpers (base-target only: sm_80/90-class) ----------------
__device__ __forceinline__ uint32_t cvta_shared(const void* p) {
    uint32_t a;
    asm("{ .reg .u64 t; cvta.to.shared.u64 t, %1; cvt.u32.u64 %0, t; }" : "=r"(a) : "l"(p));
    return a;
}
#define CP16(dst, src) \
    asm volatile("cp.async.cg.shared.global [%0], [%1], 16;" :: "r"(dst), "l"(src))
#define CP_COMMIT() asm volatile("cp.async.commit_group;" ::: "memory")
#define CP_WAIT1()  asm volatile("cp.async.wait_group 1;" ::: "memory")

__device__ __forceinline__ void ldm4(uint32_t* r, uint32_t addr) {
    asm volatile("ldmatrix.sync.aligned.m8n8.x4.shared.b16 {%0,%1,%2,%3}, [%4];"
        : "=r"(r[0]), "=r"(r[1]), "=r"(r[2]), "=r"(r[3]) : "r"(addr));
}
__device__ __forceinline__ void mma16816(float* d, const uint32_t* a, const uint32_t* b) {
    asm volatile(
        "mma.sync.aligned.m16n8k16.row.col.f32.f16.f16.f32 "
        "{%0,%1,%2,%3},{%4,%5,%6,%7},{%8,%9},{%0,%1,%2,%3};"
        : "+f"(d[0]), "+f"(d[1]), "+f"(d[2]), "+f"(d[3])
        : "r"(a[0]), "r"(a[1]), "r"(a[2]), "r"(a[3]), "r"(b[0]), "r"(b[1]));
}
// vectorized global reduction (PTX ISA 8.1, sm_90 base target)
__device__ __forceinline__ void red_add_v4(float* addr, float4 v) {
    asm volatile("red.global.add.v4.f32 [%0], {%1, %2, %3, %4};"
        :: "l"(addr), "f"(v.x), "f"(v.y), "f"(v.z), "f"(v.w) : "memory");
}
__device__ __forceinline__ uint32_t pack_h2(float a, float b) {
    __half2 h = __floats2half2_rn(a, b);
    return *(uint32_t*)&h;
}

// swizzle: logical (row, 16B-chunk c in 0..3) -> phys byte offset within a
// 64B-row matrix tile. chunk' = c ^ ((row>>1)&3): ldmatrix conflict-free.
__device__ __forceinline__ uint32_t swz(uint32_t row, uint32_t c) {
    return row * 64u + ((c ^ ((row >> 1) & 3u)) << 4);
}

// ---------------- HMMA fp16 GEMM ----------------
// C[M,512] = A[M,K] @ W[512,K]^T, both fp16 (rounding err ~1.4e-4 rms each).
// CTA 128x128, BK=32, 3-stage cp.async, swizzled 64B rows, 2 CTAs/SM.
#define GBM   128
#define GBN   128
#define GBK   32
#define MATB  (128 * 64)             // 8192 per matrix per stage
#define STB   (2 * MATB)             // 16384 per stage (A, W)
#define NSTAGE 3
#define SMEMSZ (NSTAGE * STB)        // 49152 -> 2 CTAs/SM

template <bool RELU, bool BN_EN, bool OUTF32>
__global__ void __launch_bounds__(256, 2)
hmma_gemm_kernel(const __half* __restrict__ A,
                 const __half* __restrict__ Bw,
                 const float* __restrict__ bias,
                 const float* __restrict__ bng, const float* __restrict__ bnb,
                 const float* __restrict__ bnm, const float* __restrict__ bnv,
                 float* __restrict__ Cf, float* __restrict__ Cf2,
                 const float* __restrict__ epsp,
                 __half* __restrict__ Ch,
                 int M, int K) {
    extern __shared__ char smem[];
    const uint32_t sb = cvta_shared(smem);
    const int tid = threadIdx.x, lane = tid & 31, wid = tid >> 5;
    const int wm = wid >> 1, wn = wid & 1;           // 4x2 warp grid
    const int rowBase = blockIdx.y * GBM;
    const int colBase = blockIdx.x * GBN;
    const int NC = K / GBK;

    float acc[2][8][4];
#pragma unroll
    for (int a = 0; a < 2; a++)
#pragma unroll
        for (int b = 0; b < 8; b++)
#pragma unroll
            for (int c = 0; c < 4; c++) acc[a][b][c] = 0.0f;

    auto load_stage = [&](int c) {
        const int st = c % NSTAGE;
        const uint32_t base = sb + st * STB;
        const int kOff = c * GBK;
#pragma unroll
        for (int u = 0; u < 2; u++) {
            int idx = tid + u * 256;
            uint32_t row = (uint32_t)idx >> 2, ch = (uint32_t)idx & 3;
            int gr = rowBase + (int)row;
            if (gr > M - 1) gr = M - 1;              // clamp (finite junk, rows not stored)
            uint32_t so = swz(row, ch);
            CP16(base + so, A + (size_t)gr * K + kOff + ch * 8);
            CP16(base + MATB + so, Bw + (size_t)(colBase + (int)row) * K + kOff + ch * 8);
        }
        CP_COMMIT();
    };

    // ldmatrix per-lane row indices (chunk varies with ks -> swizzled per use)
    const uint32_t mrow = (uint32_t)((lane & 7) + ((lane >> 3) & 1) * 8);
    const uint32_t aChunkBit = (uint32_t)(lane >> 4);          // 0/1
    const uint32_t nrow = (uint32_t)((lane & 7) + ((lane >> 4) << 3));
    const uint32_t bChunkBit = (uint32_t)((lane >> 3) & 1);    // 0/1

    load_stage(0);
    if (NC > 1) load_stage(1); else CP_COMMIT();

    for (int c = 0; c < NC; c++) {
        CP_WAIT1();                           // stage c complete
        __syncthreads();
        if (c + 2 < NC) load_stage(c + 2);
        else            CP_COMMIT();          // keep group count uniform

        const int st = c % NSTAGE;
        const uint32_t aB = sb + st * STB;
        const uint32_t bB = aB + MATB;
#pragma unroll
        for (int ks = 0; ks < 2; ks++) {      // two k16 steps per BK=32
            const uint32_t cA = (uint32_t)ks * 2 + aChunkBit;
            const uint32_t cB = (uint32_t)ks * 2 + bChunkBit;
            uint32_t af[2][4], bf[4][4];
#pragma unroll
            for (int mt = 0; mt < 2; mt++)
                ldm4(af[mt], aB + swz((uint32_t)(wm * 32 + mt * 16) + mrow, cA));
#pragma unroll
            for (int jp = 0; jp < 4; jp++)
                ldm4(bf[jp], bB + swz((uint32_t)(wn * 64 + jp * 16) + nrow, cB));
#pragma unroll
            for (int mt = 0; mt < 2; mt++)
#pragma unroll
                for (int j = 0; j < 8; j++)
                    mma16816(acc[mt][j], af[mt], &bf[j >> 1][(j & 1) * 2]);
        }
        // no trailing sync needed: 3 distinct stage buffers; the next
        // iteration's top sync orders all compute before buffer reuse.
    }

    // ---------------- epilogue (direct from registers) ----------------
    const int g = lane >> 2, t = lane & 3;
    const float es = (OUTF32 && Cf2) ? (1.0f + *epsp) : 0.0f;
#pragma unroll
    for (int mt = 0; mt < 2; mt++) {
        int rbase = rowBase + wm * 32 + mt * 16 + g;
#pragma unroll
        for (int half = 0; half < 2; half++) {
            int r = rbase + half * 8;
            if (r >= M) continue;
#pragma unroll
            for (int j = 0; j < 8; j++) {
                int cidx = colBase + wn * 64 + j * 8 + 2 * t;
                float v0 = acc[mt][j][half * 2 + 0] + bias[cidx];
                float v1 = acc[mt][j][half * 2 + 1] + bias[cidx + 1];
                if (RELU) { v0 = fmaxf(v0, 0.0f); v1 = fmaxf(v1, 0.0f); }
                if (BN_EN) {
                    v0 = (v0 - bnm[cidx]) * rsqrtf(bnv[cidx] + BN_EPS) * bng[cidx] + bnb[cidx];
                    v1 = (v1 - bnm[cidx + 1]) * rsqrtf(bnv[cidx + 1] + BN_EPS) * bng[cidx + 1] + bnb[cidx + 1];
                }
                if (OUTF32) {
                    *(float2*)(Cf + (size_t)r * HIDDEN + cidx) = make_float2(v0, v1);
                    if (Cf2)
                        *(float2*)(Cf2 + (size_t)r * HIDDEN + cidx) =
                            make_float2(v0 * es, v1 * es);
                } else {
                    *(uint32_t*)(Ch + (size_t)r * HIDDEN + cidx) = pack_h2(v0, v1);
                }
            }
        }
    }
}

// ---------------- auxiliary kernels ----------------
__global__ void scale_copy_kernel(const float4* __restrict__ in, float4* __restrict__ out,
                                  const float* __restrict__ eps, int n4) {
    float s = 1.0f + *eps;
    int i = blockIdx.x * blockDim.x + threadIdx.x;
    if (i < n4) {
        float4 v = in[i];
        v.x *= s; v.y *= s; v.z *= s; v.w *= s;
        out[i] = v;
    }
}

// out[dst[e]] += h[src[e]]  -- one warp/edge, float4 loads, v4 vector reductions
__global__ void scatter_add_kernel(const float* __restrict__ h, float* __restrict__ out,
                                   const int* __restrict__ src, const int* __restrict__ dst,
                                   int nEdges, int F) {
    int warp = (blockIdx.x * blockDim.x + threadIdx.x) >> 5;
    int lane = threadIdx.x & 31;
    if (warp >= nEdges) return;
    int s = src[warp], d = dst[warp];
    const float4* hs = (const float4*)(h + (size_t)s * F);
    float* od = out + (size_t)d * F;
    int f4 = F >> 2;
    for (int i = lane; i < f4; i += 32) {
        float4 v = hs[i];
        red_add_v4(od + 4 * i, v);
    }
}

// fp32 -> fp16 cast (streaming)
__global__ void quant_kernel(const float4* __restrict__ in, uint32_t* __restrict__ q, int n4) {
    int i = blockIdx.x * blockDim.x + threadIdx.x;
    if (i >= n4) return;
    float4 v = in[i];
    q[2 * i]     = pack_h2(v.x, v.y);
    q[2 * i + 1] = pack_h2(v.z, v.w);
}

// W[K,N] f32 -> Wt[N,K] fp16 (transpose + cast)
__global__ void wsplit_kernel(const float* __restrict__ W, __half* __restrict__ Wh,
                              int K, int N) {
    __shared__ float t[32][33];
    int n0 = blockIdx.x * 32, k0 = blockIdx.y * 32;
    int tx = threadIdx.x, ty = threadIdx.y;
#pragma unroll
    for (int i = 0; i < 4; i++)
        t[ty + i * 8][tx] = W[(size_t)(k0 + ty + i * 8) * N + n0 + tx];
    __syncthreads();
#pragma unroll
    for (int i = 0; i < 4; i++) {
        float v = t[tx][ty + i * 8];
        Wh[(size_t)(n0 + ty + i * 8) * K + k0 + tx] = __float2half_rn(v);
    }
}

__global__ void __launch_bounds__(256)
edge_pred_kernel(const float* __restrict__ h, const int* __restrict__ ei,
                 const int* __restrict__ train_id, const float* __restrict__ W,
                 const float* __restrict__ b, float* __restrict__ out) {
    __shared__ float sW[HIDDEN * N_CLASS];
    __shared__ float sb[N_CLASS];
    for (int i = threadIdx.x; i < HIDDEN * N_CLASS; i += blockDim.x) sW[i] = W[i];
    if (threadIdx.x < N_CLASS) sb[threadIdx.x] = b[threadIdx.x];
    __syncthreads();
    int warp = (blockIdx.x * blockDim.x + threadIdx.x) >> 5;
    int lane = threadIdx.x & 31;
    if (warp >= N_TRAIN) return;
    int te = train_id[warp];
    int n0 = ei[te], n1 = ei[N_EDGES + te];
    const float4* h0 = (const float4*)(h + (size_t)n0 * HIDDEN);
    const float4* h1 = (const float4*)(h + (size_t)n1 * HIDDEN);
    float acc[N_CLASS];
#pragma unroll
    for (int j = 0; j < N_CLASS; j++) acc[j] = 0.0f;
    for (int k4 = lane; k4 < HIDDEN / 4; k4 += 32) {
        float4 a = h0[k4], c = h1[k4];
        float p0 = a.x * c.x, p1 = a.y * c.y, p2 = a.z * c.z, p3 = a.w * c.w;
        int k = k4 * 4;
#pragma unroll
        for (int j = 0; j < N_CLASS; j++)
            acc[j] += p0 * sW[(k + 0) * N_CLASS + j] + p1 * sW[(k + 1) * N_CLASS + j] +
                      p2 * sW[(k + 2) * N_CLASS + j] + p3 * sW[(k + 3) * N_CLASS + j];
    }
#pragma unroll
    for (int j = 0; j < N_CLASS; j++)
#pragma unroll
        for (int off = 16; off > 0; off >>= 1)
            acc[j] += __shfl_xor_sync(0xffffffffu, acc[j], off);
    if (lane == 0) {
#pragma unroll
        for (int j = 0; j < N_CLASS; j++)
            out[(size_t)warp * N_CLASS + j] = acc[j] + sb[j];
    }
}

// ---------------- launcher ----------------
extern "C" void kernel_launch(void* const* d_in, const int* in_sizes, int n_in,
                              void* d_out, int out_size) {
    const float* x     = (const float*)d_in[0];
    const int*   ei    = (const int*)d_in[1];
    const int*   trid  = (const int*)d_in[2];
    const float* W1    = (const float*)d_in[3];
    const float* b1    = (const float*)d_in[4];
    const float* W2    = (const float*)d_in[5];
    const float* b2    = (const float*)d_in[6];
    const float* W3    = (const float*)d_in[7];
    const float* b3    = (const float*)d_in[8];
    const float* bn1g  = (const float*)d_in[9];
    const float* bn1b  = (const float*)d_in[10];
    const float* bn1m  = (const float*)d_in[11];
    const float* bn1v  = (const float*)d_in[12];
    const float* eps1  = (const float*)d_in[13];
    const float* W4    = (const float*)d_in[14];
    const float* b4    = (const float*)d_in[15];
    const float* bn2g  = (const float*)d_in[16];
    const float* bn2b  = (const float*)d_in[17];
    const float* bn2m  = (const float*)d_in[18];
    const float* bn2v  = (const float*)d_in[19];
    const float* eps2  = (const float*)d_in[20];
    const float* lin1W = (const float*)d_in[21];
    const float* lin1b = (const float*)d_in[22];
    const float* lin2W = (const float*)d_in[23];
    const float* lin2b = (const float*)d_in[24];
    const float* fc2W  = (const float*)d_in[25];
    const float* fc2b  = (const float*)d_in[26];
    float* out = (float*)d_out;

    float *bufA, *bufB, *agg0;
    __half *hA, *hB, *wh;
    cudaGetSymbolAddress((void**)&bufA, g_bufA);
    cudaGetSymbolAddress((void**)&bufB, g_bufB);
    cudaGetSymbolAddress((void**)&agg0, g_agg0);
    cudaGetSymbolAddress((void**)&hA, g_hA);
    cudaGetSymbolAddress((void**)&hB, g_hB);
    cudaGetSymbolAddress((void**)&wh, g_wh);

    cudaFuncSetAttribute(hmma_gemm_kernel<true, false, false>,
                         cudaFuncAttributeMaxDynamicSharedMemorySize, SMEMSZ);
    cudaFuncSetAttribute(hmma_gemm_kernel<true, true, true>,
                         cudaFuncAttributeMaxDynamicSharedMemorySize, SMEMSZ);
    cudaFuncSetAttribute(hmma_gemm_kernel<true, true, false>,
                         cudaFuncAttributeMaxDynamicSharedMemorySize, SMEMSZ);
    cudaFuncSetAttribute(hmma_gemm_kernel<false, false, true>,
                         cudaFuncAttributeMaxDynamicSharedMemorySize, SMEMSZ);

    const int* src = ei;
    const int* dst = ei + N_EDGES;

    // weight transpose + fp16 cast
    dim3 wb(32, 8);
    wsplit_kernel<<<dim3(16, 2), wb>>>(W1, wh + 0 * WSLOT, IN_F, HIDDEN);
    wsplit_kernel<<<dim3(16, 16), wb>>>(W2, wh + 1 * WSLOT, HIDDEN, HIDDEN);
    wsplit_kernel<<<dim3(16, 16), wb>>>(W3, wh + 2 * WSLOT, HIDDEN, HIDDEN);
    wsplit_kernel<<<dim3(16, 16), wb>>>(W4, wh + 3 * WSLOT, HIDDEN, HIDDEN);
    wsplit_kernel<<<dim3(16, 16), wb>>>(lin1W, wh + 4 * WSLOT, HIDDEN, HIDDEN);
    wsplit_kernel<<<dim3(16, 16), wb>>>(lin2W, wh + 5 * WSLOT, HIDDEN, HIDDEN);

    // agg1 on x (fp32) then quantize to fp16
    {
        int n4 = N_NODES * IN_F / 4;
        scale_copy_kernel<<<(n4 + 255) / 256, 256>>>((const float4*)x, (float4*)agg0, eps1, n4);
        scatter_add_kernel<<<(N_EDGES * 32 + 255) / 256, 256>>>(x, agg0, src, dst, N_EDGES, IN_F);
        quant_kernel<<<(n4 + 255) / 256, 256>>>((const float4*)agg0, (uint32_t*)hA, n4);
    }

    dim3 gg(HIDDEN / GBN, (N_NODES + GBM - 1) / GBM);  // (4, 391)

    // L1: relu(agg @ W1 + b1) -> fp16
    hmma_gemm_kernel<true, false, false><<<gg, 256, SMEMSZ>>>(
        hA, wh + 0 * WSLOT, b1, nullptr, nullptr, nullptr, nullptr,
        nullptr, nullptr, nullptr, hB, N_NODES, IN_F);
    // L2: relu(h @ W2 + b2) -> fp16
    hmma_gemm_kernel<true, false, false><<<gg, 256, SMEMSZ>>>(
        hB, wh + 1 * WSLOT, b2, nullptr, nullptr, nullptr, nullptr,
        nullptr, nullptr, nullptr, hA, N_NODES, HIDDEN);
    // L3: bn1(relu(h @ W3 + b3)) -> fp32 bufA + (1+eps2)-scaled bufB (fused)
    hmma_gemm_kernel<true, true, true><<<gg, 256, SMEMSZ>>>(
        hA, wh + 2 * WSLOT, b3, bn1g, bn1b, bn1m, bn1v,
        bufA, bufB, eps2, nullptr, N_NODES, HIDDEN);
    // agg2: bufB += bufA[src] scattered, then quantize
    {
        int n4 = N_NODES * HIDDEN / 4;
        scatter_add_kernel<<<(N_EDGES * 32 + 255) / 256, 256>>>(bufA, bufB, src, dst, N_EDGES, HIDDEN);
        quant_kernel<<<(n4 + 255) / 256, 256>>>((const float4*)bufB, (uint32_t*)hA, n4);
    }
    // L4: bn2(relu(h @ W4 + b4)) -> fp16
    hmma_gemm_kernel<true, true, false><<<gg, 256, SMEMSZ>>>(
        hA, wh + 3 * WSLOT, b4, bn2g, bn2b, bn2m, bn2v,
        nullptr, nullptr, nullptr, hB, N_NODES, HIDDEN);
    // L5: relu(h @ lin1W + lin1b) -> fp16
    hmma_gemm_kernel<true, false, false><<<gg, 256, SMEMSZ>>>(
        hB, wh + 4 * WSLOT, lin1b, nullptr, nullptr, nullptr, nullptr,
        nullptr, nullptr, nullptr, hA, N_NODES, HIDDEN);
    // L6: h @ lin2W + lin2b -> fp32
    hmma_gemm_kernel<false, false, true><<<gg, 256, SMEMSZ>>>(
        hA, wh + 5 * WSLOT, lin2b, nullptr, nullptr, nullptr, nullptr,
        bufA, nullptr, nullptr, nullptr, N_NODES, HIDDEN);
    // edge classifier
    edge_pred_kernel<<<(N_TRAIN * 32 + 255) / 256, 256>>>(bufA, ei, trid, fc2W, fc2b, out);
}

// round 12
// speedup vs baseline: 3.8892x; 1.0284x over previous
#include <cuda_runtime.h>
#include <cuda_fp16.h>
#include <cstdint>

#define N_NODES 50000
#define IN_F    64
#define HIDDEN  512
#define N_EDGES 160000
#define N_TRAIN 80000
#define N_CLASS 7
#define BN_EPS  1e-5f

// ---------------- static device scratch (no allocation) ----------------
__device__ __align__(16) float g_bufA[(size_t)N_NODES * HIDDEN];
__device__ __align__(16) float g_bufB[(size_t)N_NODES * HIDDEN];
__device__ __align__(16) float g_agg0[(size_t)N_NODES * IN_F];
__device__ __align__(16) __half g_hA[(size_t)N_NODES * HIDDEN];
__device__ __align__(16) __half g_hB[(size_t)N_NODES * HIDDEN];
#define WSLOT (HIDDEN * HIDDEN)
__device__ __align__(16) __half g_wh[6 * WSLOT];

// ---------------- PTX helpers (base-target only: sm_80/90-class) ----------------
__device__ __forceinline__ uint32_t cvta_shared(const void* p) {
    uint32_t a;
    asm("{ .reg .u64 t; cvta.to.shared.u64 t, %1; cvt.u32.u64 %0, t; }" : "=r"(a) : "l"(p));
    return a;
}
#define CP16(dst, src) \
    asm volatile("cp.async.cg.shared.global [%0], [%1], 16;" :: "r"(dst), "l"(src))
#define CP_COMMIT() asm volatile("cp.async.commit_group;" ::: "memory")
#define CP_WAIT1()  asm volatile("cp.async.wait_group 1;" ::: "memory")

__device__ __forceinline__ void ldm4(uint32_t* r, uint32_t addr) {
    asm volatile("ldmatrix.sync.aligned.m8n8.x4.shared.b16 {%0,%1,%2,%3}, [%4];"
        : "=r"(r[0]), "=r"(r[1]), "=r"(r[2]), "=r"(r[3]) : "r"(addr));
}
__device__ __forceinline__ void mma16816(float* d, const uint32_t* a, const uint32_t* b) {
    asm volatile(
        "mma.sync.aligned.m16n8k16.row.col.f32.f16.f16.f32 "
        "{%0,%1,%2,%3},{%4,%5,%6,%7},{%8,%9},{%0,%1,%2,%3};"
        : "+f"(d[0]), "+f"(d[1]), "+f"(d[2]), "+f"(d[3])
        : "r"(a[0]), "r"(a[1]), "r"(a[2]), "r"(a[3]), "r"(b[0]), "r"(b[1]));
}
// vectorized global reduction (PTX ISA 8.1, sm_90 base target)
__device__ __forceinline__ void red_add_v4(float* addr, float4 v) {
    asm volatile("red.global.add.v4.f32 [%0], {%1, %2, %3, %4};"
        :: "l"(addr), "f"(v.x), "f"(v.y), "f"(v.z), "f"(v.w) : "memory");
}
__device__ __forceinline__ uint32_t pack_h2(float a, float b) {
    __half2 h = __floats2half2_rn(a, b);
    return *(uint32_t*)&h;
}

// swizzle for 128B rows: logical (row, 16B-chunk c in 0..7) -> phys byte off.
// chunk' = c ^ (row & 7): 8 consecutive rows at fixed c hit 8 distinct
// 16B bank groups -> ldmatrix conflict-free.
__device__ __forceinline__ uint32_t swz(uint32_t row, uint32_t c) {
    return row * 128u + ((c ^ (row & 7u)) << 4);
}

// ---------------- HMMA fp16 GEMM ----------------
// C[M,512] = A[M,K] @ W[512,K]^T, both fp16.
// CTA 128x128, BK=64 (4x k16 per stage), 3-stage cp.async, 2 CTAs/SM.
#define GBM   128
#define GBN   128
#define GBK   64
#define MATB  (128 * 128)            // 16384 per matrix per stage
#define STB   (2 * MATB)             // 32768 per stage (A, W)
#define NSTAGE 3
#define SMEMSZ (NSTAGE * STB)        // 98304 -> 2 CTAs/SM

template <bool RELU, bool BN_EN, bool OUTF32>
__global__ void __launch_bounds__(256, 2)
hmma_gemm_kernel(const __half* __restrict__ A,
                 const __half* __restrict__ Bw,
                 const float* __restrict__ bias,
                 const float* __restrict__ bng, const float* __restrict__ bnb,
                 const float* __restrict__ bnm, const float* __restrict__ bnv,
                 float* __restrict__ Cf, float* __restrict__ Cf2,
                 const float* __restrict__ epsp,
                 __half* __restrict__ Ch,
                 int M, int K) {
    extern __shared__ char smem[];
    const uint32_t sb = cvta_shared(smem);
    const int tid = threadIdx.x, lane = tid & 31, wid = tid >> 5;
    const int wm = wid >> 1, wn = wid & 1;           // 4x2 warp grid
    const int rowBase = blockIdx.y * GBM;
    const int colBase = blockIdx.x * GBN;
    const int NC = K / GBK;

    float acc[2][8][4];
#pragma unroll
    for (int a = 0; a < 2; a++)
#pragma unroll
        for (int b = 0; b < 8; b++)
#pragma unroll
            for (int c = 0; c < 4; c++) acc[a][b][c] = 0.0f;

    auto load_stage = [&](int c) {
        const int st = c % NSTAGE;
        const uint32_t base = sb + st * STB;
        const int kOff = c * GBK;
#pragma unroll
        for (int u = 0; u < 4; u++) {         // 1024 chunks per matrix
            int idx = tid + u * 256;
            uint32_t row = (uint32_t)idx >> 3, ch = (uint32_t)idx & 7;
            int gr = rowBase + (int)row;
            if (gr > M - 1) gr = M - 1;       // clamp (finite junk, rows not stored)
            uint32_t so = swz(row, ch);
            CP16(base + so, A + (size_t)gr * K + kOff + ch * 8);
            CP16(base + MATB + so, Bw + (size_t)(colBase + (int)row) * K + kOff + ch * 8);
        }
        CP_COMMIT();
    };

    // ldmatrix per-lane row indices (chunk varies with ks -> swizzled per use)
    const uint32_t mrow = (uint32_t)((lane & 7) + ((lane >> 3) & 1) * 8);
    const uint32_t aChunkBit = (uint32_t)(lane >> 4);          // 0/1
    const uint32_t nrow = (uint32_t)((lane & 7) + ((lane >> 4) << 3));
    const uint32_t bChunkBit = (uint32_t)((lane >> 3) & 1);    // 0/1

    load_stage(0);
    if (NC > 1) load_stage(1); else CP_COMMIT();

    for (int c = 0; c < NC; c++) {
        CP_WAIT1();                           // stage c complete
        __syncthreads();
        if (c + 2 < NC) load_stage(c + 2);
        else            CP_COMMIT();          // keep group count uniform

        const int st = c % NSTAGE;
        const uint32_t aB = sb + st * STB;
        const uint32_t bB = aB + MATB;
#pragma unroll
        for (int ks = 0; ks < 4; ks++) {      // four k16 steps per BK=64
            const uint32_t cA = (uint32_t)ks * 2 + aChunkBit;
            const uint32_t cB = (uint32_t)ks * 2 + bChunkBit;
            uint32_t af[2][4], bf[4][4];
#pragma unroll
            for (int mt = 0; mt < 2; mt++)
                ldm4(af[mt], aB + swz((uint32_t)(wm * 32 + mt * 16) + mrow, cA));
#pragma unroll
            for (int jp = 0; jp < 4; jp++)
                ldm4(bf[jp], bB + swz((uint32_t)(wn * 64 + jp * 16) + nrow, cB));
#pragma unroll
            for (int mt = 0; mt < 2; mt++)
#pragma unroll
                for (int j = 0; j < 8; j++)
                    mma16816(acc[mt][j], af[mt], &bf[j >> 1][(j & 1) * 2]);
        }
        // no trailing sync: 3 distinct stage buffers; next iteration's top
        // sync orders all compute before buffer reuse.
    }

    // ---------------- epilogue (direct from registers) ----------------
    const int g = lane >> 2, t = lane & 3;
    const float es = (OUTF32 && Cf2) ? (1.0f + *epsp) : 0.0f;
#pragma unroll
    for (int mt = 0; mt < 2; mt++) {
        int rbase = rowBase + wm * 32 + mt * 16 + g;
#pragma unroll
        for (int half = 0; half < 2; half++) {
            int r = rbase + half * 8;
            if (r >= M) continue;
#pragma unroll
            for (int j = 0; j < 8; j++) {
                int cidx = colBase + wn * 64 + j * 8 + 2 * t;
                float v0 = acc[mt][j][half * 2 + 0] + bias[cidx];
                float v1 = acc[mt][j][half * 2 + 1] + bias[cidx + 1];
                if (RELU) { v0 = fmaxf(v0, 0.0f); v1 = fmaxf(v1, 0.0f); }
                if (BN_EN) {
                    v0 = (v0 - bnm[cidx]) * rsqrtf(bnv[cidx] + BN_EPS) * bng[cidx] + bnb[cidx];
                    v1 = (v1 - bnm[cidx + 1]) * rsqrtf(bnv[cidx + 1] + BN_EPS) * bng[cidx + 1] + bnb[cidx + 1];
                }
                if (OUTF32) {
                    *(float2*)(Cf + (size_t)r * HIDDEN + cidx) = make_float2(v0, v1);
                    if (Cf2)
                        *(float2*)(Cf2 + (size_t)r * HIDDEN + cidx) =
                            make_float2(v0 * es, v1 * es);
                } else {
                    *(uint32_t*)(Ch + (size_t)r * HIDDEN + cidx) = pack_h2(v0, v1);
                }
            }
        }
    }
}

// ---------------- auxiliary kernels ----------------
__global__ void scale_copy_kernel(const float4* __restrict__ in, float4* __restrict__ out,
                                  const float* __restrict__ eps, int n4) {
    float s = 1.0f + *eps;
    int i = blockIdx.x * blockDim.x + threadIdx.x;
    if (i < n4) {
        float4 v = in[i];
        v.x *= s; v.y *= s; v.z *= s; v.w *= s;
        out[i] = v;
    }
}

// out[dst[e]] += h[src[e]]  -- one warp/edge, float4 loads, v4 vector reductions
__global__ void scatter_add_kernel(const float* __restrict__ h, float* __restrict__ out,
                                   const int* __restrict__ src, const int* __restrict__ dst,
                                   int nEdges, int F) {
    int warp = (blockIdx.x * blockDim.x + threadIdx.x) >> 5;
    int lane = threadIdx.x & 31;
    if (warp >= nEdges) return;
    int s = src[warp], d = dst[warp];
    const float4* hs = (const float4*)(h + (size_t)s * F);
    float* od = out + (size_t)d * F;
    int f4 = F >> 2;
    for (int i = lane; i < f4; i += 32) {
        float4 v = hs[i];
        red_add_v4(od + 4 * i, v);
    }
}

// fp32 -> fp16 cast (streaming)
__global__ void quant_kernel(const float4* __restrict__ in, uint32_t* __restrict__ q, int n4) {
    int i = blockIdx.x * blockDim.x + threadIdx.x;
    if (i >= n4) return;
    float4 v = in[i];
    q[2 * i]     = pack_h2(v.x, v.y);
    q[2 * i + 1] = pack_h2(v.z, v.w);
}

// W[K,N] f32 -> Wt[N,K] fp16 (transpose + cast)
__global__ void wsplit_kernel(const float* __restrict__ W, __half* __restrict__ Wh,
                              int K, int N) {
    __shared__ float t[32][33];
    int n0 = blockIdx.x * 32, k0 = blockIdx.y * 32;
    int tx = threadIdx.x, ty = threadIdx.y;
#pragma unroll
    for (int i = 0; i < 4; i++)
        t[ty + i * 8][tx] = W[(size_t)(k0 + ty + i * 8) * N + n0 + tx];
    __syncthreads();
#pragma unroll
    for (int i = 0; i < 4; i++) {
        float v = t[tx][ty + i * 8];
        Wh[(size_t)(n0 + ty + i * 8) * K + k0 + tx] = __float2half_rn(v);
    }
}

// edge classifier reading fp16 h: out[t,:] = (h[n0]*h[n1]) @ fc2_W + fc2_b
__global__ void __launch_bounds__(256)
edge_pred_kernel(const __half* __restrict__ h, const int* __restrict__ ei,
                 const int* __restrict__ train_id, const float* __restrict__ W,
                 const float* __restrict__ b, float* __restrict__ out) {
    __shared__ float sW[HIDDEN * N_CLASS];
    __shared__ float sb[N_CLASS];
    for (int i = threadIdx.x; i < HIDDEN * N_CLASS; i += blockDim.x) sW[i] = W[i];
    if (threadIdx.x < N_CLASS) sb[threadIdx.x] = b[threadIdx.x];
    __syncthreads();
    int warp = (blockIdx.x * blockDim.x + threadIdx.x) >> 5;
    int lane = threadIdx.x & 31;
    if (warp >= N_TRAIN) return;
    int te = train_id[warp];
    int n0 = ei[te], n1 = ei[N_EDGES + te];
    const uint4* h0 = (const uint4*)(h + (size_t)n0 * HIDDEN);
    const uint4* h1 = (const uint4*)(h + (size_t)n1 * HIDDEN);
    float acc[N_CLASS];
#pragma unroll
    for (int j = 0; j < N_CLASS; j++) acc[j] = 0.0f;
    for (int i = lane; i < HIDDEN / 8; i += 32) {   // 8 halves per uint4
        uint4 a4 = h0[i], c4 = h1[i];
        const __half2* ah = (const __half2*)&a4;
        const __half2* ch = (const __half2*)&c4;
        int k = i * 8;
#pragma unroll
        for (int q = 0; q < 4; q++) {
            float2 af = __half22float2(ah[q]);
            float2 cf = __half22float2(ch[q]);
            float p0 = af.x * cf.x, p1 = af.y * cf.y;
            int kk = k + 2 * q;
#pragma unroll
            for (int j = 0; j < N_CLASS; j++)
                acc[j] += p0 * sW[kk * N_CLASS + j] + p1 * sW[(kk + 1) * N_CLASS + j];
        }
    }
#pragma unroll
    for (int j = 0; j < N_CLASS; j++)
#pragma unroll
        for (int off = 16; off > 0; off >>= 1)
            acc[j] += __shfl_xor_sync(0xffffffffu, acc[j], off);
    if (lane == 0) {
#pragma unroll
        for (int j = 0; j < N_CLASS; j++)
            out[(size_t)warp * N_CLASS + j] = acc[j] + sb[j];
    }
}

// ---------------- launcher ----------------
extern "C" void kernel_launch(void* const* d_in, const int* in_sizes, int n_in,
                              void* d_out, int out_size) {
    const float* x     = (const float*)d_in[0];
    const int*   ei    = (const int*)d_in[1];
    const int*   trid  = (const int*)d_in[2];
    const float* W1    = (const float*)d_in[3];
    const float* b1    = (const float*)d_in[4];
    const float* W2    = (const float*)d_in[5];
    const float* b2    = (const float*)d_in[6];
    const float* W3    = (const float*)d_in[7];
    const float* b3    = (const float*)d_in[8];
    const float* bn1g  = (const float*)d_in[9];
    const float* bn1b  = (const float*)d_in[10];
    const float* bn1m  = (const float*)d_in[11];
    const float* bn1v  = (const float*)d_in[12];
    const float* eps1  = (const float*)d_in[13];
    const float* W4    = (const float*)d_in[14];
    const float* b4    = (const float*)d_in[15];
    const float* bn2g  = (const float*)d_in[16];
    const float* bn2b  = (const float*)d_in[17];
    const float* bn2m  = (const float*)d_in[18];
    const float* bn2v  = (const float*)d_in[19];
    const float* eps2  = (const float*)d_in[20];
    const float* lin1W = (const float*)d_in[21];
    const float* lin1b = (const float*)d_in[22];
    const float* lin2W = (const float*)d_in[23];
    const float* lin2b = (const float*)d_in[24];
    const float* fc2W  = (const float*)d_in[25];
    const float* fc2b  = (const float*)d_in[26];
    float* out = (float*)d_out;

    float *bufA, *bufB, *agg0;
    __half *hA, *hB, *wh;
    cudaGetSymbolAddress((void**)&bufA, g_bufA);
    cudaGetSymbolAddress((void**)&bufB, g_bufB);
    cudaGetSymbolAddress((void**)&agg0, g_agg0);
    cudaGetSymbolAddress((void**)&hA, g_hA);
    cudaGetSymbolAddress((void**)&hB, g_hB);
    cudaGetSymbolAddress((void**)&wh, g_wh);

    cudaFuncSetAttribute(hmma_gemm_kernel<true, false, false>,
                         cudaFuncAttributeMaxDynamicSharedMemorySize, SMEMSZ);
    cudaFuncSetAttribute(hmma_gemm_kernel<true, true, true>,
                         cudaFuncAttributeMaxDynamicSharedMemorySize, SMEMSZ);
    cudaFuncSetAttribute(hmma_gemm_kernel<true, true, false>,
                         cudaFuncAttributeMaxDynamicSharedMemorySize, SMEMSZ);
    cudaFuncSetAttribute(hmma_gemm_kernel<false, false, false>,
                         cudaFuncAttributeMaxDynamicSharedMemorySize, SMEMSZ);

    const int* src = ei;
    const int* dst = ei + N_EDGES;

    // weight transpose + fp16 cast
    dim3 wb(32, 8);
    wsplit_kernel<<<dim3(16, 2), wb>>>(W1, wh + 0 * WSLOT, IN_F, HIDDEN);
    wsplit_kernel<<<dim3(16, 16), wb>>>(W2, wh + 1 * WSLOT, HIDDEN, HIDDEN);
    wsplit_kernel<<<dim3(16, 16), wb>>>(W3, wh + 2 * WSLOT, HIDDEN, HIDDEN);
    wsplit_kernel<<<dim3(16, 16), wb>>>(W4, wh + 3 * WSLOT, HIDDEN, HIDDEN);
    wsplit_kernel<<<dim3(16, 16), wb>>>(lin1W, wh + 4 * WSLOT, HIDDEN, HIDDEN);
    wsplit_kernel<<<dim3(16, 16), wb>>>(lin2W, wh + 5 * WSLOT, HIDDEN, HIDDEN);

    // agg1 on x (fp32) then quantize to fp16
    {
        int n4 = N_NODES * IN_F / 4;
        scale_copy_kernel<<<(n4 + 255) / 256, 256>>>((const float4*)x, (float4*)agg0, eps1, n4);
        scatter_add_kernel<<<(N_EDGES * 32 + 255) / 256, 256>>>(x, agg0, src, dst, N_EDGES, IN_F);
        quant_kernel<<<(n4 + 255) / 256, 256>>>((const float4*)agg0, (uint32_t*)hA, n4);
    }

    dim3 gg(HIDDEN / GBN, (N_NODES + GBM - 1) / GBM);  // (4, 391)

    // L1: relu(agg @ W1 + b1) -> fp16
    hmma_gemm_kernel<true, false, false><<<gg, 256, SMEMSZ>>>(
        hA, wh + 0 * WSLOT, b1, nullptr, nullptr, nullptr, nullptr,
        nullptr, nullptr, nullptr, hB, N_NODES, IN_F);
    // L2: relu(h @ W2 + b2) -> fp16
    hmma_gemm_kernel<true, false, false><<<gg, 256, SMEMSZ>>>(
        hB, wh + 1 * WSLOT, b2, nullptr, nullptr, nullptr, nullptr,
        nullptr, nullptr, nullptr, hA, N_NODES, HIDDEN);
    // L3: bn1(relu(h @ W3 + b3)) -> fp32 bufA + (1+eps2)-scaled bufB (fused)
    hmma_gemm_kernel<true, true, true><<<gg, 256, SMEMSZ>>>(
        hA, wh + 2 * WSLOT, b3, bn1g, bn1b, bn1m, bn1v,
        bufA, bufB, eps2, nullptr, N_NODES, HIDDEN);
    // agg2: bufB += bufA[src] scattered, then quantize
    {
        int n4 = N_NODES * HIDDEN / 4;
        scatter_add_kernel<<<(N_EDGES * 32 + 255) / 256, 256>>>(bufA, bufB, src, dst, N_EDGES, HIDDEN);
        quant_kernel<<<(n4 + 255) / 256, 256>>>((const float4*)bufB, (uint32_t*)hA, n4);
    }
    // L4: bn2(relu(h @ W4 + b4)) -> fp16
    hmma_gemm_kernel<true, true, false><<<gg, 256, SMEMSZ>>>(
        hA, wh + 3 * WSLOT, b4, bn2g, bn2b, bn2m, bn2v,
        nullptr, nullptr, nullptr, hB, N_NODES, HIDDEN);
    // L5: relu(h @ lin1W + lin1b) -> fp16
    hmma_gemm_kernel<true, false, false><<<gg, 256, SMEMSZ>>>(
        hB, wh + 4 * WSLOT, lin1b, nullptr, nullptr, nullptr, nullptr,
        nullptr, nullptr, nullptr, hA, N_NODES, HIDDEN);
    // L6: h @ lin2W + lin2b -> fp16 (consumed only by edge classifier)
    hmma_gemm_kernel<false, false, false><<<gg, 256, SMEMSZ>>>(
        hA, wh + 5 * WSLOT, lin2b, nullptr, nullptr, nullptr, nullptr,
        nullptr, nullptr, nullptr, hB, N_NODES, HIDDEN);
    // edge classifier (fp16 h)
    edge_pred_kernel<<<(N_TRAIN * 32 + 255) / 256, 256>>>(hB, ei, trid, fc2W, fc2b, out);
}

// round 14
// speedup vs baseline: 3.9887x; 1.0256x over previous
#include <cuda_runtime.h>
#include <cuda_fp16.h>
#include <cstdint>

#define N_NODES 50000
#define IN_F    64
#define HIDDEN  512
#define N_EDGES 160000
#define N_TRAIN 80000
#define N_CLASS 7
#define BN_EPS  1e-5f

// ---------------- static device scratch (no allocation) ----------------
__device__ __align__(16) float g_bufA[(size_t)N_NODES * HIDDEN];
__device__ __align__(16) float g_bufB[(size_t)N_NODES * HIDDEN];
__device__ __align__(16) float g_agg0[(size_t)N_NODES * IN_F];
__device__ __align__(16) __half g_hA[(size_t)N_NODES * HIDDEN];
__device__ __align__(16) __half g_hB[(size_t)N_NODES * HIDDEN];
#define WSLOT (HIDDEN * HIDDEN)
__device__ __align__(16) __half g_wh[6 * WSLOT];

// ---------------- PTX helpers (base-target only: sm_80/90-class) ----------------
__device__ __forceinline__ uint32_t cvta_shared(const void* p) {
    uint32_t a;
    asm("{ .reg .u64 t; cvta.to.shared.u64 t, %1; cvt.u32.u64 %0, t; }" : "=r"(a) : "l"(p));
    return a;
}
#define CP16(dst, src) \
    asm volatile("cp.async.cg.shared.global [%0], [%1], 16;" :: "r"(dst), "l"(src))
#define CP_COMMIT() asm volatile("cp.async.commit_group;" ::: "memory")
#define CP_WAIT1()  asm volatile("cp.async.wait_group 1;" ::: "memory")

__device__ __forceinline__ void ldm4(uint32_t* r, uint32_t addr) {
    asm volatile("ldmatrix.sync.aligned.m8n8.x4.shared.b16 {%0,%1,%2,%3}, [%4];"
        : "=r"(r[0]), "=r"(r[1]), "=r"(r[2]), "=r"(r[3]) : "r"(addr));
}
__device__ __forceinline__ void mma16816(float* d, const uint32_t* a, const uint32_t* b) {
    asm volatile(
        "mma.sync.aligned.m16n8k16.row.col.f32.f16.f16.f32 "
        "{%0,%1,%2,%3},{%4,%5,%6,%7},{%8,%9},{%0,%1,%2,%3};"
        : "+f"(d[0]), "+f"(d[1]), "+f"(d[2]), "+f"(d[3])
        : "r"(a[0]), "r"(a[1]), "r"(a[2]), "r"(a[3]), "r"(b[0]), "r"(b[1]));
}
// vectorized global reduction (PTX ISA 8.1, sm_90 base target)
__device__ __forceinline__ void red_add_v4(float* addr, float4 v) {
    asm volatile("red.global.add.v4.f32 [%0], {%1, %2, %3, %4};"
        :: "l"(addr), "f"(v.x), "f"(v.y), "f"(v.z), "f"(v.w) : "memory");
}
__device__ __forceinline__ uint32_t pack_h2(float a, float b) {
    __half2 h = __floats2half2_rn(a, b);
    return *(uint32_t*)&h;
}

// swizzle for 128B rows: logical (row, 16B-chunk c in 0..7) -> phys byte off.
// chunk' = c ^ (row & 7): 8 consecutive rows at fixed c hit 8 distinct
// 16B bank groups -> ldmatrix conflict-free.
__device__ __forceinline__ uint32_t swz(uint32_t row, uint32_t c) {
    return row * 128u + ((c ^ (row & 7u)) << 4);
}

// ---------------- HMMA fp16 GEMM ----------------
// C[M,512] = A[M,K] @ W[512,K]^T, both fp16.
// CTA 128x128, BK=64 (4x k16 per stage), 3-stage cp.async, 2 CTAs/SM.
#define GBM   128
#define GBN   128
#define GBK   64
#define MATB  (128 * 128)            // 16384 per matrix per stage
#define STB   (2 * MATB)             // 32768 per stage (A, W)
#define NSTAGE 3
#define SMEMSZ (NSTAGE * STB)        // 98304 -> 2 CTAs/SM

template <bool RELU, bool BN_EN, bool OUTF32>
__global__ void __launch_bounds__(256, 2)
hmma_gemm_kernel(const __half* __restrict__ A,
                 const __half* __restrict__ Bw,
                 const float* __restrict__ bias,
                 const float* __restrict__ bng, const float* __restrict__ bnb,
                 const float* __restrict__ bnm, const float* __restrict__ bnv,
                 float* __restrict__ Cf, float* __restrict__ Cf2,
                 const float* __restrict__ epsp,
                 __half* __restrict__ Ch,
                 int M, int K) {
    extern __shared__ char smem[];
    const uint32_t sb = cvta_shared(smem);
    const int tid = threadIdx.x, lane = tid & 31, wid = tid >> 5;
    const int wm = wid >> 1, wn = wid & 1;           // 4x2 warp grid
    const int rowBase = blockIdx.y * GBM;
    const int colBase = blockIdx.x * GBN;
    const int NC = K / GBK;

    float acc[2][8][4];
#pragma unroll
    for (int a = 0; a < 2; a++)
#pragma unroll
        for (int b = 0; b < 8; b++)
#pragma unroll
            for (int c = 0; c < 4; c++) acc[a][b][c] = 0.0f;

    auto load_stage = [&](int c) {
        const int st = c % NSTAGE;
        const uint32_t base = sb + st * STB;
        const int kOff = c * GBK;
#pragma unroll
        for (int u = 0; u < 4; u++) {         // 1024 chunks per matrix
            int idx = tid + u * 256;
            uint32_t row = (uint32_t)idx >> 3, ch = (uint32_t)idx & 7;
            int gr = rowBase + (int)row;
            if (gr > M - 1) gr = M - 1;       // clamp (finite junk, rows not stored)
            uint32_t so = swz(row, ch);
            CP16(base + so, A + (size_t)gr * K + kOff + ch * 8);
            CP16(base + MATB + so, Bw + (size_t)(colBase + (int)row) * K + kOff + ch * 8);
        }
        CP_COMMIT();
    };

    // ldmatrix per-lane row indices (chunk varies with ks -> swizzled per use)
    const uint32_t mrow = (uint32_t)((lane & 7) + ((lane >> 3) & 1) * 8);
    const uint32_t aChunkBit = (uint32_t)(lane >> 4);          // 0/1
    const uint32_t nrow = (uint32_t)((lane & 7) + ((lane >> 4) << 3));
    const uint32_t bChunkBit = (uint32_t)((lane >> 3) & 1);    // 0/1

    load_stage(0);
    if (NC > 1) load_stage(1); else CP_COMMIT();

    for (int c = 0; c < NC; c++) {
        CP_WAIT1();                           // own copies for stage c done
        __syncthreads();                      // publish ALL threads' stage-c data
        if (c + 2 < NC) load_stage(c + 2);    // overwrites stage (c-1)%3 (safe: sync above)
        else            CP_COMMIT();          // keep group count uniform

        const int st = c % NSTAGE;
        const uint32_t aB = sb + st * STB;
        const uint32_t bB = aB + MATB;
#pragma unroll
        for (int ks = 0; ks < 4; ks++) {      // four k16 steps per BK=64
            const uint32_t cA = (uint32_t)ks * 2 + aChunkBit;
            const uint32_t cB = (uint32_t)ks * 2 + bChunkBit;
            uint32_t af[2][4], bf[4][4];
#pragma unroll
            for (int mt = 0; mt < 2; mt++)
                ldm4(af[mt], aB + swz((uint32_t)(wm * 32 + mt * 16) + mrow, cA));
#pragma unroll
            for (int jp = 0; jp < 4; jp++)
                ldm4(bf[jp], bB + swz((uint32_t)(wn * 64 + jp * 16) + nrow, cB));
#pragma unroll
            for (int mt = 0; mt < 2; mt++)
#pragma unroll
                for (int j = 0; j < 8; j++)
                    mma16816(acc[mt][j], af[mt], &bf[j >> 1][(j & 1) * 2]);
        }
        // no trailing sync: 3 distinct stage buffers; next iteration's top
        // sync orders all compute before buffer reuse.
    }

    // ---------------- epilogue (direct from registers) ----------------
    const int g = lane >> 2, t = lane & 3;
    const float es = (OUTF32 && Cf2) ? (1.0f + *epsp) : 0.0f;
#pragma unroll
    for (int mt = 0; mt < 2; mt++) {
        int rbase = rowBase + wm * 32 + mt * 16 + g;
#pragma unroll
        for (int half = 0; half < 2; half++) {
            int r = rbase + half * 8;
            if (r >= M) continue;
#pragma unroll
            for (int j = 0; j < 8; j++) {
                int cidx = colBase + wn * 64 + j * 8 + 2 * t;
                float v0 = acc[mt][j][half * 2 + 0] + bias[cidx];
                float v1 = acc[mt][j][half * 2 + 1] + bias[cidx + 1];
                if (RELU) { v0 = fmaxf(v0, 0.0f); v1 = fmaxf(v1, 0.0f); }
                if (BN_EN) {
                    v0 = (v0 - bnm[cidx]) * rsqrtf(bnv[cidx] + BN_EPS) * bng[cidx] + bnb[cidx];
                    v1 = (v1 - bnm[cidx + 1]) * rsqrtf(bnv[cidx + 1] + BN_EPS) * bng[cidx + 1] + bnb[cidx + 1];
                }
                if (OUTF32) {
                    *(float2*)(Cf + (size_t)r * HIDDEN + cidx) = make_float2(v0, v1);
                    if (Cf2)
                        *(float2*)(Cf2 + (size_t)r * HIDDEN + cidx) =
                            make_float2(v0 * es, v1 * es);
                } else {
                    *(uint32_t*)(Ch + (size_t)r * HIDDEN + cidx) = pack_h2(v0, v1);
                }
            }
        }
    }
}

// ---------------- auxiliary kernels ----------------
__global__ void scale_copy_kernel(const float4* __restrict__ in, float4* __restrict__ out,
                                  const float* __restrict__ eps, int n4) {
    float s = 1.0f + *eps;
    int i = blockIdx.x * blockDim.x + threadIdx.x;
    if (i < n4) {
        float4 v = in[i];
        v.x *= s; v.y *= s; v.z *= s; v.w *= s;
        out[i] = v;
    }
}

// out[dst[e]] += h[src[e]]  -- one warp/edge, float4 loads, v4 vector reductions
__global__ void scatter_add_kernel(const float* __restrict__ h, float* __restrict__ out,
                                   const int* __restrict__ src, const int* __restrict__ dst,
                                   int nEdges, int F) {
    int warp = (blockIdx.x * blockDim.x + threadIdx.x) >> 5;
    int lane = threadIdx.x & 31;
    if (warp >= nEdges) return;
    int s = src[warp], d = dst[warp];
    const float4* hs = (const float4*)(h + (size_t)s * F);
    float* od = out + (size_t)d * F;
    int f4 = F >> 2;
    for (int i = lane; i < f4; i += 32) {
        float4 v = hs[i];
        red_add_v4(od + 4 * i, v);
    }
}

// fp32 -> fp16 cast (streaming)
__global__ void quant_kernel(const float4* __restrict__ in, uint32_t* __restrict__ q, int n4) {
    int i = blockIdx.x * blockDim.x + threadIdx.x;
    if (i >= n4) return;
    float4 v = in[i];
    q[2 * i]     = pack_h2(v.x, v.y);
    q[2 * i + 1] = pack_h2(v.z, v.w);
}

// All 6 weights: W[K,N] f32 -> Wt[N,K] fp16 (transpose + cast). z = weight idx.
__global__ void wsplit_all_kernel(const float* __restrict__ W0, const float* __restrict__ W1p,
                                  const float* __restrict__ W2p, const float* __restrict__ W3p,
                                  const float* __restrict__ W4p, const float* __restrict__ W5p,
                                  __half* __restrict__ Wh) {
    __shared__ float t[32][33];
    int z = blockIdx.z;
    const float* W = z == 0 ? W0 : z == 1 ? W1p : z == 2 ? W2p : z == 3 ? W3p
                   : z == 4 ? W4p : W5p;
    int K = (z == 0) ? IN_F : HIDDEN;
    int k0 = blockIdx.y * 32;
    if (k0 >= K) return;
    int n0 = blockIdx.x * 32;
    int tx = threadIdx.x, ty = threadIdx.y;
#pragma unroll
    for (int i = 0; i < 4; i++)
        t[ty + i * 8][tx] = W[(size_t)(k0 + ty + i * 8) * HIDDEN + n0 + tx];
    __syncthreads();
    __half* dst = Wh + (size_t)z * WSLOT;
#pragma unroll
    for (int i = 0; i < 4; i++) {
        float v = t[tx][ty + i * 8];
        dst[(size_t)(n0 + ty + i * 8) * K + k0 + tx] = __float2half_rn(v);
    }
}

// edge classifier reading fp16 h: out[t,:] = (h[n0]*h[n1]) @ fc2_W + fc2_b
// smem weights transposed to [N_CLASS][HIDDEN] for conflict-free stride-1 reads.
__global__ void __launch_bounds__(256)
edge_pred_kernel(const __half* __restrict__ h, const int* __restrict__ ei,
                 const int* __restrict__ train_id, const float* __restrict__ W,
                 const float* __restrict__ b, float* __restrict__ out) {
    __shared__ float sWT[N_CLASS * HIDDEN];   // [j][k]
    __shared__ float sb[N_CLASS];
    for (int i = threadIdx.x; i < N_CLASS * HIDDEN; i += blockDim.x) {
        int j = i >> 9, k = i & 511;          // i = j*512 + k
        sWT[i] = W[k * N_CLASS + j];
    }
    if (threadIdx.x < N_CLASS) sb[threadIdx.x] = b[threadIdx.x];
    __syncthreads();
    int warp = (blockIdx.x * blockDim.x + threadIdx.x) >> 5;
    int lane = threadIdx.x & 31;
    if (warp >= N_TRAIN) return;
    int te = train_id[warp];
    int n0 = ei[te], n1 = ei[N_EDGES + te];
    const uint4* h0 = (const uint4*)(h + (size_t)n0 * HIDDEN);
    const uint4* h1 = (const uint4*)(h + (size_t)n1 * HIDDEN);
    float acc[N_CLASS];
#pragma unroll
    for (int j = 0; j < N_CLASS; j++) acc[j] = 0.0f;
    for (int i = lane; i < HIDDEN / 8; i += 32) {   // 8 halves per uint4
        uint4 a4 = h0[i], c4 = h1[i];
        const __half2* ah = (const __half2*)&a4;
        const __half2* ch = (const __half2*)&c4;
        int k = i * 8;
        float p[8];
#pragma unroll
        for (int q = 0; q < 4; q++) {
            float2 af = __half22float2(ah[q]);
            float2 cf = __half22float2(ch[q]);
            p[2 * q]     = af.x * cf.x;
            p[2 * q + 1] = af.y * cf.y;
        }
#pragma unroll
        for (int j = 0; j < N_CLASS; j++) {
            const float* wrow = sWT + j * HIDDEN + k;
#pragma unroll
            for (int q = 0; q < 8; q++)
                acc[j] += p[q] * wrow[q];
        }
    }
#pragma unroll
    for (int j = 0; j < N_CLASS; j++)
#pragma unroll
        for (int off = 16; off > 0; off >>= 1)
            acc[j] += __shfl_xor_sync(0xffffffffu, acc[j], off);
    if (lane == 0) {
#pragma unroll
        for (int j = 0; j < N_CLASS; j++)
            out[(size_t)warp * N_CLASS + j] = acc[j] + sb[j];
    }
}

// ---------------- launcher ----------------
extern "C" void kernel_launch(void* const* d_in, const int* in_sizes, int n_in,
                              void* d_out, int out_size) {
    const float* x     = (const float*)d_in[0];
    const int*   ei    = (const int*)d_in[1];
    const int*   trid  = (const int*)d_in[2];
    const float* W1    = (const float*)d_in[3];
    const float* b1    = (const float*)d_in[4];
    const float* W2    = (const float*)d_in[5];
    const float* b2    = (const float*)d_in[6];
    const float* W3    = (const float*)d_in[7];
    const float* b3    = (const float*)d_in[8];
    const float* bn1g  = (const float*)d_in[9];
    const float* bn1b  = (const float*)d_in[10];
    const float* bn1m  = (const float*)d_in[11];
    const float* bn1v  = (const float*)d_in[12];
    const float* eps1  = (const float*)d_in[13];
    const float* W4    = (const float*)d_in[14];
    const float* b4    = (const float*)d_in[15];
    const float* bn2g  = (const float*)d_in[16];
    const float* bn2b  = (const float*)d_in[17];
    const float* bn2m  = (const float*)d_in[18];
    const float* bn2v  = (const float*)d_in[19];
    const float* eps2  = (const float*)d_in[20];
    const float* lin1W = (const float*)d_in[21];
    const float* lin1b = (const float*)d_in[22];
    const float* lin2W = (const float*)d_in[23];
    const float* lin2b = (const float*)d_in[24];
    const float* fc2W  = (const float*)d_in[25];
    const float* fc2b  = (const float*)d_in[26];
    float* out = (float*)d_out;

    float *bufA, *bufB, *agg0;
    __half *hA, *hB, *wh;
    cudaGetSymbolAddress((void**)&bufA, g_bufA);
    cudaGetSymbolAddress((void**)&bufB, g_bufB);
    cudaGetSymbolAddress((void**)&agg0, g_agg0);
    cudaGetSymbolAddress((void**)&hA, g_hA);
    cudaGetSymbolAddress((void**)&hB, g_hB);
    cudaGetSymbolAddress((void**)&wh, g_wh);

    cudaFuncSetAttribute(hmma_gemm_kernel<true, false, false>,
                         cudaFuncAttributeMaxDynamicSharedMemorySize, SMEMSZ);
    cudaFuncSetAttribute(hmma_gemm_kernel<true, true, true>,
                         cudaFuncAttributeMaxDynamicSharedMemorySize, SMEMSZ);
    cudaFuncSetAttribute(hmma_gemm_kernel<true, true, false>,
                         cudaFuncAttributeMaxDynamicSharedMemorySize, SMEMSZ);
    cudaFuncSetAttribute(hmma_gemm_kernel<false, false, false>,
                         cudaFuncAttributeMaxDynamicSharedMemorySize, SMEMSZ);

    const int* src = ei;
    const int* dst = ei + N_EDGES;

    // all weight transposes + fp16 casts in one launch
    wsplit_all_kernel<<<dim3(16, 16, 6), dim3(32, 8)>>>(W1, W2, W3, W4, lin1W, lin2W, wh);

    // agg1 on x (fp32) then quantize to fp16
    {
        int n4 = N_NODES * IN_F / 4;
        scale_copy_kernel<<<(n4 + 255) / 256, 256>>>((const float4*)x, (float4*)agg0, eps1, n4);
        scatter_add_kernel<<<(N_EDGES * 32 + 255) / 256, 256>>>(x, agg0, src, dst, N_EDGES, IN_F);
        quant_kernel<<<(n4 + 255) / 256, 256>>>((const float4*)agg0, (uint32_t*)hA, n4);
    }

    dim3 gg(HIDDEN / GBN, (N_NODES + GBM - 1) / GBM);  // (4, 391)

    // L1: relu(agg @ W1 + b1) -> fp16
    hmma_gemm_kernel<true, false, false><<<gg, 256, SMEMSZ>>>(
        hA, wh + 0 * WSLOT, b1, nullptr, nullptr, nullptr, nullptr,
        nullptr, nullptr, nullptr, hB, N_NODES, IN_F);
    // L2: relu(h @ W2 + b2) -> fp16
    hmma_gemm_kernel<true, false, false><<<gg, 256, SMEMSZ>>>(
        hB, wh + 1 * WSLOT, b2, nullptr, nullptr, nullptr, nullptr,
        nullptr, nullptr, nullptr, hA, N_NODES, HIDDEN);
    // L3: bn1(relu(h @ W3 + b3)) -> fp32 bufA + (1+eps2)-scaled bufB (fused)
    hmma_gemm_kernel<true, true, true><<<gg, 256, SMEMSZ>>>(
        hA, wh + 2 * WSLOT, b3, bn1g, bn1b, bn1m, bn1v,
        bufA, bufB, eps2, nullptr, N_NODES, HIDDEN);
    // agg2: bufB += bufA[src] scattered, then quantize
    {
        int n4 = N_NODES * HIDDEN / 4;
        scatter_add_kernel<<<(N_EDGES * 32 + 255) / 256, 256>>>(bufA, bufB, src, dst, N_EDGES, HIDDEN);
        quant_kernel<<<(n4 + 255) / 256, 256>>>((const float4*)bufB, (uint32_t*)hA, n4);
    }
    // L4: bn2(relu(h @ W4 + b4)) -> fp16
    hmma_gemm_kernel<true, true, false><<<gg, 256, SMEMSZ>>>(
        hA, wh + 3 * WSLOT, b4, bn2g, bn2b, bn2m, bn2v,
        nullptr, nullptr, nullptr, hB, N_NODES, HIDDEN);
    // L5: relu(h @ lin1W + lin1b) -> fp16
    hmma_gemm_kernel<true, false, false><<<gg, 256, SMEMSZ>>>(
        hB, wh + 4 * WSLOT, lin1b, nullptr, nullptr, nullptr, nullptr,
        nullptr, nullptr, nullptr, hA, N_NODES, HIDDEN);
    // L6: h @ lin2W + lin2b -> fp16 (consumed only by edge classifier)
    hmma_gemm_kernel<false, false, false><<<gg, 256, SMEMSZ>>>(
        hA, wh + 5 * WSLOT, lin2b, nullptr, nullptr, nullptr, nullptr,
        nullptr, nullptr, nullptr, hB, N_NODES, HIDDEN);
    // edge classifier (fp16 h)
    edge_pred_kernel<<<(N_TRAIN * 32 + 255) / 256, 256>>>(hB, ei, trid, fc2W, fc2b, out);
}

// round 15
// speedup vs baseline: 4.5174x; 1.1326x over previous
#include <cuda_runtime.h>
#include <cuda_fp16.h>
#include <cstdint>

#define N_NODES 50000
#define IN_F    64
#define HIDDEN  512
#define N_EDGES 160000
#define N_TRAIN 80000
#define N_CLASS 7
#define BN_EPS  1e-5f

// ---------------- static device scratch (no allocation) ----------------
__device__ __align__(16) float g_agg0[(size_t)N_NODES * IN_F];
__device__ __align__(16) __half g_hA[(size_t)N_NODES * HIDDEN];
__device__ __align__(16) __half g_hB[(size_t)N_NODES * HIDDEN];
__device__ __align__(16) __half g_hC[(size_t)N_NODES * HIDDEN];
#define WSLOT (HIDDEN * HIDDEN)
__device__ __align__(16) __half g_wh[6 * WSLOT];

// ---------------- PTX helpers (base-target only: sm_80/90-class) ----------------
__device__ __forceinline__ uint32_t cvta_shared(const void* p) {
    uint32_t a;
    asm("{ .reg .u64 t; cvta.to.shared.u64 t, %1; cvt.u32.u64 %0, t; }" : "=r"(a) : "l"(p));
    return a;
}
#define CP16(dst, src) \
    asm volatile("cp.async.cg.shared.global [%0], [%1], 16;" :: "r"(dst), "l"(src))
#define CP_COMMIT() asm volatile("cp.async.commit_group;" ::: "memory")
#define CP_WAIT1()  asm volatile("cp.async.wait_group 1;" ::: "memory")

__device__ __forceinline__ void ldm4(uint32_t* r, uint32_t addr) {
    asm volatile("ldmatrix.sync.aligned.m8n8.x4.shared.b16 {%0,%1,%2,%3}, [%4];"
        : "=r"(r[0]), "=r"(r[1]), "=r"(r[2]), "=r"(r[3]) : "r"(addr));
}
__device__ __forceinline__ void mma16816(float* d, const uint32_t* a, const uint32_t* b) {
    asm volatile(
        "mma.sync.aligned.m16n8k16.row.col.f32.f16.f16.f32 "
        "{%0,%1,%2,%3},{%4,%5,%6,%7},{%8,%9},{%0,%1,%2,%3};"
        : "+f"(d[0]), "+f"(d[1]), "+f"(d[2]), "+f"(d[3])
        : "r"(a[0]), "r"(a[1]), "r"(a[2]), "r"(a[3]), "r"(b[0]), "r"(b[1]));
}
// fp32 vector reduction (PTX ISA 8.1)
__device__ __forceinline__ void red_add_v4(float* addr, float4 v) {
    asm volatile("red.global.add.v4.f32 [%0], {%1, %2, %3, %4};"
        :: "l"(addr), "f"(v.x), "f"(v.y), "f"(v.z), "f"(v.w) : "memory");
}
// fp16x2 vector reduction: 8 halves per instruction (PTX ISA 8.1)
__device__ __forceinline__ void red_add_v4h2(__half* addr, uint4 v) {
    asm volatile("red.global.add.noftz.v4.f16x2 [%0], {%1, %2, %3, %4};"
        :: "l"(addr), "r"(v.x), "r"(v.y), "r"(v.z), "r"(v.w) : "memory");
}
__device__ __forceinline__ uint32_t pack_h2(float a, float b) {
    __half2 h = __floats2half2_rn(a, b);
    return *(uint32_t*)&h;
}

// swizzle for 128B rows: logical (row, 16B-chunk c in 0..7) -> phys byte off.
// chunk' = c ^ (row & 7): 8 consecutive rows at fixed c hit 8 distinct
// 16B bank groups -> ldmatrix conflict-free.
__device__ __forceinline__ uint32_t swz(uint32_t row, uint32_t c) {
    return row * 128u + ((c ^ (row & 7u)) << 4);
}

// ---------------- HMMA fp16 GEMM ----------------
// C[M,512] = A[M,K] @ W[512,K]^T, both fp16.
// CTA 128x128, BK=64 (4x k16 per stage), 3-stage cp.async, 2 CTAs/SM.
// DUAL: also emit Ch2 = (1+eps)*h (fp16) as the aggregation base.
#define GBM   128
#define GBN   128
#define GBK   64
#define MATB  (128 * 128)            // 16384 per matrix per stage
#define STB   (2 * MATB)             // 32768 per stage (A, W)
#define NSTAGE 3
#define SMEMSZ (NSTAGE * STB)        // 98304 -> 2 CTAs/SM

template <bool RELU, bool BN_EN, bool DUAL>
__global__ void __launch_bounds__(256, 2)
hmma_gemm_kernel(const __half* __restrict__ A,
                 const __half* __restrict__ Bw,
                 const float* __restrict__ bias,
                 const float* __restrict__ bng, const float* __restrict__ bnb,
                 const float* __restrict__ bnm, const float* __restrict__ bnv,
                 const float* __restrict__ epsp,
                 __half* __restrict__ Ch, __half* __restrict__ Ch2,
                 int M, int K) {
    extern __shared__ char smem[];
    const uint32_t sb = cvta_shared(smem);
    const int tid = threadIdx.x, lane = tid & 31, wid = tid >> 5;
    const int wm = wid >> 1, wn = wid & 1;           // 4x2 warp grid
    const int rowBase = blockIdx.y * GBM;
    const int colBase = blockIdx.x * GBN;
    const int NC = K / GBK;

    float acc[2][8][4];
#pragma unroll
    for (int a = 0; a < 2; a++)
#pragma unroll
        for (int b = 0; b < 8; b++)
#pragma unroll
            for (int c = 0; c < 4; c++) acc[a][b][c] = 0.0f;

    auto load_stage = [&](int c) {
        const int st = c % NSTAGE;
        const uint32_t base = sb + st * STB;
        const int kOff = c * GBK;
#pragma unroll
        for (int u = 0; u < 4; u++) {         // 1024 chunks per matrix
            int idx = tid + u * 256;
            uint32_t row = (uint32_t)idx >> 3, ch = (uint32_t)idx & 7;
            int gr = rowBase + (int)row;
            if (gr > M - 1) gr = M - 1;       // clamp (finite junk, rows not stored)
            uint32_t so = swz(row, ch);
            CP16(base + so, A + (size_t)gr * K + kOff + ch * 8);
            CP16(base + MATB + so, Bw + (size_t)(colBase + (int)row) * K + kOff + ch * 8);
        }
        CP_COMMIT();
    };

    // ldmatrix per-lane row indices (chunk varies with ks -> swizzled per use)
    const uint32_t mrow = (uint32_t)((lane & 7) + ((lane >> 3) & 1) * 8);
    const uint32_t aChunkBit = (uint32_t)(lane >> 4);          // 0/1
    const uint32_t nrow = (uint32_t)((lane & 7) + ((lane >> 4) << 3));
    const uint32_t bChunkBit = (uint32_t)((lane >> 3) & 1);    // 0/1

    load_stage(0);
    if (NC > 1) load_stage(1); else CP_COMMIT();

    for (int c = 0; c < NC; c++) {
        CP_WAIT1();                           // own copies for stage c done
        __syncthreads();                      // publish ALL threads' stage-c data
        if (c + 2 < NC) load_stage(c + 2);    // overwrites stage (c-1)%3 (safe: sync above)
        else            CP_COMMIT();          // keep group count uniform

        const int st = c % NSTAGE;
        const uint32_t aB = sb + st * STB;
        const uint32_t bB = aB + MATB;
#pragma unroll
        for (int ks = 0; ks < 4; ks++) {      // four k16 steps per BK=64
            const uint32_t cA = (uint32_t)ks * 2 + aChunkBit;
            const uint32_t cB = (uint32_t)ks * 2 + bChunkBit;
            uint32_t af[2][4], bf[4][4];
#pragma unroll
            for (int mt = 0; mt < 2; mt++)
                ldm4(af[mt], aB + swz((uint32_t)(wm * 32 + mt * 16) + mrow, cA));
#pragma unroll
            for (int jp = 0; jp < 4; jp++)
                ldm4(bf[jp], bB + swz((uint32_t)(wn * 64 + jp * 16) + nrow, cB));
#pragma unroll
            for (int mt = 0; mt < 2; mt++)
#pragma unroll
                for (int j = 0; j < 8; j++)
                    mma16816(acc[mt][j], af[mt], &bf[j >> 1][(j & 1) * 2]);
        }
        // no trailing sync: 3 distinct stage buffers; next iteration's top
        // sync orders all compute before buffer reuse.
    }

    // ---------------- epilogue (direct from registers) ----------------
    const int g = lane >> 2, t = lane & 3;
    const float es = DUAL ? (1.0f + *epsp) : 0.0f;
#pragma unroll
    for (int mt = 0; mt < 2; mt++) {
        int rbase = rowBase + wm * 32 + mt * 16 + g;
#pragma unroll
        for (int half = 0; half < 2; half++) {
            int r = rbase + half * 8;
            if (r >= M) continue;
#pragma unroll
            for (int j = 0; j < 8; j++) {
                int cidx = colBase + wn * 64 + j * 8 + 2 * t;
                float v0 = acc[mt][j][half * 2 + 0] + bias[cidx];
                float v1 = acc[mt][j][half * 2 + 1] + bias[cidx + 1];
                if (RELU) { v0 = fmaxf(v0, 0.0f); v1 = fmaxf(v1, 0.0f); }
                if (BN_EN) {
                    v0 = (v0 - bnm[cidx]) * rsqrtf(bnv[cidx] + BN_EPS) * bng[cidx] + bnb[cidx];
                    v1 = (v1 - bnm[cidx + 1]) * rsqrtf(bnv[cidx + 1] + BN_EPS) * bng[cidx + 1] + bnb[cidx + 1];
                }
                *(uint32_t*)(Ch + (size_t)r * HIDDEN + cidx) = pack_h2(v0, v1);
                if (DUAL)
                    *(uint32_t*)(Ch2 + (size_t)r * HIDDEN + cidx) =
                        pack_h2(v0 * es, v1 * es);
            }
        }
    }
}

// ---------------- auxiliary kernels ----------------
__global__ void scale_copy_kernel(const float4* __restrict__ in, float4* __restrict__ out,
                                  const float* __restrict__ eps, int n4) {
    float s = 1.0f + *eps;
    int i = blockIdx.x * blockDim.x + threadIdx.x;
    if (i < n4) {
        float4 v = in[i];
        v.x *= s; v.y *= s; v.z *= s; v.w *= s;
        out[i] = v;
    }
}

// fp32 scatter (agg1): out[dst[e]] += h[src[e]], one warp/edge
__global__ void scatter_add_kernel(const float* __restrict__ h, float* __restrict__ out,
                                   const int* __restrict__ src, const int* __restrict__ dst,
                                   int nEdges, int F) {
    int warp = (blockIdx.x * blockDim.x + threadIdx.x) >> 5;
    int lane = threadIdx.x & 31;
    if (warp >= nEdges) return;
    int s = src[warp], d = dst[warp];
    const float4* hs = (const float4*)(h + (size_t)s * F);
    float* od = out + (size_t)d * F;
    int f4 = F >> 2;
    for (int i = lane; i < f4; i += 32) {
        float4 v = hs[i];
        red_add_v4(od + 4 * i, v);
    }
}

// fp16 scatter (agg2): out[dst[e]] += h[src[e]], 512 halves/row = 64 uint4
__global__ void scatter_add_f16_kernel(const __half* __restrict__ h, __half* __restrict__ out,
                                       const int* __restrict__ src, const int* __restrict__ dst,
                                       int nEdges) {
    int warp = (blockIdx.x * blockDim.x + threadIdx.x) >> 5;
    int lane = threadIdx.x & 31;
    if (warp >= nEdges) return;
    int s = src[warp], d = dst[warp];
    const uint4* hs = (const uint4*)(h + (size_t)s * HIDDEN);
    __half* od = out + (size_t)d * HIDDEN;
#pragma unroll
    for (int i = lane; i < HIDDEN / 8; i += 32) {
        uint4 v = hs[i];
        red_add_v4h2(od + 8 * i, v);
    }
}

// fp32 -> fp16 cast (streaming)
__global__ void quant_kernel(const float4* __restrict__ in, uint32_t* __restrict__ q, int n4) {
    int i = blockIdx.x * blockDim.x + threadIdx.x;
    if (i >= n4) return;
    float4 v = in[i];
    q[2 * i]     = pack_h2(v.x, v.y);
    q[2 * i + 1] = pack_h2(v.z, v.w);
}

// All 6 weights: W[K,N] f32 -> Wt[N,K] fp16 (transpose + cast). z = weight idx.
__global__ void wsplit_all_kernel(const float* __restrict__ W0, const float* __restrict__ W1p,
                                  const float* __restrict__ W2p, const float* __restrict__ W3p,
                                  const float* __restrict__ W4p, const float* __restrict__ W5p,
                                  __half* __restrict__ Wh) {
    __shared__ float t[32][33];
    int z = blockIdx.z;
    const float* W = z == 0 ? W0 : z == 1 ? W1p : z == 2 ? W2p : z == 3 ? W3p
                   : z == 4 ? W4p : W5p;
    int K = (z == 0) ? IN_F : HIDDEN;
    int k0 = blockIdx.y * 32;
    if (k0 >= K) return;
    int n0 = blockIdx.x * 32;
    int tx = threadIdx.x, ty = threadIdx.y;
#pragma unroll
    for (int i = 0; i < 4; i++)
        t[ty + i * 8][tx] = W[(size_t)(k0 + ty + i * 8) * HIDDEN + n0 + tx];
    __syncthreads();
    __half* dst = Wh + (size_t)z * WSLOT;
#pragma unroll
    for (int i = 0; i < 4; i++) {
        float v = t[tx][ty + i * 8];
        dst[(size_t)(n0 + ty + i * 8) * K + k0 + tx] = __float2half_rn(v);
    }
}

// edge classifier reading fp16 h: out[t,:] = (h[n0]*h[n1]) @ fc2_W + fc2_b
// smem weights transposed to [N_CLASS][HIDDEN] for conflict-free stride-1 reads.
__global__ void __launch_bounds__(256)
edge_pred_kernel(const __half* __restrict__ h, const int* __restrict__ ei,
                 const int* __restrict__ train_id, const float* __restrict__ W,
                 const float* __restrict__ b, float* __restrict__ out) {
    __shared__ float sWT[N_CLASS * HIDDEN];   // [j][k]
    __shared__ float sb[N_CLASS];
    for (int i = threadIdx.x; i < N_CLASS * HIDDEN; i += blockDim.x) {
        int j = i >> 9, k = i & 511;          // i = j*512 + k
        sWT[i] = W[k * N_CLASS + j];
    }
    if (threadIdx.x < N_CLASS) sb[threadIdx.x] = b[threadIdx.x];
    __syncthreads();
    int warp = (blockIdx.x * blockDim.x + threadIdx.x) >> 5;
    int lane = threadIdx.x & 31;
    if (warp >= N_TRAIN) return;
    int te = train_id[warp];
    int n0 = ei[te], n1 = ei[N_EDGES + te];
    const uint4* h0 = (const uint4*)(h + (size_t)n0 * HIDDEN);
    const uint4* h1 = (const uint4*)(h + (size_t)n1 * HIDDEN);
    float acc[N_CLASS];
#pragma unroll
    for (int j = 0; j < N_CLASS; j++) acc[j] = 0.0f;
    for (int i = lane; i < HIDDEN / 8; i += 32) {   // 8 halves per uint4
        uint4 a4 = h0[i], c4 = h1[i];
        const __half2* ah = (const __half2*)&a4;
        const __half2* ch = (const __half2*)&c4;
        int k = i * 8;
        float p[8];
#pragma unroll
        for (int q = 0; q < 4; q++) {
            float2 af = __half22float2(ah[q]);
            float2 cf = __half22float2(ch[q]);
            p[2 * q]     = af.x * cf.x;
            p[2 * q + 1] = af.y * cf.y;
        }
#pragma unroll
        for (int j = 0; j < N_CLASS; j++) {
            const float* wrow = sWT + j * HIDDEN + k;
#pragma unroll
            for (int q = 0; q < 8; q++)
                acc[j] += p[q] * wrow[q];
        }
    }
#pragma unroll
    for (int j = 0; j < N_CLASS; j++)
#pragma unroll
        for (int off = 16; off > 0; off >>= 1)
            acc[j] += __shfl_xor_sync(0xffffffffu, acc[j], off);
    if (lane == 0) {
#pragma unroll
        for (int j = 0; j < N_CLASS; j++)
            out[(size_t)warp * N_CLASS + j] = acc[j] + sb[j];
    }
}

// ---------------- launcher ----------------
extern "C" void kernel_launch(void* const* d_in, const int* in_sizes, int n_in,
                              void* d_out, int out_size) {
    const float* x     = (const float*)d_in[0];
    const int*   ei    = (const int*)d_in[1];
    const int*   trid  = (const int*)d_in[2];
    const float* W1    = (const float*)d_in[3];
    const float* b1    = (const float*)d_in[4];
    const float* W2    = (const float*)d_in[5];
    const float* b2    = (const float*)d_in[6];
    const float* W3    = (const float*)d_in[7];
    const float* b3    = (const float*)d_in[8];
    const float* bn1g  = (const float*)d_in[9];
    const float* bn1b  = (const float*)d_in[10];
    const float* bn1m  = (const float*)d_in[11];
    const float* bn1v  = (const float*)d_in[12];
    const float* eps1  = (const float*)d_in[13];
    const float* W4    = (const float*)d_in[14];
    const float* b4    = (const float*)d_in[15];
    const float* bn2g  = (const float*)d_in[16];
    const float* bn2b  = (const float*)d_in[17];
    const float* bn2m  = (const float*)d_in[18];
    const float* bn2v  = (const float*)d_in[19];
    const float* eps2  = (const float*)d_in[20];
    const float* lin1W = (const float*)d_in[21];
    const float* lin1b = (const float*)d_in[22];
    const float* lin2W = (const float*)d_in[23];
    const float* lin2b = (const float*)d_in[24];
    const float* fc2W  = (const float*)d_in[25];
    const float* fc2b  = (const float*)d_in[26];
    float* out = (float*)d_out;

    float* agg0;
    __half *hA, *hB, *hC, *wh;
    cudaGetSymbolAddress((void**)&agg0, g_agg0);
    cudaGetSymbolAddress((void**)&hA, g_hA);
    cudaGetSymbolAddress((void**)&hB, g_hB);
    cudaGetSymbolAddress((void**)&hC, g_hC);
    cudaGetSymbolAddress((void**)&wh, g_wh);

    cudaFuncSetAttribute(hmma_gemm_kernel<true, false, false>,
                         cudaFuncAttributeMaxDynamicSharedMemorySize, SMEMSZ);
    cudaFuncSetAttribute(hmma_gemm_kernel<true, true, true>,
                         cudaFuncAttributeMaxDynamicSharedMemorySize, SMEMSZ);
    cudaFuncSetAttribute(hmma_gemm_kernel<true, true, false>,
                         cudaFuncAttributeMaxDynamicSharedMemorySize, SMEMSZ);
    cudaFuncSetAttribute(hmma_gemm_kernel<false, false, false>,
                         cudaFuncAttributeMaxDynamicSharedMemorySize, SMEMSZ);

    const int* src = ei;
    const int* dst = ei + N_EDGES;

    // all weight transposes + fp16 casts in one launch
    wsplit_all_kernel<<<dim3(16, 16, 6), dim3(32, 8)>>>(W1, W2, W3, W4, lin1W, lin2W, wh);

    // agg1 on x (fp32) then quantize to fp16
    {
        int n4 = N_NODES * IN_F / 4;
        scale_copy_kernel<<<(n4 + 255) / 256, 256>>>((const float4*)x, (float4*)agg0, eps1, n4);
        scatter_add_kernel<<<(N_EDGES * 32 + 255) / 256, 256>>>(x, agg0, src, dst, N_EDGES, IN_F);
        quant_kernel<<<(n4 + 255) / 256, 256>>>((const float4*)agg0, (uint32_t*)hA, n4);
    }

    dim3 gg(HIDDEN / GBN, (N_NODES + GBM - 1) / GBM);  // (4, 391)

    // L1: relu(agg @ W1 + b1) -> hB
    hmma_gemm_kernel<true, false, false><<<gg, 256, SMEMSZ>>>(
        hA, wh + 0 * WSLOT, b1, nullptr, nullptr, nullptr, nullptr,
        nullptr, hB, nullptr, N_NODES, IN_F);
    // L2: relu(h @ W2 + b2) -> hA
    hmma_gemm_kernel<true, false, false><<<gg, 256, SMEMSZ>>>(
        hB, wh + 1 * WSLOT, b2, nullptr, nullptr, nullptr, nullptr,
        nullptr, hA, nullptr, N_NODES, HIDDEN);
    // L3: bn1(relu(h @ W3 + b3)) -> hB (h) + hC ((1+eps2)*h, fused agg base)
    hmma_gemm_kernel<true, true, true><<<gg, 256, SMEMSZ>>>(
        hA, wh + 2 * WSLOT, b3, bn1g, bn1b, bn1m, bn1v,
        eps2, hB, hC, N_NODES, HIDDEN);
    // agg2 (fp16): hC[dst] += hB[src]
    scatter_add_f16_kernel<<<(N_EDGES * 32 + 255) / 256, 256>>>(hB, hC, src, dst, N_EDGES);
    // L4: bn2(relu(h @ W4 + b4)) -> hA
    hmma_gemm_kernel<true, true, false><<<gg, 256, SMEMSZ>>>(
        hC, wh + 3 * WSLOT, b4, bn2g, bn2b, bn2m, bn2v,
        nullptr, hA, nullptr, N_NODES, HIDDEN);
    // L5: relu(h @ lin1W + lin1b) -> hB
    hmma_gemm_kernel<true, false, false><<<gg, 256, SMEMSZ>>>(
        hA, wh + 4 * WSLOT, lin1b, nullptr, nullptr, nullptr, nullptr,
        nullptr, hB, nullptr, N_NODES, HIDDEN);
    // L6: h @ lin2W + lin2b -> hC
    hmma_gemm_kernel<false, false, false><<<gg, 256, SMEMSZ>>>(
        hB, wh + 5 * WSLOT, lin2b, nullptr, nullptr, nullptr, nullptr,
        nullptr, hC, nullptr, N_NODES, HIDDEN);
    // edge classifier (fp16 h)
    edge_pred_kernel<<<(N_TRAIN * 32 + 255) / 256, 256>>>(hC, ei, trid, fc2W, fc2b, out);
}

// round 16
// speedup vs baseline: 4.8103x; 1.0648x over previous
#include <cuda_runtime.h>
#include <cuda_fp16.h>
#include <cstdint>

#define N_NODES 50000
#define IN_F    64
#define HIDDEN  512
#define N_EDGES 160000
#define N_TRAIN 80000
#define N_CLASS 7
#define BN_EPS  1e-5f

// ---------------- static device scratch (no allocation) ----------------
__device__ __align__(16) __half g_hA[(size_t)N_NODES * HIDDEN];
__device__ __align__(16) __half g_hB[(size_t)N_NODES * HIDDEN];
__device__ __align__(16) __half g_hC[(size_t)N_NODES * HIDDEN];
__device__ __align__(16) __half g_hX[(size_t)N_NODES * IN_F];
#define WSLOT (HIDDEN * HIDDEN)
__device__ __align__(16) __half g_wh[6 * WSLOT];

// ---------------- PTX helpers (base-target only: sm_80/90-class) ----------------
__device__ __forceinline__ uint32_t cvta_shared(const void* p) {
    uint32_t a;
    asm("{ .reg .u64 t; cvta.to.shared.u64 t, %1; cvt.u32.u64 %0, t; }" : "=r"(a) : "l"(p));
    return a;
}
#define CP16(dst, src) \
    asm volatile("cp.async.cg.shared.global [%0], [%1], 16;" :: "r"(dst), "l"(src))
#define CP_COMMIT() asm volatile("cp.async.commit_group;" ::: "memory")
#define CP_WAIT1()  asm volatile("cp.async.wait_group 1;" ::: "memory")

__device__ __forceinline__ void ldm4(uint32_t* r, uint32_t addr) {
    asm volatile("ldmatrix.sync.aligned.m8n8.x4.shared.b16 {%0,%1,%2,%3}, [%4];"
        : "=r"(r[0]), "=r"(r[1]), "=r"(r[2]), "=r"(r[3]) : "r"(addr));
}
__device__ __forceinline__ void mma16816(float* d, const uint32_t* a, const uint32_t* b) {
    asm volatile(
        "mma.sync.aligned.m16n8k16.row.col.f32.f16.f16.f32 "
        "{%0,%1,%2,%3},{%4,%5,%6,%7},{%8,%9},{%0,%1,%2,%3};"
        : "+f"(d[0]), "+f"(d[1]), "+f"(d[2]), "+f"(d[3])
        : "r"(a[0]), "r"(a[1]), "r"(a[2]), "r"(a[3]), "r"(b[0]), "r"(b[1]));
}
// fp16x2 vector reduction: 8 halves per instruction (PTX ISA 8.1)
__device__ __forceinline__ void red_add_v4h2(__half* addr, uint4 v) {
    asm volatile("red.global.add.noftz.v4.f16x2 [%0], {%1, %2, %3, %4};"
        :: "l"(addr), "r"(v.x), "r"(v.y), "r"(v.z), "r"(v.w) : "memory");
}
__device__ __forceinline__ uint32_t pack_h2(float a, float b) {
    __half2 h = __floats2half2_rn(a, b);
    return *(uint32_t*)&h;
}

// swizzle for 128B rows: logical (row, 16B-chunk c in 0..7) -> phys byte off.
// chunk' = c ^ (row & 7): 8 consecutive rows at fixed c hit 8 distinct
// 16B bank groups -> ldmatrix conflict-free.
__device__ __forceinline__ uint32_t swz(uint32_t row, uint32_t c) {
    return row * 128u + ((c ^ (row & 7u)) << 4);
}

// ---------------- HMMA fp16 GEMM ----------------
// C[M,512] = A[M,K] @ W[512,K]^T, both fp16.
// CTA 128x128, BK=64 (4x k16 per stage), 3-stage cp.async, 2 CTAs/SM.
// DUAL: also emit Ch2 = (1+eps)*h (fp16) as the aggregation base.
#define GBM   128
#define GBN   128
#define GBK   64
#define MATB  (128 * 128)            // 16384 per matrix per stage
#define STB   (2 * MATB)             // 32768 per stage (A, W)
#define NSTAGE 3
#define SMEMSZ (NSTAGE * STB)        // 98304 -> 2 CTAs/SM

template <bool RELU, bool BN_EN, bool DUAL>
__global__ void __launch_bounds__(256, 2)
hmma_gemm_kernel(const __half* __restrict__ A,
                 const __half* __restrict__ Bw,
                 const float* __restrict__ bias,
                 const float* __restrict__ bng, const float* __restrict__ bnb,
                 const float* __restrict__ bnm, const float* __restrict__ bnv,
                 const float* __restrict__ epsp,
                 __half* __restrict__ Ch, __half* __restrict__ Ch2,
                 int M, int K) {
    extern __shared__ char smem[];
    const uint32_t sb = cvta_shared(smem);
    const int tid = threadIdx.x, lane = tid & 31, wid = tid >> 5;
    const int wm = wid >> 1, wn = wid & 1;           // 4x2 warp grid
    const int rowBase = blockIdx.y * GBM;
    const int colBase = blockIdx.x * GBN;
    const int NC = K / GBK;

    float acc[2][8][4];
#pragma unroll
    for (int a = 0; a < 2; a++)
#pragma unroll
        for (int b = 0; b < 8; b++)
#pragma unroll
            for (int c = 0; c < 4; c++) acc[a][b][c] = 0.0f;

    auto load_stage = [&](int c) {
        const int st = c % NSTAGE;
        const uint32_t base = sb + st * STB;
        const int kOff = c * GBK;
#pragma unroll
        for (int u = 0; u < 4; u++) {         // 1024 chunks per matrix
            int idx = tid + u * 256;
            uint32_t row = (uint32_t)idx >> 3, ch = (uint32_t)idx & 7;
            int gr = rowBase + (int)row;
            if (gr > M - 1) gr = M - 1;       // clamp (finite junk, rows not stored)
            uint32_t so = swz(row, ch);
            CP16(base + so, A + (size_t)gr * K + kOff + ch * 8);
            CP16(base + MATB + so, Bw + (size_t)(colBase + (int)row) * K + kOff + ch * 8);
        }
        CP_COMMIT();
    };

    // ldmatrix per-lane row indices (chunk varies with ks -> swizzled per use)
    const uint32_t mrow = (uint32_t)((lane & 7) + ((lane >> 3) & 1) * 8);
    const uint32_t aChunkBit = (uint32_t)(lane >> 4);          // 0/1
    const uint32_t nrow = (uint32_t)((lane & 7) + ((lane >> 4) << 3));
    const uint32_t bChunkBit = (uint32_t)((lane >> 3) & 1);    // 0/1

    load_stage(0);
    if (NC > 1) load_stage(1); else CP_COMMIT();

    for (int c = 0; c < NC; c++) {
        CP_WAIT1();                           // own copies for stage c done
        __syncthreads();                      // publish ALL threads' stage-c data
        if (c + 2 < NC) load_stage(c + 2);    // overwrites stage (c-1)%3 (safe: sync above)
        else            CP_COMMIT();          // keep group count uniform

        const int st = c % NSTAGE;
        const uint32_t aB = sb + st * STB;
        const uint32_t bB = aB + MATB;
#pragma unroll
        for (int ks = 0; ks < 4; ks++) {      // four k16 steps per BK=64
            const uint32_t cA = (uint32_t)ks * 2 + aChunkBit;
            const uint32_t cB = (uint32_t)ks * 2 + bChunkBit;
            uint32_t af[2][4], bf[4][4];
#pragma unroll
            for (int mt = 0; mt < 2; mt++)
                ldm4(af[mt], aB + swz((uint32_t)(wm * 32 + mt * 16) + mrow, cA));
#pragma unroll
            for (int jp = 0; jp < 4; jp++)
                ldm4(bf[jp], bB + swz((uint32_t)(wn * 64 + jp * 16) + nrow, cB));
#pragma unroll
            for (int mt = 0; mt < 2; mt++)
#pragma unroll
                for (int j = 0; j < 8; j++)
                    mma16816(acc[mt][j], af[mt], &bf[j >> 1][(j & 1) * 2]);
        }
        // no trailing sync: 3 distinct stage buffers; next iteration's top
        // sync orders all compute before buffer reuse.
    }

    // ---------------- epilogue (direct from registers) ----------------
    const int g = lane >> 2, t = lane & 3;
    const float es = DUAL ? (1.0f + *epsp) : 0.0f;
#pragma unroll
    for (int mt = 0; mt < 2; mt++) {
        int rbase = rowBase + wm * 32 + mt * 16 + g;
#pragma unroll
        for (int half = 0; half < 2; half++) {
            int r = rbase + half * 8;
            if (r >= M) continue;
#pragma unroll
            for (int j = 0; j < 8; j++) {
                int cidx = colBase + wn * 64 + j * 8 + 2 * t;
                float v0 = acc[mt][j][half * 2 + 0] + bias[cidx];
                float v1 = acc[mt][j][half * 2 + 1] + bias[cidx + 1];
                if (RELU) { v0 = fmaxf(v0, 0.0f); v1 = fmaxf(v1, 0.0f); }
                if (BN_EN) {
                    v0 = (v0 - bnm[cidx]) * rsqrtf(bnv[cidx] + BN_EPS) * bng[cidx] + bnb[cidx];
                    v1 = (v1 - bnm[cidx + 1]) * rsqrtf(bnv[cidx + 1] + BN_EPS) * bng[cidx + 1] + bnb[cidx + 1];
                }
                *(uint32_t*)(Ch + (size_t)r * HIDDEN + cidx) = pack_h2(v0, v1);
                if (DUAL)
                    *(uint32_t*)(Ch2 + (size_t)r * HIDDEN + cidx) =
                        pack_h2(v0 * es, v1 * es);
            }
        }
    }
}

// ---------------- auxiliary kernels ----------------
// x (fp32) -> hX = fp16(x), hA = fp16((1+eps1)*x). One pass.
__global__ void quantx_kernel(const float4* __restrict__ x, uint32_t* __restrict__ hX,
                              uint32_t* __restrict__ hA, const float* __restrict__ eps,
                              int n4) {
    float s = 1.0f + *eps;
    int i = blockIdx.x * blockDim.x + threadIdx.x;
    if (i >= n4) return;
    float4 v = x[i];
    hX[2 * i]     = pack_h2(v.x, v.y);
    hX[2 * i + 1] = pack_h2(v.z, v.w);
    hA[2 * i]     = pack_h2(v.x * s, v.y * s);
    hA[2 * i + 1] = pack_h2(v.z * s, v.w * s);
}

// fp16 scatter for F=64: 4 edges per warp (8 lanes each, 1 uint4 per lane)
__global__ void scatter64_f16_kernel(const __half* __restrict__ h, __half* __restrict__ out,
                                     const int* __restrict__ src, const int* __restrict__ dst,
                                     int nEdges) {
    int t = blockIdx.x * blockDim.x + threadIdx.x;
    int e = t >> 3, c = t & 7;
    if (e >= nEdges) return;
    int s = src[e], d = dst[e];
    uint4 v = *(const uint4*)(h + (size_t)s * IN_F + c * 8);
    red_add_v4h2(out + (size_t)d * IN_F + c * 8, v);
}

// fp16 scatter for F=512: one warp per edge, 64 uint4 per row
__global__ void scatter_add_f16_kernel(const __half* __restrict__ h, __half* __restrict__ out,
                                       const int* __restrict__ src, const int* __restrict__ dst,
                                       int nEdges) {
    int warp = (blockIdx.x * blockDim.x + threadIdx.x) >> 5;
    int lane = threadIdx.x & 31;
    if (warp >= nEdges) return;
    int s = src[warp], d = dst[warp];
    const uint4* hs = (const uint4*)(h + (size_t)s * HIDDEN);
    __half* od = out + (size_t)d * HIDDEN;
#pragma unroll
    for (int i = lane; i < HIDDEN / 8; i += 32) {
        uint4 v = hs[i];
        red_add_v4h2(od + 8 * i, v);
    }
}

// All 6 weights: W[K,N] f32 -> Wt[N,K] fp16 (transpose + cast). z = weight idx.
__global__ void wsplit_all_kernel(const float* __restrict__ W0, const float* __restrict__ W1p,
                                  const float* __restrict__ W2p, const float* __restrict__ W3p,
                                  const float* __restrict__ W4p, const float* __restrict__ W5p,
                                  __half* __restrict__ Wh) {
    __shared__ float t[32][33];
    int z = blockIdx.z;
    const float* W = z == 0 ? W0 : z == 1 ? W1p : z == 2 ? W2p : z == 3 ? W3p
                   : z == 4 ? W4p : W5p;
    int K = (z == 0) ? IN_F : HIDDEN;
    int k0 = blockIdx.y * 32;
    if (k0 >= K) return;
    int n0 = blockIdx.x * 32;
    int tx = threadIdx.x, ty = threadIdx.y;
#pragma unroll
    for (int i = 0; i < 4; i++)
        t[ty + i * 8][tx] = W[(size_t)(k0 + ty + i * 8) * HIDDEN + n0 + tx];
    __syncthreads();
    __half* dst = Wh + (size_t)z * WSLOT;
#pragma unroll
    for (int i = 0; i < 4; i++) {
        float v = t[tx][ty + i * 8];
        dst[(size_t)(n0 + ty + i * 8) * K + k0 + tx] = __float2half_rn(v);
    }
}

// edge classifier reading fp16 h: out[t,:] = (h[n0]*h[n1]) @ fc2_W + fc2_b
// smem weights fp16, [N_CLASS][HIDDEN], uint4 loads per class row.
__global__ void __launch_bounds__(256)
edge_pred_kernel(const __half* __restrict__ h, const int* __restrict__ ei,
                 const int* __restrict__ train_id, const float* __restrict__ W,
                 const float* __restrict__ b, float* __restrict__ out) {
    __shared__ __half sWT[N_CLASS * HIDDEN];  // [j][k]
    __shared__ float sb[N_CLASS];
    for (int i = threadIdx.x; i < N_CLASS * HIDDEN; i += blockDim.x) {
        int j = i >> 9, k = i & 511;          // i = j*512 + k
        sWT[i] = __float2half_rn(W[k * N_CLASS + j]);
    }
    if (threadIdx.x < N_CLASS) sb[threadIdx.x] = b[threadIdx.x];
    __syncthreads();
    int warp = (blockIdx.x * blockDim.x + threadIdx.x) >> 5;
    int lane = threadIdx.x & 31;
    if (warp >= N_TRAIN) return;
    int te = train_id[warp];
    int n0 = ei[te], n1 = ei[N_EDGES + te];
    const uint4* h0 = (const uint4*)(h + (size_t)n0 * HIDDEN);
    const uint4* h1 = (const uint4*)(h + (size_t)n1 * HIDDEN);
    float acc[N_CLASS];
#pragma unroll
    for (int j = 0; j < N_CLASS; j++) acc[j] = 0.0f;
    for (int i = lane; i < HIDDEN / 8; i += 32) {   // 8 halves per uint4
        uint4 a4 = h0[i], c4 = h1[i];
        const __half2* ah = (const __half2*)&a4;
        const __half2* ch = (const __half2*)&c4;
        float p[8];
#pragma unroll
        for (int q = 0; q < 4; q++) {
            float2 af = __half22float2(ah[q]);
            float2 cf = __half22float2(ch[q]);
            p[2 * q]     = af.x * cf.x;
            p[2 * q + 1] = af.y * cf.y;
        }
#pragma unroll
        for (int j = 0; j < N_CLASS; j++) {
            uint4 w4 = *(const uint4*)(sWT + j * HIDDEN + i * 8);
            const __half2* wh2 = (const __half2*)&w4;
#pragma unroll
            for (int q = 0; q < 4; q++) {
                float2 wf = __half22float2(wh2[q]);
                acc[j] += p[2 * q] * wf.x + p[2 * q + 1] * wf.y;
            }
        }
    }
#pragma unroll
    for (int j = 0; j < N_CLASS; j++)
#pragma unroll
        for (int off = 16; off > 0; off >>= 1)
            acc[j] += __shfl_xor_sync(0xffffffffu, acc[j], off);
    if (lane == 0) {
#pragma unroll
        for (int j = 0; j < N_CLASS; j++)
            out[(size_t)warp * N_CLASS + j] = acc[j] + sb[j];
    }
}

// ---------------- launcher ----------------
extern "C" void kernel_launch(void* const* d_in, const int* in_sizes, int n_in,
                              void* d_out, int out_size) {
    const float* x     = (const float*)d_in[0];
    const int*   ei    = (const int*)d_in[1];
    const int*   trid  = (const int*)d_in[2];
    const float* W1    = (const float*)d_in[3];
    const float* b1    = (const float*)d_in[4];
    const float* W2    = (const float*)d_in[5];
    const float* b2    = (const float*)d_in[6];
    const float* W3    = (const float*)d_in[7];
    const float* b3    = (const float*)d_in[8];
    const float* bn1g  = (const float*)d_in[9];
    const float* bn1b  = (const float*)d_in[10];
    const float* bn1m  = (const float*)d_in[11];
    const float* bn1v  = (const float*)d_in[12];
    const float* eps1  = (const float*)d_in[13];
    const float* W4    = (const float*)d_in[14];
    const float* b4    = (const float*)d_in[15];
    const float* bn2g  = (const float*)d_in[16];
    const float* bn2b  = (const float*)d_in[17];
    const float* bn2m  = (const float*)d_in[18];
    const float* bn2v  = (const float*)d_in[19];
    const float* eps2  = (const float*)d_in[20];
    const float* lin1W = (const float*)d_in[21];
    const float* lin1b = (const float*)d_in[22];
    const float* lin2W = (const float*)d_in[23];
    const float* lin2b = (const float*)d_in[24];
    const float* fc2W  = (const float*)d_in[25];
    const float* fc2b  = (const float*)d_in[26];
    float* out = (float*)d_out;

    __half *hA, *hB, *hC, *hX, *wh;
    cudaGetSymbolAddress((void**)&hA, g_hA);
    cudaGetSymbolAddress((void**)&hB, g_hB);
    cudaGetSymbolAddress((void**)&hC, g_hC);
    cudaGetSymbolAddress((void**)&hX, g_hX);
    cudaGetSymbolAddress((void**)&wh, g_wh);

    cudaFuncSetAttribute(hmma_gemm_kernel<true, false, false>,
                         cudaFuncAttributeMaxDynamicSharedMemorySize, SMEMSZ);
    cudaFuncSetAttribute(hmma_gemm_kernel<true, true, true>,
                         cudaFuncAttributeMaxDynamicSharedMemorySize, SMEMSZ);
    cudaFuncSetAttribute(hmma_gemm_kernel<true, true, false>,
                         cudaFuncAttributeMaxDynamicSharedMemorySize, SMEMSZ);
    cudaFuncSetAttribute(hmma_gemm_kernel<false, false, false>,
                         cudaFuncAttributeMaxDynamicSharedMemorySize, SMEMSZ);

    const int* src = ei;
    const int* dst = ei + N_EDGES;

    // all weight transposes + fp16 casts in one launch
    wsplit_all_kernel<<<dim3(16, 16, 6), dim3(32, 8)>>>(W1, W2, W3, W4, lin1W, lin2W, wh);

    // agg1 fully fp16: hX = fp16(x), hA = fp16((1+eps1)x); hA[dst] += hX[src]
    {
        int n4 = N_NODES * IN_F / 4;
        quantx_kernel<<<(n4 + 255) / 256, 256>>>((const float4*)x, (uint32_t*)hX,
                                                 (uint32_t*)hA, eps1, n4);
        scatter64_f16_kernel<<<(N_EDGES * 8 + 255) / 256, 256>>>(hX, hA, src, dst, N_EDGES);
    }

    dim3 gg(HIDDEN / GBN, (N_NODES + GBM - 1) / GBM);  // (4, 391)

    // L1: relu(agg @ W1 + b1) -> hB
    hmma_gemm_kernel<true, false, false><<<gg, 256, SMEMSZ>>>(
        hA, wh + 0 * WSLOT, b1, nullptr, nullptr, nullptr, nullptr,
        nullptr, hB, nullptr, N_NODES, IN_F);
    // L2: relu(h @ W2 + b2) -> hA
    hmma_gemm_kernel<true, false, false><<<gg, 256, SMEMSZ>>>(
        hB, wh + 1 * WSLOT, b2, nullptr, nullptr, nullptr, nullptr,
        nullptr, hA, nullptr, N_NODES, HIDDEN);
    // L3: bn1(relu(h @ W3 + b3)) -> hB (h) + hC ((1+eps2)*h, fused agg base)
    hmma_gemm_kernel<true, true, true><<<gg, 256, SMEMSZ>>>(
        hA, wh + 2 * WSLOT, b3, bn1g, bn1b, bn1m, bn1v,
        eps2, hB, hC, N_NODES, HIDDEN);
    // agg2 (fp16): hC[dst] += hB[src]
    scatter_add_f16_kernel<<<(N_EDGES * 32 + 255) / 256, 256>>>(hB, hC, src, dst, N_EDGES);
    // L4: bn2(relu(h @ W4 + b4)) -> hA
    hmma_gemm_kernel<true, true, false><<<gg, 256, SMEMSZ>>>(
        hC, wh + 3 * WSLOT, b4, bn2g, bn2b, bn2m, bn2v,
        nullptr, hA, nullptr, N_NODES, HIDDEN);
    // L5: relu(h @ lin1W + lin1b) -> hB
    hmma_gemm_kernel<true, false, false><<<gg, 256, SMEMSZ>>>(
        hA, wh + 4 * WSLOT, lin1b, nullptr, nullptr, nullptr, nullptr,
        nullptr, hB, nullptr, N_NODES, HIDDEN);
    // L6: h @ lin2W + lin2b -> hC
    hmma_gemm_kernel<false, false, false><<<gg, 256, SMEMSZ>>>(
        hB, wh + 5 * WSLOT, lin2b, nullptr, nullptr, nullptr, nullptr,
        nullptr, hC, nullptr, N_NODES, HIDDEN);
    // edge classifier (fp16 h)
    edge_pred_kernel<<<(N_TRAIN * 32 + 255) / 256, 256>>>(hC, ei, trid, fc2W, fc2b, out);
}